// round 1
// baseline (speedup 1.0000x reference)
#include <cuda_runtime.h>
#include <cuda_bf16.h>
#include <math.h>

// ---------------- problem constants ----------------
#define Vv 50257
#define Ee 768
#define NHh 12
#define HDd 64
#define Ll 4
#define Tt 1024
#define Bb 2
#define FFf 3072
#define BT (Bb*Tt)            // 2048 rows

// ---------------- scratch (no allocs allowed) ----------------
__device__ float g_x  [BT * Ee];    // residual stream
__device__ float g_h  [BT * Ee];    // layernorm output
__device__ float g_qkv[BT * 3*Ee];  // qkv projection
__device__ float g_att[BT * Ee];    // attention output
__device__ float g_ffn[BT * FFf];   // ffn hidden

// ---------------- embedding ----------------
__global__ void embed_kernel(const int* __restrict__ ids,
                             const float* __restrict__ tok,
                             const float* __restrict__ pos,
                             float* __restrict__ out) {
    int i = blockIdx.x * blockDim.x + threadIdx.x;
    if (i >= BT * Ee) return;
    int e   = i % Ee;
    int row = i / Ee;            // b*T + t
    int t   = row % Tt;
    int id  = ids[row];
    out[i] = tok[(long)id * Ee + e] + pos[t * Ee + e];
}

// ---------------- layernorm (one block per row) ----------------
__global__ void layernorm_kernel(const float* __restrict__ x,
                                 const float* __restrict__ scale,
                                 const float* __restrict__ bias,
                                 float* __restrict__ out) {
    __shared__ float s1[256], s2[256];
    int row = blockIdx.x;
    int tid = threadIdx.x;
    const float* xr = x + (long)row * Ee;
    float sum = 0.f, sq = 0.f;
    for (int c = tid; c < Ee; c += 256) { float v = xr[c]; sum += v; sq += v * v; }
    s1[tid] = sum; s2[tid] = sq; __syncthreads();
    for (int s = 128; s > 0; s >>= 1) {
        if (tid < s) { s1[tid] += s1[tid+s]; s2[tid] += s2[tid+s]; }
        __syncthreads();
    }
    float mean = s1[0] * (1.0f / Ee);
    float var  = s2[0] * (1.0f / Ee) - mean * mean;
    float rstd = rsqrtf(var + 1e-5f);
    float* orow = out + (long)row * Ee;
    for (int c = tid; c < Ee; c += 256)
        orow[c] = (xr[c] - mean) * rstd * scale[c] + bias[c];
}

// ---------------- tiled SGEMM: C[m,n] = epilogue( sum_k A[m,k]*W[n,k] ) ----------------
// A: (M,K) row-major.  W: (N,K) row-major (so this computes A @ W^T).
// flags: 1=add bias[n], 2=exact GELU, 4=add residual[m,n]
#define BMt 128
#define BNt 128
#define BKt 16
#define FLAG_BIAS 1
#define FLAG_GELU 2
#define FLAG_RES  4

__global__ __launch_bounds__(256)
void gemm_kernel(const float* __restrict__ A, const float* __restrict__ W,
                 const float* __restrict__ bias, const float* __restrict__ res,
                 float* __restrict__ C, int M, int N, int K, int flags) {
    __shared__ float As[BKt][BMt];
    __shared__ float Ws[BKt][BNt];

    const int bm = blockIdx.y * BMt;
    const int bn = blockIdx.x * BNt;
    const int tid = threadIdx.x;          // 256 threads
    const int tx = tid & 15;              // 0..15  -> 8 cols each
    const int ty = tid >> 4;              // 0..15  -> 8 rows each

    const int l_row  = tid >> 2;          // 0..63
    const int l_col4 = (tid & 3) << 2;    // 0,4,8,12

    float acc[8][8];
    #pragma unroll
    for (int i = 0; i < 8; i++)
        #pragma unroll
        for (int j = 0; j < 8; j++) acc[i][j] = 0.f;

    for (int k0 = 0; k0 < K; k0 += BKt) {
        // load A tile (M always multiple of 128 here, K multiple of 16)
        #pragma unroll
        for (int it = 0; it < 2; it++) {
            int m = l_row + it * 64;
            float4 v = *(const float4*)&A[(long)(bm + m) * K + k0 + l_col4];
            As[l_col4+0][m] = v.x; As[l_col4+1][m] = v.y;
            As[l_col4+2][m] = v.z; As[l_col4+3][m] = v.w;
        }
        // load W tile with N bounds
        #pragma unroll
        for (int it = 0; it < 2; it++) {
            int n = l_row + it * 64;
            float4 v = make_float4(0.f, 0.f, 0.f, 0.f);
            if (bn + n < N) v = *(const float4*)&W[(long)(bn + n) * K + k0 + l_col4];
            Ws[l_col4+0][n] = v.x; Ws[l_col4+1][n] = v.y;
            Ws[l_col4+2][n] = v.z; Ws[l_col4+3][n] = v.w;
        }
        __syncthreads();

        #pragma unroll
        for (int kk = 0; kk < BKt; kk++) {
            float4 a0 = *(const float4*)&As[kk][ty * 8];
            float4 a1 = *(const float4*)&As[kk][ty * 8 + 4];
            float4 b0 = *(const float4*)&Ws[kk][tx * 8];
            float4 b1 = *(const float4*)&Ws[kk][tx * 8 + 4];
            float ar[8] = {a0.x, a0.y, a0.z, a0.w, a1.x, a1.y, a1.z, a1.w};
            float br[8] = {b0.x, b0.y, b0.z, b0.w, b1.x, b1.y, b1.z, b1.w};
            #pragma unroll
            for (int i = 0; i < 8; i++)
                #pragma unroll
                for (int j = 0; j < 8; j++)
                    acc[i][j] = fmaf(ar[i], br[j], acc[i][j]);
        }
        __syncthreads();
    }

    // epilogue
    #pragma unroll
    for (int i = 0; i < 8; i++) {
        int m = bm + ty * 8 + i;
        #pragma unroll
        for (int j = 0; j < 8; j++) {
            int n = bn + tx * 8 + j;
            if (n < N) {
                float v = acc[i][j];
                if (flags & FLAG_BIAS) v += bias[n];
                if (flags & FLAG_GELU) v = 0.5f * v * (1.0f + erff(v * 0.7071067811865476f));
                long ci = (long)m * N + n;
                if (flags & FLAG_RES) v += res[ci];
                C[ci] = v;
            }
        }
    }
}

// ---------------- fused causal attention: one block per (b,h,q) ----------------
// qkv row layout: [q(0:E) | k(E:2E) | v(2E:3E)], head h at offset h*64.
__global__ __launch_bounds__(128)
void attn_kernel(const float* __restrict__ qkv, float* __restrict__ out) {
    __shared__ float qs[HDd];
    __shared__ float sc[Tt];
    __shared__ float red[128];

    const int q = blockIdx.x;
    const int h = blockIdx.y;
    const int b = blockIdx.z;
    const int tid = threadIdx.x;
    const int nk = q + 1;
    const float scale = 0.125f; // 1/sqrt(64)

    const float* qptr = qkv + ((long)(b * Tt + q)) * (3 * Ee) + h * HDd;
    if (tid < HDd) qs[tid] = qptr[tid];
    __syncthreads();

    // scores + local max
    float lmax = -1e30f;
    for (int k = tid; k < nk; k += 128) {
        const float* kp = qkv + ((long)(b * Tt + k)) * (3 * Ee) + Ee + h * HDd;
        float s = 0.f;
        #pragma unroll
        for (int d = 0; d < HDd; d += 4) {
            float4 kv = *(const float4*)&kp[d];
            float4 qv = *(const float4*)&qs[d];
            s = fmaf(qv.x, kv.x, s); s = fmaf(qv.y, kv.y, s);
            s = fmaf(qv.z, kv.z, s); s = fmaf(qv.w, kv.w, s);
        }
        s *= scale;
        sc[k] = s;
        lmax = fmaxf(lmax, s);
    }
    red[tid] = lmax; __syncthreads();
    for (int s = 64; s > 0; s >>= 1) {
        if (tid < s) red[tid] = fmaxf(red[tid], red[tid + s]);
        __syncthreads();
    }
    float mx = red[0];
    __syncthreads();

    // exp + sum
    float lsum = 0.f;
    for (int k = tid; k < nk; k += 128) {
        float p = expf(sc[k] - mx);
        sc[k] = p;
        lsum += p;
    }
    red[tid] = lsum; __syncthreads();
    for (int s = 64; s > 0; s >>= 1) {
        if (tid < s) red[tid] += red[tid + s];
        __syncthreads();
    }
    float inv_sum = 1.0f / red[0];

    // AV: threads 0..63 own output dims
    if (tid < HDd) {
        const float* vb = qkv + ((long)b * Tt) * (3 * Ee) + 2 * Ee + h * HDd + tid;
        float acc = 0.f;
        for (int k = 0; k < nk; k++)
            acc = fmaf(sc[k], vb[(long)k * (3 * Ee)], acc);
        out[((long)(b * Tt + q)) * Ee + h * HDd + tid] = acc * inv_sum;
    }
}

// ---------------- launcher ----------------
static void launch_gemm(const float* A, const float* W, const float* bias,
                        const float* res, float* C, int M, int N, int K, int flags) {
    dim3 grid((N + BNt - 1) / BNt, (M + BMt - 1) / BMt);
    gemm_kernel<<<grid, 256>>>(A, W, bias, res, C, M, N, K, flags);
}

extern "C" void kernel_launch(void* const* d_in, const int* in_sizes, int n_in,
                              void* d_out, int out_size) {
    const int*   input_ids = (const int*)  d_in[0];
    const float* tok_emb   = (const float*)d_in[1];
    const float* pos_emb   = (const float*)d_in[2];
    const float* ln1_scale = (const float*)d_in[3];
    const float* ln1_bias  = (const float*)d_in[4];
    const float* qkv_w     = (const float*)d_in[5];
    const float* out_w     = (const float*)d_in[6];
    const float* ln2_scale = (const float*)d_in[7];
    const float* ln2_bias  = (const float*)d_in[8];
    const float* fc1_w     = (const float*)d_in[9];
    const float* fc1_b     = (const float*)d_in[10];
    const float* fc2_w     = (const float*)d_in[11];
    const float* fc2_b     = (const float*)d_in[12];
    const float* lnf_scale = (const float*)d_in[13];
    const float* lnf_bias  = (const float*)d_in[14];
    float* logits = (float*)d_out;

    float *x, *h, *qkv, *att, *ffn;
    cudaGetSymbolAddress((void**)&x,   g_x);
    cudaGetSymbolAddress((void**)&h,   g_h);
    cudaGetSymbolAddress((void**)&qkv, g_qkv);
    cudaGetSymbolAddress((void**)&att, g_att);
    cudaGetSymbolAddress((void**)&ffn, g_ffn);

    // embedding
    embed_kernel<<<(BT * Ee + 255) / 256, 256>>>(input_ids, tok_emb, pos_emb, x);

    for (int l = 0; l < Ll; l++) {
        // attention block (pre-norm)
        layernorm_kernel<<<BT, 256>>>(x, ln1_scale + l * Ee, ln1_bias + l * Ee, h);
        launch_gemm(h, qkv_w + (long)l * 3 * Ee * Ee, nullptr, nullptr, qkv,
                    BT, 3 * Ee, Ee, 0);
        attn_kernel<<<dim3(Tt, NHh, Bb), 128>>>(qkv, att);
        launch_gemm(att, out_w + (long)l * Ee * Ee, nullptr, x, x,
                    BT, Ee, Ee, FLAG_RES);
        // FFN block (pre-norm)
        layernorm_kernel<<<BT, 256>>>(x, ln2_scale + l * Ee, ln2_bias + l * Ee, h);
        launch_gemm(h, fc1_w + (long)l * FFf * Ee, fc1_b + (long)l * FFf, nullptr,
                    ffn, BT, FFf, Ee, FLAG_BIAS | FLAG_GELU);
        launch_gemm(ffn, fc2_w + (long)l * Ee * FFf, fc2_b + (long)l * Ee, x,
                    x, BT, Ee, FFf, FLAG_BIAS | FLAG_RES);
    }

    // final layernorm + tied LM head
    layernorm_kernel<<<BT, 256>>>(x, lnf_scale, lnf_bias, h);
    launch_gemm(h, tok_emb, nullptr, nullptr, logits, BT, Vv, Ee, 0);
}

// round 4
// speedup vs baseline: 1.9838x; 1.9838x over previous
#include <cuda_runtime.h>
#include <cuda_bf16.h>
#include <cstdint>
#include <math.h>

// ---------------- problem constants ----------------
#define Vv 50257
#define Ee 768
#define NHh 12
#define HDd 64
#define Ll 4
#define Tt 1024
#define Bb 2
#define FFf 3072
#define BT (Bb*Tt)            // 2048 rows

// ---------------- scratch (static, no allocs) ----------------
__device__ float g_x  [BT * Ee];                      // residual stream (fp32)
__device__ float g_qkv[BT * 3*Ee];                    // qkv projection (fp32)
__device__ __nv_bfloat16 g_hh[BT*Ee],  g_hl[BT*Ee];   // LN output hi/lo
__device__ __nv_bfloat16 g_ath[BT*Ee], g_atl[BT*Ee];  // attn output hi/lo
__device__ __nv_bfloat16 g_fh[BT*FFf], g_fl[BT*FFf];  // ffn hidden hi/lo
// weight hi/lo
__device__ __nv_bfloat16 g_qw_h[Ll*3*Ee*Ee], g_qw_l[Ll*3*Ee*Ee];
__device__ __nv_bfloat16 g_ow_h[Ll*Ee*Ee],   g_ow_l[Ll*Ee*Ee];
__device__ __nv_bfloat16 g_f1_h[Ll*FFf*Ee],  g_f1_l[Ll*FFf*Ee];
__device__ __nv_bfloat16 g_f2_h[Ll*Ee*FFf],  g_f2_l[Ll*Ee*FFf];
__device__ __nv_bfloat16 g_te_h[Vv*Ee],      g_te_l[Vv*Ee];

__device__ __forceinline__ void split1(float v, __nv_bfloat16& h, __nv_bfloat16& l) {
    h = __float2bfloat16(v);
    l = __float2bfloat16(v - __bfloat162float(h));
}

__device__ __forceinline__ uint32_t smem_u32(const void* p) {
    uint32_t a;
    asm("{ .reg .u64 t; cvta.to.shared.u64 t, %1; cvt.u32.u64 %0, t; }" : "=r"(a) : "l"(p));
    return a;
}
__device__ __forceinline__ void cp16(uint32_t dst, const void* src) {
    asm volatile("cp.async.cg.shared.global [%0], [%1], 16;" :: "r"(dst), "l"(src));
}
#define CP_COMMIT() asm volatile("cp.async.commit_group;" ::: "memory")
#define CP_WAIT(n)  asm volatile("cp.async.wait_group %0;" :: "n"(n) : "memory")

__device__ __forceinline__ void ldsm_x4(uint32_t a, uint32_t& r0, uint32_t& r1, uint32_t& r2, uint32_t& r3) {
    asm volatile("ldmatrix.sync.aligned.m8n8.x4.shared.b16 {%0,%1,%2,%3}, [%4];"
                 : "=r"(r0), "=r"(r1), "=r"(r2), "=r"(r3) : "r"(a));
}
__device__ __forceinline__ void mma16816(float* d, const uint32_t* a, const uint32_t* b) {
    asm volatile("mma.sync.aligned.m16n8k16.row.col.f32.bf16.bf16.f32 "
                 "{%0,%1,%2,%3}, {%4,%5,%6,%7}, {%8,%9}, {%0,%1,%2,%3};"
                 : "+f"(d[0]), "+f"(d[1]), "+f"(d[2]), "+f"(d[3])
                 : "r"(a[0]), "r"(a[1]), "r"(a[2]), "r"(a[3]), "r"(b[0]), "r"(b[1]));
}

// ---------------- fp32 -> bf16 hi/lo split ----------------
__global__ void split_kernel(const float* __restrict__ src,
                             __nv_bfloat16* __restrict__ hi,
                             __nv_bfloat16* __restrict__ lo, int n4) {
    int i = blockIdx.x * blockDim.x + threadIdx.x;
    if (i >= n4) return;
    float4 v = ((const float4*)src)[i];
    __nv_bfloat16 h0,h1,h2,h3,l0,l1,l2,l3;
    split1(v.x,h0,l0); split1(v.y,h1,l1); split1(v.z,h2,l2); split1(v.w,h3,l3);
    __nv_bfloat162 a,b,c,d;
    a.x=h0; a.y=h1; b.x=h2; b.y=h3; c.x=l0; c.y=l1; d.x=l2; d.y=l3;
    ((__nv_bfloat162*)hi)[2*i]   = a; ((__nv_bfloat162*)hi)[2*i+1] = b;
    ((__nv_bfloat162*)lo)[2*i]   = c; ((__nv_bfloat162*)lo)[2*i+1] = d;
}

// ---------------- embedding ----------------
__global__ void embed_kernel(const int* __restrict__ ids, const float* __restrict__ tok,
                             const float* __restrict__ pos, float* __restrict__ out) {
    int i = blockIdx.x * blockDim.x + threadIdx.x;
    if (i >= BT * Ee) return;
    int e = i % Ee, row = i / Ee, t = row % Tt;
    out[i] = tok[(size_t)ids[row] * Ee + e] + pos[t * Ee + e];
}

// ---------------- layernorm -> split bf16 hi/lo ----------------
__global__ void ln_split_kernel(const float* __restrict__ x,
                                const float* __restrict__ scale, const float* __restrict__ bias,
                                __nv_bfloat16* __restrict__ oh, __nv_bfloat16* __restrict__ ol) {
    __shared__ float s1[256], s2[256];
    int row = blockIdx.x, tid = threadIdx.x;
    const float* xr = x + (size_t)row * Ee;
    float sum = 0.f, sq = 0.f;
    for (int c = tid; c < Ee; c += 256) { float v = xr[c]; sum += v; sq += v * v; }
    s1[tid] = sum; s2[tid] = sq; __syncthreads();
    for (int s = 128; s > 0; s >>= 1) {
        if (tid < s) { s1[tid] += s1[tid+s]; s2[tid] += s2[tid+s]; }
        __syncthreads();
    }
    float mean = s1[0] * (1.0f / Ee);
    float var  = s2[0] * (1.0f / Ee) - mean * mean;
    float rstd = rsqrtf(var + 1e-5f);
    for (int c = tid; c < Ee; c += 256) {
        float v = (xr[c] - mean) * rstd * scale[c] + bias[c];
        __nv_bfloat16 h, l; split1(v, h, l);
        oh[(size_t)row * Ee + c] = h; ol[(size_t)row * Ee + c] = l;
    }
}

// ---------------- HMMA GEMM: C = epi(A @ W^T), bf16x3 split ----------------
// A: (2048,K) hi/lo bf16 row-major.  W: (N,K) hi/lo bf16 row-major.
#define FLAG_BIAS 1
#define FLAG_GELU 2
#define FLAG_RES  4
#define FLAG_SPLITOUT 8

// SMEM tile: 128 rows x 32 bf16 (64B) padded to 80B stride -> 10240B per tile.
#define TILE_B   10240
#define STAGE_B  (4 * TILE_B)      // Ah | Al | Wh | Wl
#define GEMM_SMEM (2 * STAGE_B)    // 81920 B double-buffered

__global__ __launch_bounds__(256, 1)
void gemm_mma(const __nv_bfloat16* __restrict__ Ah, const __nv_bfloat16* __restrict__ Al,
              const __nv_bfloat16* __restrict__ Wh, const __nv_bfloat16* __restrict__ Wl,
              const float* __restrict__ bias, const float* __restrict__ res,
              float* __restrict__ C, __nv_bfloat16* __restrict__ Chi, __nv_bfloat16* __restrict__ Clo,
              int N, int K, int flags) {
    extern __shared__ char smem[];
    const uint32_t sb = smem_u32(smem);
    const int tid  = threadIdx.x;
    const int lane = tid & 31;
    const int wid  = tid >> 5;
    const int wm   = wid >> 2;            // 0..1 : 64-row band
    const int wn   = wid & 3;             // 0..3 : 32-col band
    const int bm   = blockIdx.x * 128;
    const int bn   = blockIdx.y * 128;

    float acc[4][4][4];
    #pragma unroll
    for (int i = 0; i < 4; i++)
        #pragma unroll
        for (int j = 0; j < 4; j++)
            #pragma unroll
            for (int r = 0; r < 4; r++) acc[i][j][r] = 0.f;

    const int nc = K >> 5;   // BK = 32

    // ---- async stage loader: 2048 16B chunks / 256 threads = 8 each ----
    auto load_stage = [&](int c, int stage) {
        const int k0 = c << 5;
        const uint32_t sdst = sb + stage * STAGE_B;
        #pragma unroll
        for (int it = 0; it < 8; it++) {
            int gi    = it * 256 + tid;
            int tile  = gi >> 9;           // 0..3
            int within= gi & 511;
            int row   = within >> 2;       // 0..127
            int chunk = within & 3;        // 16B chunk
            uint32_t dst = sdst + tile * TILE_B + row * 80 + chunk * 16;
            const __nv_bfloat16* srcb;
            if (tile < 2) {
                srcb = (tile == 0 ? Ah : Al) + (size_t)(bm + row) * K + k0 + chunk * 8;
            } else {
                int gn = bn + row; if (gn > N - 1) gn = N - 1;
                srcb = (tile == 2 ? Wh : Wl) + (size_t)gn * K + k0 + chunk * 8;
            }
            cp16(dst, srcb);
        }
    };

    load_stage(0, 0);
    CP_COMMIT();

    for (int c = 0; c < nc; c++) {
        if (c + 1 < nc) {
            load_stage(c + 1, (c + 1) & 1);
            CP_COMMIT();
            CP_WAIT(1);
        } else {
            CP_WAIT(0);
        }
        __syncthreads();

        const uint32_t st = sb + (c & 1) * STAGE_B;
        #pragma unroll
        for (int ks = 0; ks < 2; ks++) {
            // B fragments (hi & lo): non-trans ldmatrix on [n][k] row-major tiles.
            // lanes 0-7: n0-7,k0-7 | 8-15: n0-7,k8-15 | 16-23: n8-15,k0-7 | 24-31: n8-15,k8-15
            uint32_t bh[4][2], bl[4][2];
            #pragma unroll
            for (int p = 0; p < 2; p++) {
                int nrow = wn * 32 + p * 16 + (lane & 7) + 8 * (lane >> 4);
                uint32_t koff = ks * 32 + ((lane >> 3) & 1) * 16;
                uint32_t ah = st + 2 * TILE_B + nrow * 80 + koff;
                uint32_t al = st + 3 * TILE_B + nrow * 80 + koff;
                uint32_t r0,r1,r2,r3;
                ldsm_x4(ah, r0, r1, r2, r3);
                bh[2*p][0]=r0; bh[2*p][1]=r1; bh[2*p+1][0]=r2; bh[2*p+1][1]=r3;
                ldsm_x4(al, r0, r1, r2, r3);
                bl[2*p][0]=r0; bl[2*p][1]=r1; bl[2*p+1][0]=r2; bl[2*p+1][1]=r3;
            }
            // A hi fragments; hi*hi and hi*lo
            uint32_t a[4][4];
            #pragma unroll
            for (int i = 0; i < 4; i++) {
                int mrow = wm * 64 + i * 16 + (lane & 7) + 8 * ((lane >> 3) & 1);
                uint32_t koff = ks * 32 + (lane >> 4) * 16;
                ldsm_x4(st + mrow * 80 + koff, a[i][0], a[i][1], a[i][2], a[i][3]);
            }
            #pragma unroll
            for (int i = 0; i < 4; i++)
                #pragma unroll
                for (int j = 0; j < 4; j++) {
                    mma16816(acc[i][j], a[i], bh[j]);
                    mma16816(acc[i][j], a[i], bl[j]);
                }
            // A lo fragments; lo*hi
            #pragma unroll
            for (int i = 0; i < 4; i++) {
                int mrow = wm * 64 + i * 16 + (lane & 7) + 8 * ((lane >> 3) & 1);
                uint32_t koff = ks * 32 + (lane >> 4) * 16;
                ldsm_x4(st + TILE_B + mrow * 80 + koff, a[i][0], a[i][1], a[i][2], a[i][3]);
            }
            #pragma unroll
            for (int i = 0; i < 4; i++)
                #pragma unroll
                for (int j = 0; j < 4; j++)
                    mma16816(acc[i][j], a[i], bh[j]);
        }
        __syncthreads();
    }

    // ---- epilogue: scalar stores (adjacent lanes contiguous; safe for odd N) ----
    #pragma unroll
    for (int i = 0; i < 4; i++) {
        int row0 = bm + wm * 64 + i * 16 + (lane >> 2);
        #pragma unroll
        for (int j = 0; j < 4; j++) {
            int col = bn + wn * 32 + j * 8 + (lane & 3) * 2;
            float bv0 = 0.f, bv1 = 0.f;
            if (flags & FLAG_BIAS) {
                if (col < N)     bv0 = bias[col];
                if (col + 1 < N) bv1 = bias[col + 1];
            }
            #pragma unroll
            for (int half = 0; half < 2; half++) {
                int row = row0 + half * 8;
                float v0 = acc[i][j][2*half]     + bv0;
                float v1 = acc[i][j][2*half + 1] + bv1;
                if (flags & FLAG_GELU) {
                    v0 = 0.5f * v0 * (1.0f + erff(v0 * 0.7071067811865476f));
                    v1 = 0.5f * v1 * (1.0f + erff(v1 * 0.7071067811865476f));
                }
                size_t ci = (size_t)row * N + col;
                if (flags & FLAG_RES) {
                    if (col < N)     v0 += res[ci];
                    if (col + 1 < N) v1 += res[ci + 1];
                }
                if (flags & FLAG_SPLITOUT) {
                    __nv_bfloat16 h0,l0,h1,l1;
                    split1(v0,h0,l0); split1(v1,h1,l1);
                    if (col < N)     { Chi[ci]   = h0; Clo[ci]   = l0; }
                    if (col + 1 < N) { Chi[ci+1] = h1; Clo[ci+1] = l1; }
                } else {
                    if (col < N)     C[ci]   = v0;
                    if (col + 1 < N) C[ci+1] = v1;
                }
            }
        }
    }
}

// ---------------- fused causal attention, smem K-tiles ----------------
__global__ __launch_bounds__(128) void attn_kernel(const float* __restrict__ qkv,
                                                   __nv_bfloat16* __restrict__ oh,
                                                   __nv_bfloat16* __restrict__ ol) {
    __shared__ float qs[HDd];
    __shared__ float Ks[128 * 65];
    __shared__ float sc[Tt];
    __shared__ float red[128];
    __shared__ float av[2][HDd];

    const int q = blockIdx.x, h = blockIdx.y, b = blockIdx.z;
    const int tid = threadIdx.x;
    const int nk = q + 1;

    const float* qptr = qkv + ((size_t)(b * Tt + q)) * (3 * Ee) + h * HDd;
    if (tid < 32) ((float2*)qs)[tid] = ((const float2*)qptr)[tid];
    __syncthreads();

    float lmax = -1e30f;
    const int ntiles = (nk + 127) >> 7;
    for (int kt = 0; kt < ntiles; kt++) {
        const int kbase = kt << 7;
        const int rows = min(128, nk - kbase);
        for (int i = tid; i < rows * 16; i += 128) {
            int r = i >> 4, c4 = (i & 15) << 2;
            float4 v = *(const float4*)&qkv[((size_t)(b * Tt + kbase + r)) * (3 * Ee) + Ee + h * HDd + c4];
            float* dst = &Ks[r * 65 + c4];
            dst[0] = v.x; dst[1] = v.y; dst[2] = v.z; dst[3] = v.w;
        }
        __syncthreads();
        if (tid < rows) {
            float s = 0.f;
            const float* kr = &Ks[tid * 65];
            #pragma unroll
            for (int d = 0; d < HDd; d++) s = fmaf(qs[d], kr[d], s);
            s *= 0.125f;
            sc[kbase + tid] = s;
            lmax = fmaxf(lmax, s);
        }
        __syncthreads();
    }
    red[tid] = lmax; __syncthreads();
    for (int s = 64; s > 0; s >>= 1) {
        if (tid < s) red[tid] = fmaxf(red[tid], red[tid + s]);
        __syncthreads();
    }
    float mx = red[0];
    __syncthreads();

    float ls = 0.f;
    for (int k = tid; k < nk; k += 128) {
        float p = __expf(sc[k] - mx);
        sc[k] = p; ls += p;
    }
    red[tid] = ls; __syncthreads();
    for (int s = 64; s > 0; s >>= 1) {
        if (tid < s) red[tid] += red[tid + s];
        __syncthreads();
    }
    float inv = 1.0f / red[0];

    {
        const int d = tid & 63, half = tid >> 6;
        const float* vb = qkv + ((size_t)b * Tt) * (3 * Ee) + 2 * Ee + h * HDd + d;
        float acc = 0.f;
        for (int k = half; k < nk; k += 2)
            acc = fmaf(sc[k], vb[(size_t)k * (3 * Ee)], acc);
        av[half][d] = acc;
    }
    __syncthreads();
    if (tid < HDd) {
        float o = (av[0][tid] + av[1][tid]) * inv;
        __nv_bfloat16 hh, ll; split1(o, hh, ll);
        size_t idx = ((size_t)(b * Tt + q)) * Ee + h * HDd + tid;
        oh[idx] = hh; ol[idx] = ll;
    }
}

// ---------------- launcher ----------------
static void run_gemm(const __nv_bfloat16* Ah, const __nv_bfloat16* Al,
                     const __nv_bfloat16* Wh, const __nv_bfloat16* Wl,
                     const float* bias, const float* res,
                     float* C, __nv_bfloat16* Chi, __nv_bfloat16* Clo,
                     int N, int K, int flags) {
    dim3 g(BT / 128, (N + 127) / 128);
    gemm_mma<<<g, 256, GEMM_SMEM>>>(Ah, Al, Wh, Wl, bias, res, C, Chi, Clo, N, K, flags);
}

static void run_split(const float* src, __nv_bfloat16* hi, __nv_bfloat16* lo, long n) {
    int n4 = (int)(n / 4);
    split_kernel<<<(n4 + 255) / 256, 256>>>(src, hi, lo, n4);
}

extern "C" void kernel_launch(void* const* d_in, const int* in_sizes, int n_in,
                              void* d_out, int out_size) {
    const int*   input_ids = (const int*)  d_in[0];
    const float* tok_emb   = (const float*)d_in[1];
    const float* pos_emb   = (const float*)d_in[2];
    const float* ln1_scale = (const float*)d_in[3];
    const float* ln1_bias  = (const float*)d_in[4];
    const float* qkv_w     = (const float*)d_in[5];
    const float* out_w     = (const float*)d_in[6];
    const float* ln2_scale = (const float*)d_in[7];
    const float* ln2_bias  = (const float*)d_in[8];
    const float* fc1_w     = (const float*)d_in[9];
    const float* fc1_b     = (const float*)d_in[10];
    const float* fc2_w     = (const float*)d_in[11];
    const float* fc2_b     = (const float*)d_in[12];
    const float* lnf_scale = (const float*)d_in[13];
    const float* lnf_bias  = (const float*)d_in[14];
    float* logits = (float*)d_out;

    cudaFuncSetAttribute(gemm_mma, cudaFuncAttributeMaxDynamicSharedMemorySize, GEMM_SMEM);

    float *x, *qkv;
    __nv_bfloat16 *hh, *hl, *ath, *atl, *fh, *fl;
    __nv_bfloat16 *qwh, *qwl, *owh, *owl, *f1h, *f1l, *f2h, *f2l, *teh, *tel;
    cudaGetSymbolAddress((void**)&x,   g_x);
    cudaGetSymbolAddress((void**)&qkv, g_qkv);
    cudaGetSymbolAddress((void**)&hh,  g_hh);  cudaGetSymbolAddress((void**)&hl,  g_hl);
    cudaGetSymbolAddress((void**)&ath, g_ath); cudaGetSymbolAddress((void**)&atl, g_atl);
    cudaGetSymbolAddress((void**)&fh,  g_fh);  cudaGetSymbolAddress((void**)&fl,  g_fl);
    cudaGetSymbolAddress((void**)&qwh, g_qw_h); cudaGetSymbolAddress((void**)&qwl, g_qw_l);
    cudaGetSymbolAddress((void**)&owh, g_ow_h); cudaGetSymbolAddress((void**)&owl, g_ow_l);
    cudaGetSymbolAddress((void**)&f1h, g_f1_h); cudaGetSymbolAddress((void**)&f1l, g_f1_l);
    cudaGetSymbolAddress((void**)&f2h, g_f2_h); cudaGetSymbolAddress((void**)&f2l, g_f2_l);
    cudaGetSymbolAddress((void**)&teh, g_te_h); cudaGetSymbolAddress((void**)&tel, g_te_l);

    // weight conversions (per replay; ~35us of HBM traffic)
    run_split(qkv_w, qwh, qwl, (long)Ll * 3 * Ee * Ee);
    run_split(out_w, owh, owl, (long)Ll * Ee * Ee);
    run_split(fc1_w, f1h, f1l, (long)Ll * FFf * Ee);
    run_split(fc2_w, f2h, f2l, (long)Ll * Ee * FFf);
    run_split(tok_emb, teh, tel, (long)Vv * Ee);

    embed_kernel<<<(BT * Ee + 255) / 256, 256>>>(input_ids, tok_emb, pos_emb, x);

    for (int l = 0; l < Ll; l++) {
        // attention block (pre-norm)
        ln_split_kernel<<<BT, 256>>>(x, ln1_scale + l * Ee, ln1_bias + l * Ee, hh, hl);
        run_gemm(hh, hl, qwh + (size_t)l * 3 * Ee * Ee, qwl + (size_t)l * 3 * Ee * Ee,
                 nullptr, nullptr, qkv, nullptr, nullptr, 3 * Ee, Ee, 0);
        attn_kernel<<<dim3(Tt, NHh, Bb), 128>>>(qkv, ath, atl);
        run_gemm(ath, atl, owh + (size_t)l * Ee * Ee, owl + (size_t)l * Ee * Ee,
                 nullptr, x, x, nullptr, nullptr, Ee, Ee, FLAG_RES);
        // FFN block (pre-norm)
        ln_split_kernel<<<BT, 256>>>(x, ln2_scale + l * Ee, ln2_bias + l * Ee, hh, hl);
        run_gemm(hh, hl, f1h + (size_t)l * FFf * Ee, f1l + (size_t)l * FFf * Ee,
                 fc1_b + (size_t)l * FFf, nullptr, nullptr, fh, fl,
                 FFf, Ee, FLAG_BIAS | FLAG_GELU | FLAG_SPLITOUT);
        run_gemm(fh, fl, f2h + (size_t)l * Ee * FFf, f2l + (size_t)l * Ee * FFf,
                 fc2_b + (size_t)l * Ee, x, x, nullptr, nullptr,
                 Ee, FFf, FLAG_BIAS | FLAG_RES);
    }

    // final layernorm + tied LM head
    ln_split_kernel<<<BT, 256>>>(x, lnf_scale, lnf_bias, hh, hl);
    run_gemm(hh, hl, teh, tel, nullptr, nullptr, logits, nullptr, nullptr,
             Vv, Ee, 0);
}

// round 6
// speedup vs baseline: 2.2349x; 1.1266x over previous
#include <cuda_runtime.h>
#include <cuda_bf16.h>
#include <cstdint>
#include <math.h>

// ---------------- problem constants ----------------
#define Vv 50257
#define Ee 768
#define NHh 12
#define HDd 64
#define Ll 4
#define Tt 1024
#define Bb 2
#define FFf 3072
#define BT (Bb*Tt)            // 2048 rows

// ---------------- scratch (static, no allocs) ----------------
__device__ float g_x  [BT * Ee];                      // residual stream (fp32)
__device__ float g_qkv[BT * 3*Ee];                    // qkv projection (fp32)
__device__ __nv_bfloat16 g_hh[BT*Ee],  g_hl[BT*Ee];   // LN output hi/lo
__device__ __nv_bfloat16 g_ath[BT*Ee], g_atl[BT*Ee];  // attn output hi/lo
__device__ __nv_bfloat16 g_fh[BT*FFf], g_fl[BT*FFf];  // ffn hidden hi/lo
// weight hi/lo
__device__ __nv_bfloat16 g_qw_h[Ll*3*Ee*Ee], g_qw_l[Ll*3*Ee*Ee];
__device__ __nv_bfloat16 g_ow_h[Ll*Ee*Ee],   g_ow_l[Ll*Ee*Ee];
__device__ __nv_bfloat16 g_f1_h[Ll*FFf*Ee],  g_f1_l[Ll*FFf*Ee];
__device__ __nv_bfloat16 g_f2_h[Ll*Ee*FFf],  g_f2_l[Ll*Ee*FFf];
__device__ __nv_bfloat16 g_te_h[Vv*Ee],      g_te_l[Vv*Ee];

__device__ __forceinline__ void split1(float v, __nv_bfloat16& h, __nv_bfloat16& l) {
    h = __float2bfloat16(v);
    l = __float2bfloat16(v - __bfloat162float(h));
}

__device__ __forceinline__ uint32_t smem_u32(const void* p) {
    uint32_t a;
    asm("{ .reg .u64 t; cvta.to.shared.u64 t, %1; cvt.u32.u64 %0, t; }" : "=r"(a) : "l"(p));
    return a;
}
__device__ __forceinline__ void cp16(uint32_t dst, const void* src) {
    asm volatile("cp.async.cg.shared.global [%0], [%1], 16;" :: "r"(dst), "l"(src));
}
#define CP_COMMIT() asm volatile("cp.async.commit_group;" ::: "memory")
template<int N> __device__ __forceinline__ void cp_wait() {
    asm volatile("cp.async.wait_group %0;" :: "n"(N) : "memory");
}

__device__ __forceinline__ void ldsm_x4(uint32_t a, uint32_t& r0, uint32_t& r1, uint32_t& r2, uint32_t& r3) {
    asm volatile("ldmatrix.sync.aligned.m8n8.x4.shared.b16 {%0,%1,%2,%3}, [%4];"
                 : "=r"(r0), "=r"(r1), "=r"(r2), "=r"(r3) : "r"(a));
}
__device__ __forceinline__ void mma16816(float* d, const uint32_t* a, const uint32_t* b) {
    asm volatile("mma.sync.aligned.m16n8k16.row.col.f32.bf16.bf16.f32 "
                 "{%0,%1,%2,%3}, {%4,%5,%6,%7}, {%8,%9}, {%0,%1,%2,%3};"
                 : "+f"(d[0]), "+f"(d[1]), "+f"(d[2]), "+f"(d[3])
                 : "r"(a[0]), "r"(a[1]), "r"(a[2]), "r"(a[3]), "r"(b[0]), "r"(b[1]));
}

// ---------------- fp32 -> bf16 hi/lo split ----------------
__global__ void split_kernel(const float* __restrict__ src,
                             __nv_bfloat16* __restrict__ hi,
                             __nv_bfloat16* __restrict__ lo, int n4) {
    int i = blockIdx.x * blockDim.x + threadIdx.x;
    if (i >= n4) return;
    float4 v = ((const float4*)src)[i];
    __nv_bfloat16 h0,h1,h2,h3,l0,l1,l2,l3;
    split1(v.x,h0,l0); split1(v.y,h1,l1); split1(v.z,h2,l2); split1(v.w,h3,l3);
    __nv_bfloat162 a,b,c,d;
    a.x=h0; a.y=h1; b.x=h2; b.y=h3; c.x=l0; c.y=l1; d.x=l2; d.y=l3;
    ((__nv_bfloat162*)hi)[2*i]   = a; ((__nv_bfloat162*)hi)[2*i+1] = b;
    ((__nv_bfloat162*)lo)[2*i]   = c; ((__nv_bfloat162*)lo)[2*i+1] = d;
}

// ---------------- embedding ----------------
__global__ void embed_kernel(const int* __restrict__ ids, const float* __restrict__ tok,
                             const float* __restrict__ pos, float* __restrict__ out) {
    int i = blockIdx.x * blockDim.x + threadIdx.x;
    if (i >= BT * Ee) return;
    int e = i % Ee, row = i / Ee, t = row % Tt;
    out[i] = tok[(size_t)ids[row] * Ee + e] + pos[t * Ee + e];
}

// ---------------- layernorm -> split bf16 hi/lo ----------------
__global__ void ln_split_kernel(const float* __restrict__ x,
                                const float* __restrict__ scale, const float* __restrict__ bias,
                                __nv_bfloat16* __restrict__ oh, __nv_bfloat16* __restrict__ ol) {
    __shared__ float s1[256], s2[256];
    int row = blockIdx.x, tid = threadIdx.x;
    const float* xr = x + (size_t)row * Ee;
    float sum = 0.f, sq = 0.f;
    for (int c = tid; c < Ee; c += 256) { float v = xr[c]; sum += v; sq += v * v; }
    s1[tid] = sum; s2[tid] = sq; __syncthreads();
    for (int s = 128; s > 0; s >>= 1) {
        if (tid < s) { s1[tid] += s1[tid+s]; s2[tid] += s2[tid+s]; }
        __syncthreads();
    }
    float mean = s1[0] * (1.0f / Ee);
    float var  = s2[0] * (1.0f / Ee) - mean * mean;
    float rstd = rsqrtf(var + 1e-5f);
    for (int c = tid; c < Ee; c += 256) {
        float v = (xr[c] - mean) * rstd * scale[c] + bias[c];
        __nv_bfloat16 h, l; split1(v, h, l);
        oh[(size_t)row * Ee + c] = h; ol[(size_t)row * Ee + c] = l;
    }
}

// ---------------- HMMA GEMM: C = epi(A @ W^T), bf16x3 split ----------------
#define FLAG_BIAS 1
#define FLAG_GELU 2
#define FLAG_RES  4
#define FLAG_SPLITOUT 8

// SMEM tiles: rows x 32 bf16 (64B) padded to 80B stride.
#define W_TILE_B 10240

template<int BM, int STAGES>
__global__ __launch_bounds__(256, 1)
void gemm_mma(const __nv_bfloat16* __restrict__ Ah, const __nv_bfloat16* __restrict__ Al,
              const __nv_bfloat16* __restrict__ Wh, const __nv_bfloat16* __restrict__ Wl,
              const float* __restrict__ bias, const float* __restrict__ res,
              float* __restrict__ C, __nv_bfloat16* __restrict__ Chi, __nv_bfloat16* __restrict__ Clo,
              int N, int K, int flags) {
    constexpr int A_TILE = BM * 80;
    constexpr int STAGE_B = 2 * A_TILE + 2 * W_TILE_B;
    constexpr int AC = BM * 4;               // A 16B chunks per tile
    constexpr int WNG = (BM == 128) ? 4 : 8; // warp cols
    constexpr int NJ  = (BM == 128) ? 4 : 2; // 8-col mma tiles per warp
    constexpr int NP  = (BM == 128) ? 2 : 1; // B ldsm pair iters
    constexpr int WNW = 128 / WNG;           // warp n width
    constexpr int NIT = (2 * AC + 1024) / 256;

    extern __shared__ char smem[];
    const uint32_t sb = smem_u32(smem);
    const int tid  = threadIdx.x;
    const int lane = tid & 31;
    const int wid  = tid >> 5;
    const int wm   = wid / WNG;
    const int wn   = wid % WNG;
    const int bm   = blockIdx.x * BM;
    const int bn   = blockIdx.y * 128;

    float acc[4][NJ][4];
    #pragma unroll
    for (int i = 0; i < 4; i++)
        #pragma unroll
        for (int j = 0; j < NJ; j++)
            #pragma unroll
            for (int r = 0; r < 4; r++) acc[i][j][r] = 0.f;

    const int nc = K >> 5;   // BK = 32

    auto load_stage = [&](int c, int stage) {
        const int k0 = c << 5;
        const uint32_t sdst = sb + stage * STAGE_B;
        #pragma unroll
        for (int it = 0; it < NIT; it++) {
            int gi = it * 256 + tid;
            uint32_t dst; const __nv_bfloat16* src;
            if (gi < AC) {
                int row = gi >> 2, chunk = gi & 3;
                dst = sdst + row * 80 + chunk * 16;
                src = Ah + (size_t)(bm + row) * K + k0 + chunk * 8;
            } else if (gi < 2 * AC) {
                int li = gi - AC;
                int row = li >> 2, chunk = li & 3;
                dst = sdst + A_TILE + row * 80 + chunk * 16;
                src = Al + (size_t)(bm + row) * K + k0 + chunk * 8;
            } else if (gi < 2 * AC + 512) {
                int li = gi - 2 * AC;
                int row = li >> 2, chunk = li & 3;
                int gn = bn + row; if (gn > N - 1) gn = N - 1;
                dst = sdst + 2 * A_TILE + row * 80 + chunk * 16;
                src = Wh + (size_t)gn * K + k0 + chunk * 8;
            } else {
                int li = gi - 2 * AC - 512;
                int row = li >> 2, chunk = li & 3;
                int gn = bn + row; if (gn > N - 1) gn = N - 1;
                dst = sdst + 2 * A_TILE + W_TILE_B + row * 80 + chunk * 16;
                src = Wl + (size_t)gn * K + k0 + chunk * 8;
            }
            cp16(dst, src);
        }
    };

    #pragma unroll
    for (int s = 0; s < STAGES - 1; s++) {
        if (s < nc) load_stage(s, s);
        CP_COMMIT();
    }

    for (int c = 0; c < nc; c++) {
        if (c + STAGES - 1 < nc) load_stage(c + STAGES - 1, (c + STAGES - 1) % STAGES);
        CP_COMMIT();
        cp_wait<STAGES - 1>();
        __syncthreads();

        const uint32_t st = sb + (c % STAGES) * STAGE_B;
        #pragma unroll
        for (int ks = 0; ks < 2; ks++) {
            uint32_t bh[NJ][2], bl[NJ][2];
            #pragma unroll
            for (int p = 0; p < NP; p++) {
                int nrow = wn * WNW + p * 16 + (lane & 7) + 8 * (lane >> 4);
                uint32_t koff = ks * 32 + ((lane >> 3) & 1) * 16;
                uint32_t ah = st + 2 * A_TILE + nrow * 80 + koff;
                uint32_t al = st + 2 * A_TILE + W_TILE_B + nrow * 80 + koff;
                uint32_t r0,r1,r2,r3;
                ldsm_x4(ah, r0, r1, r2, r3);
                bh[2*p][0]=r0; bh[2*p][1]=r1; bh[2*p+1][0]=r2; bh[2*p+1][1]=r3;
                ldsm_x4(al, r0, r1, r2, r3);
                bl[2*p][0]=r0; bl[2*p][1]=r1; bl[2*p+1][0]=r2; bl[2*p+1][1]=r3;
            }
            uint32_t a[4][4];
            #pragma unroll
            for (int i = 0; i < 4; i++) {
                int mrow = wm * 64 + i * 16 + (lane & 7) + 8 * ((lane >> 3) & 1);
                uint32_t koff = ks * 32 + (lane >> 4) * 16;
                ldsm_x4(st + mrow * 80 + koff, a[i][0], a[i][1], a[i][2], a[i][3]);
            }
            #pragma unroll
            for (int i = 0; i < 4; i++)
                #pragma unroll
                for (int j = 0; j < NJ; j++) {
                    mma16816(acc[i][j], a[i], bh[j]);
                    mma16816(acc[i][j], a[i], bl[j]);
                }
            #pragma unroll
            for (int i = 0; i < 4; i++) {
                int mrow = wm * 64 + i * 16 + (lane & 7) + 8 * ((lane >> 3) & 1);
                uint32_t koff = ks * 32 + (lane >> 4) * 16;
                ldsm_x4(st + A_TILE + mrow * 80 + koff, a[i][0], a[i][1], a[i][2], a[i][3]);
            }
            #pragma unroll
            for (int i = 0; i < 4; i++)
                #pragma unroll
                for (int j = 0; j < NJ; j++)
                    mma16816(acc[i][j], a[i], bh[j]);
        }
        __syncthreads();
    }

    // ---- epilogue: scalar stores (adjacent lanes contiguous; safe for odd N) ----
    #pragma unroll
    for (int i = 0; i < 4; i++) {
        int row0 = bm + wm * 64 + i * 16 + (lane >> 2);
        #pragma unroll
        for (int j = 0; j < NJ; j++) {
            int col = bn + wn * WNW + j * 8 + (lane & 3) * 2;
            float bv0 = 0.f, bv1 = 0.f;
            if (flags & FLAG_BIAS) {
                if (col < N)     bv0 = bias[col];
                if (col + 1 < N) bv1 = bias[col + 1];
            }
            #pragma unroll
            for (int half = 0; half < 2; half++) {
                int row = row0 + half * 8;
                float v0 = acc[i][j][2*half]     + bv0;
                float v1 = acc[i][j][2*half + 1] + bv1;
                if (flags & FLAG_GELU) {
                    v0 = 0.5f * v0 * (1.0f + erff(v0 * 0.7071067811865476f));
                    v1 = 0.5f * v1 * (1.0f + erff(v1 * 0.7071067811865476f));
                }
                size_t ci = (size_t)row * N + col;
                if (flags & FLAG_RES) {
                    if (col < N)     v0 += res[ci];
                    if (col + 1 < N) v1 += res[ci + 1];
                }
                if (flags & FLAG_SPLITOUT) {
                    __nv_bfloat16 h0,l0,h1,l1;
                    split1(v0,h0,l0); split1(v1,h1,l1);
                    if (col < N)     { Chi[ci]   = h0; Clo[ci]   = l0; }
                    if (col + 1 < N) { Chi[ci+1] = h1; Clo[ci+1] = l1; }
                } else {
                    if (col < N)     C[ci]   = v0;
                    if (col + 1 < N) C[ci+1] = v1;
                }
            }
        }
    }
}

// ---------------- flash attention: 64 queries per block ----------------
// grid (T/64, NH, B), 256 threads. smem: Q,K,V,P tiles 64x68 fp32.
#define ATT_SMEM (4 * 64 * 68 * 4)
__global__ __launch_bounds__(256)
void attn_flash(const float* __restrict__ qkv,
                __nv_bfloat16* __restrict__ oh, __nv_bfloat16* __restrict__ ol) {
    extern __shared__ float sm[];
    float* Qs = sm;                 // [64][68]
    float* Ks = sm + 64 * 68;       // [64][68], col4 XOR-swizzled by (row>>4)
    float* Vs = sm + 2 * 64 * 68;   // [64][68]
    float* Ps = sm + 3 * 64 * 68;   // [64][68]

    const int qt = blockIdx.x, h = blockIdx.y, b = blockIdx.z;
    const int tid = threadIdx.x;
    const int q   = tid >> 2;       // 0..63
    const int sg  = tid & 3;        // k-group (scores) / d-group (AV & out)
    const int q_glob = qt * 64 + q;

    // load Q tile
    for (int i = tid; i < 64 * 16; i += 256) {
        int r = i >> 4, c4 = (i & 15);
        float4 v = *(const float4*)&qkv[((size_t)(b*Tt + qt*64 + r))*(3*Ee) + h*HDd + c4*4];
        *(float4*)&Qs[r * 68 + c4 * 4] = v;
    }

    float m_run = -1e30f, l_run = 0.f;
    float out[16];
    #pragma unroll
    for (int i = 0; i < 16; i++) out[i] = 0.f;
    __syncthreads();

    for (int kt = 0; kt <= qt; kt++) {
        // load K (swizzled) + V tiles
        for (int i = tid; i < 64 * 16; i += 256) {
            int r = i >> 4, c4 = (i & 15);
            size_t base = ((size_t)(b*Tt + kt*64 + r)) * (3*Ee) + h*HDd;
            float4 kv = *(const float4*)&qkv[base + Ee   + c4*4];
            float4 vv = *(const float4*)&qkv[base + 2*Ee + c4*4];
            *(float4*)&Ks[r * 68 + (c4 ^ ((r >> 4) & 3)) * 4] = kv;
            *(float4*)&Vs[r * 68 + c4 * 4] = vv;
        }
        __syncthreads();

        // scores for k = kt*64 + sg*16 + kk
        float s[16];
        #pragma unroll
        for (int kk = 0; kk < 16; kk++) s[kk] = 0.f;
        #pragma unroll
        for (int d4 = 0; d4 < 16; d4++) {
            float4 qv = *(const float4*)&Qs[q * 68 + d4 * 4];
            #pragma unroll
            for (int kk = 0; kk < 16; kk++) {
                int krow = sg * 16 + kk;
                float4 kv = *(const float4*)&Ks[krow * 68 + (d4 ^ sg) * 4];
                s[kk] = fmaf(qv.x, kv.x, fmaf(qv.y, kv.y, fmaf(qv.z, kv.z, fmaf(qv.w, kv.w, s[kk]))));
            }
        }
        const int k0g = kt * 64 + sg * 16;
        float lmax = -1e30f;
        #pragma unroll
        for (int kk = 0; kk < 16; kk++) {
            s[kk] *= 0.125f;
            if (k0g + kk > q_glob) s[kk] = -1e30f;
            lmax = fmaxf(lmax, s[kk]);
        }
        lmax = fmaxf(lmax, __shfl_xor_sync(0xFFFFFFFFu, lmax, 1));
        lmax = fmaxf(lmax, __shfl_xor_sync(0xFFFFFFFFu, lmax, 2));
        float mnew = fmaxf(m_run, lmax);
        float f = __expf(m_run - mnew);
        l_run *= f;
        #pragma unroll
        for (int i = 0; i < 16; i++) out[i] *= f;
        float psum = 0.f;
        #pragma unroll
        for (int kk = 0; kk < 16; kk++) {
            float p = __expf(s[kk] - mnew);
            psum += p;
            Ps[q * 68 + sg * 16 + kk] = p;
        }
        psum += __shfl_xor_sync(0xFFFFFFFFu, psum, 1);
        psum += __shfl_xor_sync(0xFFFFFFFFu, psum, 2);
        l_run += psum;
        m_run = mnew;
        __syncwarp();   // Ps rows for q are written within this warp

        // AV: out[q][sg*16 + dd] += sum_k P[q][k] * V[k][sg*16 + dd]
        for (int k = 0; k < 64; k++) {
            float p = Ps[q * 68 + k];
            #pragma unroll
            for (int d4i = 0; d4i < 4; d4i++) {
                float4 vv = *(const float4*)&Vs[k * 68 + sg * 16 + d4i * 4];
                out[d4i*4+0] = fmaf(p, vv.x, out[d4i*4+0]);
                out[d4i*4+1] = fmaf(p, vv.y, out[d4i*4+1]);
                out[d4i*4+2] = fmaf(p, vv.z, out[d4i*4+2]);
                out[d4i*4+3] = fmaf(p, vv.w, out[d4i*4+3]);
            }
        }
        __syncthreads();
    }

    float inv = 1.0f / l_run;
    size_t obase = ((size_t)(b*Tt + q_glob)) * Ee + h * HDd + sg * 16;
    #pragma unroll
    for (int i = 0; i < 16; i++) {
        float o = out[i] * inv;
        __nv_bfloat16 hh, ll; split1(o, hh, ll);
        oh[obase + i] = hh; ol[obase + i] = ll;
    }
}

// ---------------- launcher ----------------
#define GEMM_SMEM_128 (2 * (2*128*80 + 2*W_TILE_B))   // 81920
#define GEMM_SMEM_64  (3 * (2*64*80  + 2*W_TILE_B))   // 92160

static void run_gemm(const __nv_bfloat16* Ah, const __nv_bfloat16* Al,
                     const __nv_bfloat16* Wh, const __nv_bfloat16* Wl,
                     const float* bias, const float* res,
                     float* C, __nv_bfloat16* Chi, __nv_bfloat16* Clo,
                     int N, int K, int flags, bool narrow) {
    if (narrow) {
        dim3 g(BT / 64, (N + 127) / 128);
        gemm_mma<64,3><<<g, 256, GEMM_SMEM_64>>>(Ah, Al, Wh, Wl, bias, res, C, Chi, Clo, N, K, flags);
    } else {
        dim3 g(BT / 128, (N + 127) / 128);
        gemm_mma<128,2><<<g, 256, GEMM_SMEM_128>>>(Ah, Al, Wh, Wl, bias, res, C, Chi, Clo, N, K, flags);
    }
}

static void run_split(const float* src, __nv_bfloat16* hi, __nv_bfloat16* lo, long n) {
    int n4 = (int)(n / 4);
    split_kernel<<<(n4 + 255) / 256, 256>>>(src, hi, lo, n4);
}

extern "C" void kernel_launch(void* const* d_in, const int* in_sizes, int n_in,
                              void* d_out, int out_size) {
    const int*   input_ids = (const int*)  d_in[0];
    const float* tok_emb   = (const float*)d_in[1];
    const float* pos_emb   = (const float*)d_in[2];
    const float* ln1_scale = (const float*)d_in[3];
    const float* ln1_bias  = (const float*)d_in[4];
    const float* qkv_w     = (const float*)d_in[5];
    const float* out_w     = (const float*)d_in[6];
    const float* ln2_scale = (const float*)d_in[7];
    const float* ln2_bias  = (const float*)d_in[8];
    const float* fc1_w     = (const float*)d_in[9];
    const float* fc1_b     = (const float*)d_in[10];
    const float* fc2_w     = (const float*)d_in[11];
    const float* fc2_b     = (const float*)d_in[12];
    const float* lnf_scale = (const float*)d_in[13];
    const float* lnf_bias  = (const float*)d_in[14];
    float* logits = (float*)d_out;

    cudaFuncSetAttribute((const void*)gemm_mma<128,2>, cudaFuncAttributeMaxDynamicSharedMemorySize, GEMM_SMEM_128);
    cudaFuncSetAttribute((const void*)gemm_mma<64,3>,  cudaFuncAttributeMaxDynamicSharedMemorySize, GEMM_SMEM_64);
    cudaFuncSetAttribute((const void*)attn_flash,      cudaFuncAttributeMaxDynamicSharedMemorySize, ATT_SMEM);

    float *x, *qkv;
    __nv_bfloat16 *hh, *hl, *ath, *atl, *fh, *fl;
    __nv_bfloat16 *qwh, *qwl, *owh, *owl, *f1h, *f1l, *f2h, *f2l, *teh, *tel;
    cudaGetSymbolAddress((void**)&x,   g_x);
    cudaGetSymbolAddress((void**)&qkv, g_qkv);
    cudaGetSymbolAddress((void**)&hh,  g_hh);  cudaGetSymbolAddress((void**)&hl,  g_hl);
    cudaGetSymbolAddress((void**)&ath, g_ath); cudaGetSymbolAddress((void**)&atl, g_atl);
    cudaGetSymbolAddress((void**)&fh,  g_fh);  cudaGetSymbolAddress((void**)&fl,  g_fl);
    cudaGetSymbolAddress((void**)&qwh, g_qw_h); cudaGetSymbolAddress((void**)&qwl, g_qw_l);
    cudaGetSymbolAddress((void**)&owh, g_ow_h); cudaGetSymbolAddress((void**)&owl, g_ow_l);
    cudaGetSymbolAddress((void**)&f1h, g_f1_h); cudaGetSymbolAddress((void**)&f1l, g_f1_l);
    cudaGetSymbolAddress((void**)&f2h, g_f2_h); cudaGetSymbolAddress((void**)&f2l, g_f2_l);
    cudaGetSymbolAddress((void**)&teh, g_te_h); cudaGetSymbolAddress((void**)&tel, g_te_l);

    // weight conversions (per replay; ~120us of HBM traffic)
    run_split(qkv_w, qwh, qwl, (long)Ll * 3 * Ee * Ee);
    run_split(out_w, owh, owl, (long)Ll * Ee * Ee);
    run_split(fc1_w, f1h, f1l, (long)Ll * FFf * Ee);
    run_split(fc2_w, f2h, f2l, (long)Ll * Ee * FFf);
    run_split(tok_emb, teh, tel, (long)Vv * Ee);

    embed_kernel<<<(BT * Ee + 255) / 256, 256>>>(input_ids, tok_emb, pos_emb, x);

    for (int l = 0; l < Ll; l++) {
        // attention block (pre-norm)
        ln_split_kernel<<<BT, 256>>>(x, ln1_scale + l * Ee, ln1_bias + l * Ee, hh, hl);
        run_gemm(hh, hl, qwh + (size_t)l * 3 * Ee * Ee, qwl + (size_t)l * 3 * Ee * Ee,
                 nullptr, nullptr, qkv, nullptr, nullptr, 3 * Ee, Ee, 0, false);
        attn_flash<<<dim3(Tt/64, NHh, Bb), 256, ATT_SMEM>>>(qkv, ath, atl);
        run_gemm(ath, atl, owh + (size_t)l * Ee * Ee, owl + (size_t)l * Ee * Ee,
                 nullptr, x, x, nullptr, nullptr, Ee, Ee, FLAG_RES, true);
        // FFN block (pre-norm)
        ln_split_kernel<<<BT, 256>>>(x, ln2_scale + l * Ee, ln2_bias + l * Ee, hh, hl);
        run_gemm(hh, hl, f1h + (size_t)l * FFf * Ee, f1l + (size_t)l * FFf * Ee,
                 fc1_b + (size_t)l * FFf, nullptr, nullptr, fh, fl,
                 FFf, Ee, FLAG_BIAS | FLAG_GELU | FLAG_SPLITOUT, false);
        run_gemm(fh, fl, f2h + (size_t)l * Ee * FFf, f2l + (size_t)l * Ee * FFf,
                 fc2_b + (size_t)l * Ee, x, x, nullptr, nullptr,
                 Ee, FFf, FLAG_BIAS | FLAG_RES, true);
    }

    // final layernorm + tied LM head
    ln_split_kernel<<<BT, 256>>>(x, lnf_scale, lnf_bias, hh, hl);
    run_gemm(hh, hl, teh, tel, nullptr, nullptr, logits, nullptr, nullptr,
             Vv, Ee, 0, false);
}

// round 7
// speedup vs baseline: 2.2992x; 1.0288x over previous
#include <cuda_runtime.h>
#include <cuda_bf16.h>
#include <cstdint>
#include <math.h>

// ---------------- problem constants ----------------
#define Vv 50257
#define Ee 768
#define NHh 12
#define HDd 64
#define Ll 4
#define Tt 1024
#define Bb 2
#define FFf 3072
#define BT (Bb*Tt)            // 2048 rows

// ---------------- scratch (static, no allocs) ----------------
__device__ float g_x  [BT * Ee];                      // residual stream (fp32)
__device__ float g_qkv[BT * 3*Ee];                    // qkv projection (fp32)
__device__ __nv_bfloat16 g_hh[BT*Ee],  g_hl[BT*Ee];   // LN output hi/lo
__device__ __nv_bfloat16 g_ath[BT*Ee], g_atl[BT*Ee];  // attn output hi/lo
__device__ __nv_bfloat16 g_fh[BT*FFf], g_fl[BT*FFf];  // ffn hidden hi/lo
// weight hi/lo
__device__ __nv_bfloat16 g_qw_h[Ll*3*Ee*Ee], g_qw_l[Ll*3*Ee*Ee];
__device__ __nv_bfloat16 g_ow_h[Ll*Ee*Ee],   g_ow_l[Ll*Ee*Ee];
__device__ __nv_bfloat16 g_f1_h[Ll*FFf*Ee],  g_f1_l[Ll*FFf*Ee];
__device__ __nv_bfloat16 g_f2_h[Ll*Ee*FFf],  g_f2_l[Ll*Ee*FFf];
__device__ __nv_bfloat16 g_te_h[Vv*Ee],      g_te_l[Vv*Ee];

__device__ __forceinline__ void split1(float v, __nv_bfloat16& h, __nv_bfloat16& l) {
    h = __float2bfloat16(v);
    l = __float2bfloat16(v - __bfloat162float(h));
}

__device__ __forceinline__ uint32_t smem_u32(const void* p) {
    uint32_t a;
    asm("{ .reg .u64 t; cvta.to.shared.u64 t, %1; cvt.u32.u64 %0, t; }" : "=r"(a) : "l"(p));
    return a;
}
__device__ __forceinline__ void cp16(uint32_t dst, const void* src) {
    asm volatile("cp.async.cg.shared.global [%0], [%1], 16;" :: "r"(dst), "l"(src));
}
#define CP_COMMIT() asm volatile("cp.async.commit_group;" ::: "memory")
template<int N> __device__ __forceinline__ void cp_wait() {
    asm volatile("cp.async.wait_group %0;" :: "n"(N) : "memory");
}

__device__ __forceinline__ void ldsm_x4(uint32_t a, uint32_t& r0, uint32_t& r1, uint32_t& r2, uint32_t& r3) {
    asm volatile("ldmatrix.sync.aligned.m8n8.x4.shared.b16 {%0,%1,%2,%3}, [%4];"
                 : "=r"(r0), "=r"(r1), "=r"(r2), "=r"(r3) : "r"(a));
}
__device__ __forceinline__ void mma16816(float* d, const uint32_t* a, const uint32_t* b) {
    asm volatile("mma.sync.aligned.m16n8k16.row.col.f32.bf16.bf16.f32 "
                 "{%0,%1,%2,%3}, {%4,%5,%6,%7}, {%8,%9}, {%0,%1,%2,%3};"
                 : "+f"(d[0]), "+f"(d[1]), "+f"(d[2]), "+f"(d[3])
                 : "r"(a[0]), "r"(a[1]), "r"(a[2]), "r"(a[3]), "r"(b[0]), "r"(b[1]));
}

// ---------------- fp32 -> bf16 hi/lo split ----------------
__global__ void split_kernel(const float* __restrict__ src,
                             __nv_bfloat16* __restrict__ hi,
                             __nv_bfloat16* __restrict__ lo, int n4) {
    int i = blockIdx.x * blockDim.x + threadIdx.x;
    if (i >= n4) return;
    float4 v = ((const float4*)src)[i];
    __nv_bfloat16 h0,h1,h2,h3,l0,l1,l2,l3;
    split1(v.x,h0,l0); split1(v.y,h1,l1); split1(v.z,h2,l2); split1(v.w,h3,l3);
    __nv_bfloat162 a,b,c,d;
    a.x=h0; a.y=h1; b.x=h2; b.y=h3; c.x=l0; c.y=l1; d.x=l2; d.y=l3;
    ((__nv_bfloat162*)hi)[2*i]   = a; ((__nv_bfloat162*)hi)[2*i+1] = b;
    ((__nv_bfloat162*)lo)[2*i]   = c; ((__nv_bfloat162*)lo)[2*i+1] = d;
}

// ---------------- embedding ----------------
__global__ void embed_kernel(const int* __restrict__ ids, const float* __restrict__ tok,
                             const float* __restrict__ pos, float* __restrict__ out) {
    int i = blockIdx.x * blockDim.x + threadIdx.x;
    if (i >= BT * Ee) return;
    int e = i % Ee, row = i / Ee, t = row % Tt;
    out[i] = tok[(size_t)ids[row] * Ee + e] + pos[t * Ee + e];
}

// ---------------- layernorm -> split bf16 hi/lo ----------------
__global__ void ln_split_kernel(const float* __restrict__ x,
                                const float* __restrict__ scale, const float* __restrict__ bias,
                                __nv_bfloat16* __restrict__ oh, __nv_bfloat16* __restrict__ ol) {
    __shared__ float s1[256], s2[256];
    int row = blockIdx.x, tid = threadIdx.x;
    const float* xr = x + (size_t)row * Ee;
    float sum = 0.f, sq = 0.f;
    for (int c = tid; c < Ee; c += 256) { float v = xr[c]; sum += v; sq += v * v; }
    s1[tid] = sum; s2[tid] = sq; __syncthreads();
    for (int s = 128; s > 0; s >>= 1) {
        if (tid < s) { s1[tid] += s1[tid+s]; s2[tid] += s2[tid+s]; }
        __syncthreads();
    }
    float mean = s1[0] * (1.0f / Ee);
    float var  = s2[0] * (1.0f / Ee) - mean * mean;
    float rstd = rsqrtf(var + 1e-5f);
    for (int c = tid; c < Ee; c += 256) {
        float v = (xr[c] - mean) * rstd * scale[c] + bias[c];
        __nv_bfloat16 h, l; split1(v, h, l);
        oh[(size_t)row * Ee + c] = h; ol[(size_t)row * Ee + c] = l;
    }
}

// ---------------- HMMA GEMM: C = epi(A @ W^T), bf16x3 split ----------------
#define FLAG_BIAS 1
#define FLAG_GELU 2
#define FLAG_RES  4
#define FLAG_SPLITOUT 8

// SMEM tiles: rows x 32 bf16 (64B) padded to 80B stride.
#define W_TILE_B 10240
#define NSTAGE 3

template<int BM>
__global__ __launch_bounds__(256, 1)
void gemm_mma(const __nv_bfloat16* __restrict__ Ah, const __nv_bfloat16* __restrict__ Al,
              const __nv_bfloat16* __restrict__ Wh, const __nv_bfloat16* __restrict__ Wl,
              const float* __restrict__ bias, const float* __restrict__ res,
              float* __restrict__ C, __nv_bfloat16* __restrict__ Chi, __nv_bfloat16* __restrict__ Clo,
              int N, int K, int flags) {
    constexpr int A_TILE = BM * 80;
    constexpr int STAGE_B = 2 * A_TILE + 2 * W_TILE_B;
    constexpr int AC = BM * 4;               // A 16B chunks per tile
    constexpr int WNG = (BM == 128) ? 4 : 8; // warp cols
    constexpr int NJ  = (BM == 128) ? 4 : 2; // 8-col mma tiles per warp
    constexpr int NP  = (BM == 128) ? 2 : 1; // B ldsm pair iters
    constexpr int WNW = 128 / WNG;           // warp n width
    constexpr int NIT = (2 * AC + 1024) / 256;

    extern __shared__ char smem[];
    const uint32_t sb = smem_u32(smem);
    const int tid  = threadIdx.x;
    const int lane = tid & 31;
    const int wid  = tid >> 5;
    const int wm   = wid / WNG;
    const int wn   = wid % WNG;
    const int bm   = blockIdx.x * BM;
    const int bn   = blockIdx.y * 128;

    float acc[4][NJ][4];
    #pragma unroll
    for (int i = 0; i < 4; i++)
        #pragma unroll
        for (int j = 0; j < NJ; j++)
            #pragma unroll
            for (int r = 0; r < 4; r++) acc[i][j][r] = 0.f;

    const int nc = K >> 5;   // BK = 32

    auto load_stage = [&](int c, int stage) {
        const int k0 = c << 5;
        const uint32_t sdst = sb + stage * STAGE_B;
        #pragma unroll
        for (int it = 0; it < NIT; it++) {
            int gi = it * 256 + tid;
            uint32_t dst; const __nv_bfloat16* src;
            if (gi < AC) {
                int row = gi >> 2, chunk = gi & 3;
                dst = sdst + row * 80 + chunk * 16;
                src = Ah + (size_t)(bm + row) * K + k0 + chunk * 8;
            } else if (gi < 2 * AC) {
                int li = gi - AC;
                int row = li >> 2, chunk = li & 3;
                dst = sdst + A_TILE + row * 80 + chunk * 16;
                src = Al + (size_t)(bm + row) * K + k0 + chunk * 8;
            } else if (gi < 2 * AC + 512) {
                int li = gi - 2 * AC;
                int row = li >> 2, chunk = li & 3;
                int gn = bn + row; if (gn > N - 1) gn = N - 1;
                dst = sdst + 2 * A_TILE + row * 80 + chunk * 16;
                src = Wh + (size_t)gn * K + k0 + chunk * 8;
            } else {
                int li = gi - 2 * AC - 512;
                int row = li >> 2, chunk = li & 3;
                int gn = bn + row; if (gn > N - 1) gn = N - 1;
                dst = sdst + 2 * A_TILE + W_TILE_B + row * 80 + chunk * 16;
                src = Wl + (size_t)gn * K + k0 + chunk * 8;
            }
            cp16(dst, src);
        }
    };

    // prologue: fill first NSTAGE-1 stages, one commit each
    #pragma unroll
    for (int s = 0; s < NSTAGE - 1; s++) {
        if (s < nc) load_stage(s, s);
        CP_COMMIT();
    }

    // register fragment sets for the two ks sub-steps of a chunk
    uint32_t fa_h[2][4][4], fa_l[2][4][4], fb_h[2][NJ][2], fb_l[2][NJ][2];

    auto load_frags = [&](uint32_t st, int ks, int slot) {
        #pragma unroll
        for (int p = 0; p < NP; p++) {
            int nrow = wn * WNW + p * 16 + (lane & 7) + 8 * (lane >> 4);
            uint32_t koff = ks * 32 + ((lane >> 3) & 1) * 16;
            uint32_t ahp = st + 2 * A_TILE + nrow * 80 + koff;
            uint32_t alp = st + 2 * A_TILE + W_TILE_B + nrow * 80 + koff;
            uint32_t r0,r1,r2,r3;
            ldsm_x4(ahp, r0, r1, r2, r3);
            fb_h[slot][2*p][0]=r0; fb_h[slot][2*p][1]=r1; fb_h[slot][2*p+1][0]=r2; fb_h[slot][2*p+1][1]=r3;
            ldsm_x4(alp, r0, r1, r2, r3);
            fb_l[slot][2*p][0]=r0; fb_l[slot][2*p][1]=r1; fb_l[slot][2*p+1][0]=r2; fb_l[slot][2*p+1][1]=r3;
        }
        #pragma unroll
        for (int i = 0; i < 4; i++) {
            int mrow = wm * 64 + i * 16 + (lane & 7) + 8 * ((lane >> 3) & 1);
            uint32_t koff = ks * 32 + (lane >> 4) * 16;
            ldsm_x4(st + mrow * 80 + koff,
                    fa_h[slot][i][0], fa_h[slot][i][1], fa_h[slot][i][2], fa_h[slot][i][3]);
            ldsm_x4(st + A_TILE + mrow * 80 + koff,
                    fa_l[slot][i][0], fa_l[slot][i][1], fa_l[slot][i][2], fa_l[slot][i][3]);
        }
    };

    for (int c = 0; c < nc; c++) {
        cp_wait<NSTAGE - 2>();     // stage c resident (pipeline depth kept by unconditional commits)
        __syncthreads();           // all warps done reading stage (c+2)%NSTAGE from iter c-1

        // issue loads for stage c+2 while computing chunk c
        if (c + NSTAGE - 1 < nc) load_stage(c + NSTAGE - 1, (c + NSTAGE - 1) % NSTAGE);
        CP_COMMIT();

        const uint32_t st = sb + (c % NSTAGE) * STAGE_B;
        // all ldsm for both ks sub-steps issued up front
        load_frags(st, 0, 0);
        load_frags(st, 1, 1);

        #pragma unroll
        for (int ks = 0; ks < 2; ks++) {
            #pragma unroll
            for (int i = 0; i < 4; i++)
                #pragma unroll
                for (int j = 0; j < NJ; j++) {
                    mma16816(acc[i][j], fa_h[ks][i], fb_h[ks][j]);
                    mma16816(acc[i][j], fa_h[ks][i], fb_l[ks][j]);
                    mma16816(acc[i][j], fa_l[ks][i], fb_h[ks][j]);
                }
        }
    }

    // ---- epilogue: scalar stores (adjacent lanes contiguous; safe for odd N) ----
    #pragma unroll
    for (int i = 0; i < 4; i++) {
        int row0 = bm + wm * 64 + i * 16 + (lane >> 2);
        #pragma unroll
        for (int j = 0; j < NJ; j++) {
            int col = bn + wn * WNW + j * 8 + (lane & 3) * 2;
            float bv0 = 0.f, bv1 = 0.f;
            if (flags & FLAG_BIAS) {
                if (col < N)     bv0 = bias[col];
                if (col + 1 < N) bv1 = bias[col + 1];
            }
            #pragma unroll
            for (int half = 0; half < 2; half++) {
                int row = row0 + half * 8;
                float v0 = acc[i][j][2*half]     + bv0;
                float v1 = acc[i][j][2*half + 1] + bv1;
                if (flags & FLAG_GELU) {
                    v0 = 0.5f * v0 * (1.0f + erff(v0 * 0.7071067811865476f));
                    v1 = 0.5f * v1 * (1.0f + erff(v1 * 0.7071067811865476f));
                }
                size_t ci = (size_t)row * N + col;
                if (flags & FLAG_RES) {
                    if (col < N)     v0 += res[ci];
                    if (col + 1 < N) v1 += res[ci + 1];
                }
                if (flags & FLAG_SPLITOUT) {
                    __nv_bfloat16 h0,l0,h1,l1;
                    split1(v0,h0,l0); split1(v1,h1,l1);
                    if (col < N)     { Chi[ci]   = h0; Clo[ci]   = l0; }
                    if (col + 1 < N) { Chi[ci+1] = h1; Clo[ci+1] = l1; }
                } else {
                    if (col < N)     C[ci]   = v0;
                    if (col + 1 < N) C[ci+1] = v1;
                }
            }
        }
    }
}

// ---------------- flash attention: 64 queries per block ----------------
// grid (T/64, NH, B), 256 threads. smem: Q,K,V,P tiles 64x68 fp32.
#define ATT_SMEM (4 * 64 * 68 * 4)
__global__ __launch_bounds__(256)
void attn_flash(const float* __restrict__ qkv,
                __nv_bfloat16* __restrict__ oh, __nv_bfloat16* __restrict__ ol) {
    extern __shared__ float sm[];
    float* Qs = sm;                 // [64][68]
    float* Ks = sm + 64 * 68;       // [64][68], col4 XOR-swizzled by (row>>4)
    float* Vs = sm + 2 * 64 * 68;   // [64][68]
    float* Ps = sm + 3 * 64 * 68;   // [64][68]

    const int qt = blockIdx.x, h = blockIdx.y, b = blockIdx.z;
    const int tid = threadIdx.x;
    const int q   = tid >> 2;       // 0..63
    const int sg  = tid & 3;        // k-group (scores) / d-group (AV & out)
    const int q_glob = qt * 64 + q;

    // load Q tile
    for (int i = tid; i < 64 * 16; i += 256) {
        int r = i >> 4, c4 = (i & 15);
        float4 v = *(const float4*)&qkv[((size_t)(b*Tt + qt*64 + r))*(3*Ee) + h*HDd + c4*4];
        *(float4*)&Qs[r * 68 + c4 * 4] = v;
    }

    float m_run = -1e30f, l_run = 0.f;
    float out[16];
    #pragma unroll
    for (int i = 0; i < 16; i++) out[i] = 0.f;
    __syncthreads();

    for (int kt = 0; kt <= qt; kt++) {
        // load K (swizzled) + V tiles
        for (int i = tid; i < 64 * 16; i += 256) {
            int r = i >> 4, c4 = (i & 15);
            size_t base = ((size_t)(b*Tt + kt*64 + r)) * (3*Ee) + h*HDd;
            float4 kv = *(const float4*)&qkv[base + Ee   + c4*4];
            float4 vv = *(const float4*)&qkv[base + 2*Ee + c4*4];
            *(float4*)&Ks[r * 68 + (c4 ^ ((r >> 4) & 3)) * 4] = kv;
            *(float4*)&Vs[r * 68 + c4 * 4] = vv;
        }
        __syncthreads();

        // scores for k = kt*64 + sg*16 + kk
        float s[16];
        #pragma unroll
        for (int kk = 0; kk < 16; kk++) s[kk] = 0.f;
        #pragma unroll
        for (int d4 = 0; d4 < 16; d4++) {
            float4 qv = *(const float4*)&Qs[q * 68 + d4 * 4];
            #pragma unroll
            for (int kk = 0; kk < 16; kk++) {
                int krow = sg * 16 + kk;
                float4 kv = *(const float4*)&Ks[krow * 68 + (d4 ^ sg) * 4];
                s[kk] = fmaf(qv.x, kv.x, fmaf(qv.y, kv.y, fmaf(qv.z, kv.z, fmaf(qv.w, kv.w, s[kk]))));
            }
        }
        const int k0g = kt * 64 + sg * 16;
        float lmax = -1e30f;
        #pragma unroll
        for (int kk = 0; kk < 16; kk++) {
            s[kk] *= 0.125f;
            if (k0g + kk > q_glob) s[kk] = -1e30f;
            lmax = fmaxf(lmax, s[kk]);
        }
        lmax = fmaxf(lmax, __shfl_xor_sync(0xFFFFFFFFu, lmax, 1));
        lmax = fmaxf(lmax, __shfl_xor_sync(0xFFFFFFFFu, lmax, 2));
        float mnew = fmaxf(m_run, lmax);
        float f = __expf(m_run - mnew);
        l_run *= f;
        #pragma unroll
        for (int i = 0; i < 16; i++) out[i] *= f;
        float psum = 0.f;
        #pragma unroll
        for (int kk = 0; kk < 16; kk++) {
            float p = __expf(s[kk] - mnew);
            psum += p;
            Ps[q * 68 + sg * 16 + kk] = p;
        }
        psum += __shfl_xor_sync(0xFFFFFFFFu, psum, 1);
        psum += __shfl_xor_sync(0xFFFFFFFFu, psum, 2);
        l_run += psum;
        m_run = mnew;
        __syncwarp();   // Ps rows for q are written within this warp

        // AV: out[q][sg*16 + dd] += sum_k P[q][k] * V[k][sg*16 + dd]
        for (int k = 0; k < 64; k++) {
            float p = Ps[q * 68 + k];
            #pragma unroll
            for (int d4i = 0; d4i < 4; d4i++) {
                float4 vv = *(const float4*)&Vs[k * 68 + sg * 16 + d4i * 4];
                out[d4i*4+0] = fmaf(p, vv.x, out[d4i*4+0]);
                out[d4i*4+1] = fmaf(p, vv.y, out[d4i*4+1]);
                out[d4i*4+2] = fmaf(p, vv.z, out[d4i*4+2]);
                out[d4i*4+3] = fmaf(p, vv.w, out[d4i*4+3]);
            }
        }
        __syncthreads();
    }

    float inv = 1.0f / l_run;
    size_t obase = ((size_t)(b*Tt + q_glob)) * Ee + h * HDd + sg * 16;
    #pragma unroll
    for (int i = 0; i < 16; i++) {
        float o = out[i] * inv;
        __nv_bfloat16 hh, ll; split1(o, hh, ll);
        oh[obase + i] = hh; ol[obase + i] = ll;
    }
}

// ---------------- launcher ----------------
#define GEMM_SMEM_128 (NSTAGE * (2*128*80 + 2*W_TILE_B))   // 122880
#define GEMM_SMEM_64  (NSTAGE * (2*64*80  + 2*W_TILE_B))   // 92160

static void run_gemm(const __nv_bfloat16* Ah, const __nv_bfloat16* Al,
                     const __nv_bfloat16* Wh, const __nv_bfloat16* Wl,
                     const float* bias, const float* res,
                     float* C, __nv_bfloat16* Chi, __nv_bfloat16* Clo,
                     int N, int K, int flags, bool narrow) {
    if (narrow) {
        dim3 g(BT / 64, (N + 127) / 128);
        gemm_mma<64><<<g, 256, GEMM_SMEM_64>>>(Ah, Al, Wh, Wl, bias, res, C, Chi, Clo, N, K, flags);
    } else {
        dim3 g(BT / 128, (N + 127) / 128);
        gemm_mma<128><<<g, 256, GEMM_SMEM_128>>>(Ah, Al, Wh, Wl, bias, res, C, Chi, Clo, N, K, flags);
    }
}

static void run_split(const float* src, __nv_bfloat16* hi, __nv_bfloat16* lo, long n) {
    int n4 = (int)(n / 4);
    split_kernel<<<(n4 + 255) / 256, 256>>>(src, hi, lo, n4);
}

extern "C" void kernel_launch(void* const* d_in, const int* in_sizes, int n_in,
                              void* d_out, int out_size) {
    const int*   input_ids = (const int*)  d_in[0];
    const float* tok_emb   = (const float*)d_in[1];
    const float* pos_emb   = (const float*)d_in[2];
    const float* ln1_scale = (const float*)d_in[3];
    const float* ln1_bias  = (const float*)d_in[4];
    const float* qkv_w     = (const float*)d_in[5];
    const float* out_w     = (const float*)d_in[6];
    const float* ln2_scale = (const float*)d_in[7];
    const float* ln2_bias  = (const float*)d_in[8];
    const float* fc1_w     = (const float*)d_in[9];
    const float* fc1_b     = (const float*)d_in[10];
    const float* fc2_w     = (const float*)d_in[11];
    const float* fc2_b     = (const float*)d_in[12];
    const float* lnf_scale = (const float*)d_in[13];
    const float* lnf_bias  = (const float*)d_in[14];
    float* logits = (float*)d_out;

    cudaFuncSetAttribute((const void*)gemm_mma<128>, cudaFuncAttributeMaxDynamicSharedMemorySize, GEMM_SMEM_128);
    cudaFuncSetAttribute((const void*)gemm_mma<64>,  cudaFuncAttributeMaxDynamicSharedMemorySize, GEMM_SMEM_64);
    cudaFuncSetAttribute((const void*)attn_flash,    cudaFuncAttributeMaxDynamicSharedMemorySize, ATT_SMEM);

    float *x, *qkv;
    __nv_bfloat16 *hh, *hl, *ath, *atl, *fh, *fl;
    __nv_bfloat16 *qwh, *qwl, *owh, *owl, *f1h, *f1l, *f2h, *f2l, *teh, *tel;
    cudaGetSymbolAddress((void**)&x,   g_x);
    cudaGetSymbolAddress((void**)&qkv, g_qkv);
    cudaGetSymbolAddress((void**)&hh,  g_hh);  cudaGetSymbolAddress((void**)&hl,  g_hl);
    cudaGetSymbolAddress((void**)&ath, g_ath); cudaGetSymbolAddress((void**)&atl, g_atl);
    cudaGetSymbolAddress((void**)&fh,  g_fh);  cudaGetSymbolAddress((void**)&fl,  g_fl);
    cudaGetSymbolAddress((void**)&qwh, g_qw_h); cudaGetSymbolAddress((void**)&qwl, g_qw_l);
    cudaGetSymbolAddress((void**)&owh, g_ow_h); cudaGetSymbolAddress((void**)&owl, g_ow_l);
    cudaGetSymbolAddress((void**)&f1h, g_f1_h); cudaGetSymbolAddress((void**)&f1l, g_f1_l);
    cudaGetSymbolAddress((void**)&f2h, g_f2_h); cudaGetSymbolAddress((void**)&f2l, g_f2_l);
    cudaGetSymbolAddress((void**)&teh, g_te_h); cudaGetSymbolAddress((void**)&tel, g_te_l);

    // weight conversions (per replay; ~180us of HBM traffic)
    run_split(qkv_w, qwh, qwl, (long)Ll * 3 * Ee * Ee);
    run_split(out_w, owh, owl, (long)Ll * Ee * Ee);
    run_split(fc1_w, f1h, f1l, (long)Ll * FFf * Ee);
    run_split(fc2_w, f2h, f2l, (long)Ll * Ee * FFf);
    run_split(tok_emb, teh, tel, (long)Vv * Ee);

    embed_kernel<<<(BT * Ee + 255) / 256, 256>>>(input_ids, tok_emb, pos_emb, x);

    for (int l = 0; l < Ll; l++) {
        // attention block (pre-norm)
        ln_split_kernel<<<BT, 256>>>(x, ln1_scale + l * Ee, ln1_bias + l * Ee, hh, hl);
        run_gemm(hh, hl, qwh + (size_t)l * 3 * Ee * Ee, qwl + (size_t)l * 3 * Ee * Ee,
                 nullptr, nullptr, qkv, nullptr, nullptr, 3 * Ee, Ee, 0, false);
        attn_flash<<<dim3(Tt/64, NHh, Bb), 256, ATT_SMEM>>>(qkv, ath, atl);
        run_gemm(ath, atl, owh + (size_t)l * Ee * Ee, owl + (size_t)l * Ee * Ee,
                 nullptr, x, x, nullptr, nullptr, Ee, Ee, FLAG_RES, true);
        // FFN block (pre-norm)
        ln_split_kernel<<<BT, 256>>>(x, ln2_scale + l * Ee, ln2_bias + l * Ee, hh, hl);
        run_gemm(hh, hl, f1h + (size_t)l * FFf * Ee, f1l + (size_t)l * FFf * Ee,
                 fc1_b + (size_t)l * FFf, nullptr, nullptr, fh, fl,
                 FFf, Ee, FLAG_BIAS | FLAG_GELU | FLAG_SPLITOUT, false);
        run_gemm(fh, fl, f2h + (size_t)l * Ee * FFf, f2l + (size_t)l * Ee * FFf,
                 fc2_b + (size_t)l * Ee, x, x, nullptr, nullptr,
                 Ee, FFf, FLAG_BIAS | FLAG_RES, true);
    }

    // final layernorm + tied LM head
    ln_split_kernel<<<BT, 256>>>(x, lnf_scale, lnf_bias, hh, hl);
    run_gemm(hh, hl, teh, tel, nullptr, nullptr, logits, nullptr, nullptr,
             Vv, Ee, 0, false);
}

// round 8
// speedup vs baseline: 2.4562x; 1.0683x over previous
#include <cuda_runtime.h>
#include <cuda_bf16.h>
#include <cuda_fp16.h>
#include <cstdint>
#include <math.h>

// ---------------- problem constants ----------------
#define Vv 50257
#define Ee 768
#define NHh 12
#define HDd 64
#define Ll 4
#define Tt 1024
#define Bb 2
#define FFf 3072
#define BT (Bb*Tt)            // 2048 rows

// ---------------- scratch (static, no allocs) ----------------
__device__ float g_x  [BT * Ee];                      // residual stream (fp32)
__device__ float g_qkv[BT * 3*Ee];                    // qkv projection (fp32)
__device__ __nv_bfloat16 g_hh[BT*Ee],  g_hl[BT*Ee];   // LN output hi/lo (bf16 or fp16 bits)
__device__ __nv_bfloat16 g_ath[BT*Ee], g_atl[BT*Ee];  // attn output hi/lo
__device__ __nv_bfloat16 g_fh[BT*FFf], g_fl[BT*FFf];  // ffn hidden hi/lo
// weight hi/lo
__device__ __nv_bfloat16 g_qw_h[Ll*3*Ee*Ee], g_qw_l[Ll*3*Ee*Ee];
__device__ __nv_bfloat16 g_ow_h[Ll*Ee*Ee],   g_ow_l[Ll*Ee*Ee];
__device__ __nv_bfloat16 g_f1_h[Ll*FFf*Ee],  g_f1_l[Ll*FFf*Ee];
__device__ __nv_bfloat16 g_f2_h[Ll*Ee*FFf],  g_f2_l[Ll*Ee*FFf];
__device__ __half        g_te_f[Vv*Ee];               // tied LM head weight, single fp16

__device__ __forceinline__ void split1(float v, __nv_bfloat16& h, __nv_bfloat16& l) {
    h = __float2bfloat16(v);
    l = __float2bfloat16(v - __bfloat162float(h));
}
__device__ __forceinline__ void split1f(float v, __half& h, __half& l) {
    h = __float2half(v);
    l = __float2half(v - __half2float(h));
}

__device__ __forceinline__ uint32_t smem_u32(const void* p) {
    uint32_t a;
    asm("{ .reg .u64 t; cvta.to.shared.u64 t, %1; cvt.u32.u64 %0, t; }" : "=r"(a) : "l"(p));
    return a;
}
__device__ __forceinline__ void cp16(uint32_t dst, const void* src) {
    asm volatile("cp.async.cg.shared.global [%0], [%1], 16;" :: "r"(dst), "l"(src));
}
#define CP_COMMIT() asm volatile("cp.async.commit_group;" ::: "memory")
template<int N> __device__ __forceinline__ void cp_wait() {
    asm volatile("cp.async.wait_group %0;" :: "n"(N) : "memory");
}

__device__ __forceinline__ void ldsm_x4(uint32_t a, uint32_t& r0, uint32_t& r1, uint32_t& r2, uint32_t& r3) {
    asm volatile("ldmatrix.sync.aligned.m8n8.x4.shared.b16 {%0,%1,%2,%3}, [%4];"
                 : "=r"(r0), "=r"(r1), "=r"(r2), "=r"(r3) : "r"(a));
}
__device__ __forceinline__ void mma16816(float* d, const uint32_t* a, const uint32_t* b) {
    asm volatile("mma.sync.aligned.m16n8k16.row.col.f32.bf16.bf16.f32 "
                 "{%0,%1,%2,%3}, {%4,%5,%6,%7}, {%8,%9}, {%0,%1,%2,%3};"
                 : "+f"(d[0]), "+f"(d[1]), "+f"(d[2]), "+f"(d[3])
                 : "r"(a[0]), "r"(a[1]), "r"(a[2]), "r"(a[3]), "r"(b[0]), "r"(b[1]));
}
__device__ __forceinline__ void mma16816f(float* d, const uint32_t* a, const uint32_t* b) {
    asm volatile("mma.sync.aligned.m16n8k16.row.col.f32.f16.f16.f32 "
                 "{%0,%1,%2,%3}, {%4,%5,%6,%7}, {%8,%9}, {%0,%1,%2,%3};"
                 : "+f"(d[0]), "+f"(d[1]), "+f"(d[2]), "+f"(d[3])
                 : "r"(a[0]), "r"(a[1]), "r"(a[2]), "r"(a[3]), "r"(b[0]), "r"(b[1]));
}

// ---------------- fp32 -> bf16 hi/lo split ----------------
__global__ void split_kernel(const float* __restrict__ src,
                             __nv_bfloat16* __restrict__ hi,
                             __nv_bfloat16* __restrict__ lo, int n4) {
    int i = blockIdx.x * blockDim.x + threadIdx.x;
    if (i >= n4) return;
    float4 v = ((const float4*)src)[i];
    __nv_bfloat16 h0,h1,h2,h3,l0,l1,l2,l3;
    split1(v.x,h0,l0); split1(v.y,h1,l1); split1(v.z,h2,l2); split1(v.w,h3,l3);
    __nv_bfloat162 a,b,c,d;
    a.x=h0; a.y=h1; b.x=h2; b.y=h3; c.x=l0; c.y=l1; d.x=l2; d.y=l3;
    ((__nv_bfloat162*)hi)[2*i]   = a; ((__nv_bfloat162*)hi)[2*i+1] = b;
    ((__nv_bfloat162*)lo)[2*i]   = c; ((__nv_bfloat162*)lo)[2*i+1] = d;
}

// ---------------- fp32 -> fp16 convert ----------------
__global__ void conv_f16_kernel(const float* __restrict__ src, __half* __restrict__ dst, int n4) {
    int i = blockIdx.x * blockDim.x + threadIdx.x;
    if (i >= n4) return;
    float4 v = ((const float4*)src)[i];
    __half2 a, b;
    a.x = __float2half(v.x); a.y = __float2half(v.y);
    b.x = __float2half(v.z); b.y = __float2half(v.w);
    ((__half2*)dst)[2*i] = a; ((__half2*)dst)[2*i+1] = b;
}

// ---------------- embedding ----------------
__global__ void embed_kernel(const int* __restrict__ ids, const float* __restrict__ tok,
                             const float* __restrict__ pos, float* __restrict__ out) {
    int i = blockIdx.x * blockDim.x + threadIdx.x;
    if (i >= BT * Ee) return;
    int e = i % Ee, row = i / Ee, t = row % Tt;
    out[i] = tok[(size_t)ids[row] * Ee + e] + pos[t * Ee + e];
}

// ---------------- layernorm -> split bf16 hi/lo ----------------
__global__ void ln_split_kernel(const float* __restrict__ x,
                                const float* __restrict__ scale, const float* __restrict__ bias,
                                __nv_bfloat16* __restrict__ oh, __nv_bfloat16* __restrict__ ol) {
    __shared__ float s1[256], s2[256];
    int row = blockIdx.x, tid = threadIdx.x;
    const float* xr = x + (size_t)row * Ee;
    float sum = 0.f, sq = 0.f;
    for (int c = tid; c < Ee; c += 256) { float v = xr[c]; sum += v; sq += v * v; }
    s1[tid] = sum; s2[tid] = sq; __syncthreads();
    for (int s = 128; s > 0; s >>= 1) {
        if (tid < s) { s1[tid] += s1[tid+s]; s2[tid] += s2[tid+s]; }
        __syncthreads();
    }
    float mean = s1[0] * (1.0f / Ee);
    float var  = s2[0] * (1.0f / Ee) - mean * mean;
    float rstd = rsqrtf(var + 1e-5f);
    for (int c = tid; c < Ee; c += 256) {
        float v = (xr[c] - mean) * rstd * scale[c] + bias[c];
        __nv_bfloat16 h, l; split1(v, h, l);
        oh[(size_t)row * Ee + c] = h; ol[(size_t)row * Ee + c] = l;
    }
}

// ---------------- layernorm -> split fp16 hi/lo (for LM head) ----------------
__global__ void ln_split_f16_kernel(const float* __restrict__ x,
                                    const float* __restrict__ scale, const float* __restrict__ bias,
                                    __half* __restrict__ oh, __half* __restrict__ ol) {
    __shared__ float s1[256], s2[256];
    int row = blockIdx.x, tid = threadIdx.x;
    const float* xr = x + (size_t)row * Ee;
    float sum = 0.f, sq = 0.f;
    for (int c = tid; c < Ee; c += 256) { float v = xr[c]; sum += v; sq += v * v; }
    s1[tid] = sum; s2[tid] = sq; __syncthreads();
    for (int s = 128; s > 0; s >>= 1) {
        if (tid < s) { s1[tid] += s1[tid+s]; s2[tid] += s2[tid+s]; }
        __syncthreads();
    }
    float mean = s1[0] * (1.0f / Ee);
    float var  = s2[0] * (1.0f / Ee) - mean * mean;
    float rstd = rsqrtf(var + 1e-5f);
    for (int c = tid; c < Ee; c += 256) {
        float v = (xr[c] - mean) * rstd * scale[c] + bias[c];
        __half h, l; split1f(v, h, l);
        oh[(size_t)row * Ee + c] = h; ol[(size_t)row * Ee + c] = l;
    }
}

// ---------------- HMMA GEMM: C = epi(A @ W^T), bf16x3 split ----------------
#define FLAG_BIAS 1
#define FLAG_GELU 2
#define FLAG_RES  4
#define FLAG_SPLITOUT 8

// SMEM tiles: rows x 32 bf16 (64B) padded to 80B stride.
#define W_TILE_B 10240
#define NSTAGE 3

template<int BM>
__global__ __launch_bounds__(256, 1)
void gemm_mma(const __nv_bfloat16* __restrict__ Ah, const __nv_bfloat16* __restrict__ Al,
              const __nv_bfloat16* __restrict__ Wh, const __nv_bfloat16* __restrict__ Wl,
              const float* __restrict__ bias, const float* __restrict__ res,
              float* __restrict__ C, __nv_bfloat16* __restrict__ Chi, __nv_bfloat16* __restrict__ Clo,
              int N, int K, int flags) {
    constexpr int A_TILE = BM * 80;
    constexpr int STAGE_B = 2 * A_TILE + 2 * W_TILE_B;
    constexpr int AC = BM * 4;               // A 16B chunks per tile
    constexpr int WNG = (BM == 128) ? 4 : 8; // warp cols
    constexpr int NJ  = (BM == 128) ? 4 : 2; // 8-col mma tiles per warp
    constexpr int NP  = (BM == 128) ? 2 : 1; // B ldsm pair iters
    constexpr int WNW = 128 / WNG;           // warp n width
    constexpr int NIT = (2 * AC + 1024) / 256;

    extern __shared__ char smem[];
    const uint32_t sb = smem_u32(smem);
    const int tid  = threadIdx.x;
    const int lane = tid & 31;
    const int wid  = tid >> 5;
    const int wm   = wid / WNG;
    const int wn   = wid % WNG;
    const int bm   = blockIdx.x * BM;
    const int bn   = blockIdx.y * 128;

    float acc[4][NJ][4];
    #pragma unroll
    for (int i = 0; i < 4; i++)
        #pragma unroll
        for (int j = 0; j < NJ; j++)
            #pragma unroll
            for (int r = 0; r < 4; r++) acc[i][j][r] = 0.f;

    const int nc = K >> 5;   // BK = 32

    auto load_stage = [&](int c, int stage) {
        const int k0 = c << 5;
        const uint32_t sdst = sb + stage * STAGE_B;
        #pragma unroll
        for (int it = 0; it < NIT; it++) {
            int gi = it * 256 + tid;
            uint32_t dst; const __nv_bfloat16* src;
            if (gi < AC) {
                int row = gi >> 2, chunk = gi & 3;
                dst = sdst + row * 80 + chunk * 16;
                src = Ah + (size_t)(bm + row) * K + k0 + chunk * 8;
            } else if (gi < 2 * AC) {
                int li = gi - AC;
                int row = li >> 2, chunk = li & 3;
                dst = sdst + A_TILE + row * 80 + chunk * 16;
                src = Al + (size_t)(bm + row) * K + k0 + chunk * 8;
            } else if (gi < 2 * AC + 512) {
                int li = gi - 2 * AC;
                int row = li >> 2, chunk = li & 3;
                int gn = bn + row; if (gn > N - 1) gn = N - 1;
                dst = sdst + 2 * A_TILE + row * 80 + chunk * 16;
                src = Wh + (size_t)gn * K + k0 + chunk * 8;
            } else {
                int li = gi - 2 * AC - 512;
                int row = li >> 2, chunk = li & 3;
                int gn = bn + row; if (gn > N - 1) gn = N - 1;
                dst = sdst + 2 * A_TILE + W_TILE_B + row * 80 + chunk * 16;
                src = Wl + (size_t)gn * K + k0 + chunk * 8;
            }
            cp16(dst, src);
        }
    };

    #pragma unroll
    for (int s = 0; s < NSTAGE - 1; s++) {
        if (s < nc) load_stage(s, s);
        CP_COMMIT();
    }

    uint32_t fa_h[2][4][4], fa_l[2][4][4], fb_h[2][NJ][2], fb_l[2][NJ][2];

    auto load_frags = [&](uint32_t st, int ks, int slot) {
        #pragma unroll
        for (int p = 0; p < NP; p++) {
            int nrow = wn * WNW + p * 16 + (lane & 7) + 8 * (lane >> 4);
            uint32_t koff = ks * 32 + ((lane >> 3) & 1) * 16;
            uint32_t ahp = st + 2 * A_TILE + nrow * 80 + koff;
            uint32_t alp = st + 2 * A_TILE + W_TILE_B + nrow * 80 + koff;
            uint32_t r0,r1,r2,r3;
            ldsm_x4(ahp, r0, r1, r2, r3);
            fb_h[slot][2*p][0]=r0; fb_h[slot][2*p][1]=r1; fb_h[slot][2*p+1][0]=r2; fb_h[slot][2*p+1][1]=r3;
            ldsm_x4(alp, r0, r1, r2, r3);
            fb_l[slot][2*p][0]=r0; fb_l[slot][2*p][1]=r1; fb_l[slot][2*p+1][0]=r2; fb_l[slot][2*p+1][1]=r3;
        }
        #pragma unroll
        for (int i = 0; i < 4; i++) {
            int mrow = wm * 64 + i * 16 + (lane & 7) + 8 * ((lane >> 3) & 1);
            uint32_t koff = ks * 32 + (lane >> 4) * 16;
            ldsm_x4(st + mrow * 80 + koff,
                    fa_h[slot][i][0], fa_h[slot][i][1], fa_h[slot][i][2], fa_h[slot][i][3]);
            ldsm_x4(st + A_TILE + mrow * 80 + koff,
                    fa_l[slot][i][0], fa_l[slot][i][1], fa_l[slot][i][2], fa_l[slot][i][3]);
        }
    };

    for (int c = 0; c < nc; c++) {
        cp_wait<NSTAGE - 2>();
        __syncthreads();

        if (c + NSTAGE - 1 < nc) load_stage(c + NSTAGE - 1, (c + NSTAGE - 1) % NSTAGE);
        CP_COMMIT();

        const uint32_t st = sb + (c % NSTAGE) * STAGE_B;
        load_frags(st, 0, 0);
        load_frags(st, 1, 1);

        #pragma unroll
        for (int ks = 0; ks < 2; ks++) {
            #pragma unroll
            for (int i = 0; i < 4; i++)
                #pragma unroll
                for (int j = 0; j < NJ; j++) {
                    mma16816(acc[i][j], fa_h[ks][i], fb_h[ks][j]);
                    mma16816(acc[i][j], fa_h[ks][i], fb_l[ks][j]);
                    mma16816(acc[i][j], fa_l[ks][i], fb_h[ks][j]);
                }
        }
    }

    #pragma unroll
    for (int i = 0; i < 4; i++) {
        int row0 = bm + wm * 64 + i * 16 + (lane >> 2);
        #pragma unroll
        for (int j = 0; j < NJ; j++) {
            int col = bn + wn * WNW + j * 8 + (lane & 3) * 2;
            float bv0 = 0.f, bv1 = 0.f;
            if (flags & FLAG_BIAS) {
                if (col < N)     bv0 = bias[col];
                if (col + 1 < N) bv1 = bias[col + 1];
            }
            #pragma unroll
            for (int half = 0; half < 2; half++) {
                int row = row0 + half * 8;
                float v0 = acc[i][j][2*half]     + bv0;
                float v1 = acc[i][j][2*half + 1] + bv1;
                if (flags & FLAG_GELU) {
                    v0 = 0.5f * v0 * (1.0f + erff(v0 * 0.7071067811865476f));
                    v1 = 0.5f * v1 * (1.0f + erff(v1 * 0.7071067811865476f));
                }
                size_t ci = (size_t)row * N + col;
                if (flags & FLAG_RES) {
                    if (col < N)     v0 += res[ci];
                    if (col + 1 < N) v1 += res[ci + 1];
                }
                if (flags & FLAG_SPLITOUT) {
                    __nv_bfloat16 h0,l0,h1,l1;
                    split1(v0,h0,l0); split1(v1,h1,l1);
                    if (col < N)     { Chi[ci]   = h0; Clo[ci]   = l0; }
                    if (col + 1 < N) { Chi[ci+1] = h1; Clo[ci+1] = l1; }
                } else {
                    if (col < N)     C[ci]   = v0;
                    if (col + 1 < N) C[ci+1] = v1;
                }
            }
        }
    }
}

// ---------------- LM-head GEMM: fp16 2-product (A hi/lo fp16, W single fp16) ----------------
#define STAGE_B_H (2 * 128 * 80 + W_TILE_B)   // 30720
#define GEMM_SMEM_H (NSTAGE * STAGE_B_H)      // 92160

__global__ __launch_bounds__(256, 1)
void gemm_head(const __half* __restrict__ Ah, const __half* __restrict__ Al,
               const __half* __restrict__ W, float* __restrict__ C, int N, int K) {
    constexpr int A_TILE = 128 * 80;
    extern __shared__ char smem[];
    const uint32_t sb = smem_u32(smem);
    const int tid  = threadIdx.x;
    const int lane = tid & 31;
    const int wid  = tid >> 5;
    const int wm   = wid >> 2;
    const int wn   = wid & 3;
    const int bm   = blockIdx.x * 128;
    const int bn   = blockIdx.y * 128;

    float acc[4][4][4];
    #pragma unroll
    for (int i = 0; i < 4; i++)
        #pragma unroll
        for (int j = 0; j < 4; j++)
            #pragma unroll
            for (int r = 0; r < 4; r++) acc[i][j][r] = 0.f;

    const int nc = K >> 5;

    auto load_stage = [&](int c, int stage) {
        const int k0 = c << 5;
        const uint32_t sdst = sb + stage * STAGE_B_H;
        #pragma unroll
        for (int it = 0; it < 6; it++) {     // 1536 chunks / 256
            int gi = it * 256 + tid;
            uint32_t dst; const __half* src;
            if (gi < 512) {
                int row = gi >> 2, chunk = gi & 3;
                dst = sdst + row * 80 + chunk * 16;
                src = Ah + (size_t)(bm + row) * K + k0 + chunk * 8;
            } else if (gi < 1024) {
                int li = gi - 512;
                int row = li >> 2, chunk = li & 3;
                dst = sdst + A_TILE + row * 80 + chunk * 16;
                src = Al + (size_t)(bm + row) * K + k0 + chunk * 8;
            } else {
                int li = gi - 1024;
                int row = li >> 2, chunk = li & 3;
                int gn = bn + row; if (gn > N - 1) gn = N - 1;
                dst = sdst + 2 * A_TILE + row * 80 + chunk * 16;
                src = W + (size_t)gn * K + k0 + chunk * 8;
            }
            cp16(dst, src);
        }
    };

    #pragma unroll
    for (int s = 0; s < NSTAGE - 1; s++) {
        if (s < nc) load_stage(s, s);
        CP_COMMIT();
    }

    uint32_t fa_h[2][4][4], fa_l[2][4][4], fb[2][4][2];

    for (int c = 0; c < nc; c++) {
        cp_wait<NSTAGE - 2>();
        __syncthreads();

        if (c + NSTAGE - 1 < nc) load_stage(c + NSTAGE - 1, (c + NSTAGE - 1) % NSTAGE);
        CP_COMMIT();

        const uint32_t st = sb + (c % NSTAGE) * STAGE_B_H;
        #pragma unroll
        for (int ks = 0; ks < 2; ks++) {
            #pragma unroll
            for (int p = 0; p < 2; p++) {
                int nrow = wn * 32 + p * 16 + (lane & 7) + 8 * (lane >> 4);
                uint32_t koff = ks * 32 + ((lane >> 3) & 1) * 16;
                uint32_t r0,r1,r2,r3;
                ldsm_x4(st + 2 * A_TILE + nrow * 80 + koff, r0, r1, r2, r3);
                fb[ks][2*p][0]=r0; fb[ks][2*p][1]=r1; fb[ks][2*p+1][0]=r2; fb[ks][2*p+1][1]=r3;
            }
            #pragma unroll
            for (int i = 0; i < 4; i++) {
                int mrow = wm * 64 + i * 16 + (lane & 7) + 8 * ((lane >> 3) & 1);
                uint32_t koff = ks * 32 + (lane >> 4) * 16;
                ldsm_x4(st + mrow * 80 + koff,
                        fa_h[ks][i][0], fa_h[ks][i][1], fa_h[ks][i][2], fa_h[ks][i][3]);
                ldsm_x4(st + A_TILE + mrow * 80 + koff,
                        fa_l[ks][i][0], fa_l[ks][i][1], fa_l[ks][i][2], fa_l[ks][i][3]);
            }
        }
        #pragma unroll
        for (int ks = 0; ks < 2; ks++) {
            #pragma unroll
            for (int i = 0; i < 4; i++)
                #pragma unroll
                for (int j = 0; j < 4; j++) {
                    mma16816f(acc[i][j], fa_h[ks][i], fb[ks][j]);
                    mma16816f(acc[i][j], fa_l[ks][i], fb[ks][j]);
                }
        }
    }

    #pragma unroll
    for (int i = 0; i < 4; i++) {
        int row0 = bm + wm * 64 + i * 16 + (lane >> 2);
        #pragma unroll
        for (int j = 0; j < 4; j++) {
            int col = bn + wn * 32 + j * 8 + (lane & 3) * 2;
            #pragma unroll
            for (int half = 0; half < 2; half++) {
                int row = row0 + half * 8;
                size_t ci = (size_t)row * N + col;
                if (col < N)     C[ci]   = acc[i][j][2*half];
                if (col + 1 < N) C[ci+1] = acc[i][j][2*half+1];
            }
        }
    }
}

// ---------------- flash attention: 64 queries per block ----------------
#define ATT_SMEM (4 * 64 * 68 * 4)
__global__ __launch_bounds__(256)
void attn_flash(const float* __restrict__ qkv,
                __nv_bfloat16* __restrict__ oh, __nv_bfloat16* __restrict__ ol) {
    extern __shared__ float sm[];
    float* Qs = sm;
    float* Ks = sm + 64 * 68;
    float* Vs = sm + 2 * 64 * 68;
    float* Ps = sm + 3 * 64 * 68;

    const int qt = blockIdx.x, h = blockIdx.y, b = blockIdx.z;
    const int tid = threadIdx.x;
    const int q   = tid >> 2;
    const int sg  = tid & 3;
    const int q_glob = qt * 64 + q;

    for (int i = tid; i < 64 * 16; i += 256) {
        int r = i >> 4, c4 = (i & 15);
        float4 v = *(const float4*)&qkv[((size_t)(b*Tt + qt*64 + r))*(3*Ee) + h*HDd + c4*4];
        *(float4*)&Qs[r * 68 + c4 * 4] = v;
    }

    float m_run = -1e30f, l_run = 0.f;
    float out[16];
    #pragma unroll
    for (int i = 0; i < 16; i++) out[i] = 0.f;
    __syncthreads();

    for (int kt = 0; kt <= qt; kt++) {
        for (int i = tid; i < 64 * 16; i += 256) {
            int r = i >> 4, c4 = (i & 15);
            size_t base = ((size_t)(b*Tt + kt*64 + r)) * (3*Ee) + h*HDd;
            float4 kv = *(const float4*)&qkv[base + Ee   + c4*4];
            float4 vv = *(const float4*)&qkv[base + 2*Ee + c4*4];
            *(float4*)&Ks[r * 68 + (c4 ^ ((r >> 4) & 3)) * 4] = kv;
            *(float4*)&Vs[r * 68 + c4 * 4] = vv;
        }
        __syncthreads();

        float s[16];
        #pragma unroll
        for (int kk = 0; kk < 16; kk++) s[kk] = 0.f;
        #pragma unroll
        for (int d4 = 0; d4 < 16; d4++) {
            float4 qv = *(const float4*)&Qs[q * 68 + d4 * 4];
            #pragma unroll
            for (int kk = 0; kk < 16; kk++) {
                int krow = sg * 16 + kk;
                float4 kv = *(const float4*)&Ks[krow * 68 + (d4 ^ sg) * 4];
                s[kk] = fmaf(qv.x, kv.x, fmaf(qv.y, kv.y, fmaf(qv.z, kv.z, fmaf(qv.w, kv.w, s[kk]))));
            }
        }
        const int k0g = kt * 64 + sg * 16;
        float lmax = -1e30f;
        #pragma unroll
        for (int kk = 0; kk < 16; kk++) {
            s[kk] *= 0.125f;
            if (k0g + kk > q_glob) s[kk] = -1e30f;
            lmax = fmaxf(lmax, s[kk]);
        }
        lmax = fmaxf(lmax, __shfl_xor_sync(0xFFFFFFFFu, lmax, 1));
        lmax = fmaxf(lmax, __shfl_xor_sync(0xFFFFFFFFu, lmax, 2));
        float mnew = fmaxf(m_run, lmax);
        float f = __expf(m_run - mnew);
        l_run *= f;
        #pragma unroll
        for (int i = 0; i < 16; i++) out[i] *= f;
        float psum = 0.f;
        #pragma unroll
        for (int kk = 0; kk < 16; kk++) {
            float p = __expf(s[kk] - mnew);
            psum += p;
            Ps[q * 68 + sg * 16 + kk] = p;
        }
        psum += __shfl_xor_sync(0xFFFFFFFFu, psum, 1);
        psum += __shfl_xor_sync(0xFFFFFFFFu, psum, 2);
        l_run += psum;
        m_run = mnew;
        __syncwarp();

        for (int k = 0; k < 64; k++) {
            float p = Ps[q * 68 + k];
            #pragma unroll
            for (int d4i = 0; d4i < 4; d4i++) {
                float4 vv = *(const float4*)&Vs[k * 68 + sg * 16 + d4i * 4];
                out[d4i*4+0] = fmaf(p, vv.x, out[d4i*4+0]);
                out[d4i*4+1] = fmaf(p, vv.y, out[d4i*4+1]);
                out[d4i*4+2] = fmaf(p, vv.z, out[d4i*4+2]);
                out[d4i*4+3] = fmaf(p, vv.w, out[d4i*4+3]);
            }
        }
        __syncthreads();
    }

    float inv = 1.0f / l_run;
    size_t obase = ((size_t)(b*Tt + q_glob)) * Ee + h * HDd + sg * 16;
    #pragma unroll
    for (int i = 0; i < 16; i++) {
        float o = out[i] * inv;
        __nv_bfloat16 hh, ll; split1(o, hh, ll);
        oh[obase + i] = hh; ol[obase + i] = ll;
    }
}

// ---------------- launcher ----------------
#define GEMM_SMEM_128 (NSTAGE * (2*128*80 + 2*W_TILE_B))   // 122880
#define GEMM_SMEM_64  (NSTAGE * (2*64*80  + 2*W_TILE_B))   // 92160

static void run_gemm(const __nv_bfloat16* Ah, const __nv_bfloat16* Al,
                     const __nv_bfloat16* Wh, const __nv_bfloat16* Wl,
                     const float* bias, const float* res,
                     float* C, __nv_bfloat16* Chi, __nv_bfloat16* Clo,
                     int N, int K, int flags, bool narrow) {
    if (narrow) {
        dim3 g(BT / 64, (N + 127) / 128);
        gemm_mma<64><<<g, 256, GEMM_SMEM_64>>>(Ah, Al, Wh, Wl, bias, res, C, Chi, Clo, N, K, flags);
    } else {
        dim3 g(BT / 128, (N + 127) / 128);
        gemm_mma<128><<<g, 256, GEMM_SMEM_128>>>(Ah, Al, Wh, Wl, bias, res, C, Chi, Clo, N, K, flags);
    }
}

static void run_split(const float* src, __nv_bfloat16* hi, __nv_bfloat16* lo, long n) {
    int n4 = (int)(n / 4);
    split_kernel<<<(n4 + 255) / 256, 256>>>(src, hi, lo, n4);
}

extern "C" void kernel_launch(void* const* d_in, const int* in_sizes, int n_in,
                              void* d_out, int out_size) {
    const int*   input_ids = (const int*)  d_in[0];
    const float* tok_emb   = (const float*)d_in[1];
    const float* pos_emb   = (const float*)d_in[2];
    const float* ln1_scale = (const float*)d_in[3];
    const float* ln1_bias  = (const float*)d_in[4];
    const float* qkv_w     = (const float*)d_in[5];
    const float* out_w     = (const float*)d_in[6];
    const float* ln2_scale = (const float*)d_in[7];
    const float* ln2_bias  = (const float*)d_in[8];
    const float* fc1_w     = (const float*)d_in[9];
    const float* fc1_b     = (const float*)d_in[10];
    const float* fc2_w     = (const float*)d_in[11];
    const float* fc2_b     = (const float*)d_in[12];
    const float* lnf_scale = (const float*)d_in[13];
    const float* lnf_bias  = (const float*)d_in[14];
    float* logits = (float*)d_out;

    cudaFuncSetAttribute((const void*)gemm_mma<128>, cudaFuncAttributeMaxDynamicSharedMemorySize, GEMM_SMEM_128);
    cudaFuncSetAttribute((const void*)gemm_mma<64>,  cudaFuncAttributeMaxDynamicSharedMemorySize, GEMM_SMEM_64);
    cudaFuncSetAttribute((const void*)gemm_head,     cudaFuncAttributeMaxDynamicSharedMemorySize, GEMM_SMEM_H);
    cudaFuncSetAttribute((const void*)attn_flash,    cudaFuncAttributeMaxDynamicSharedMemorySize, ATT_SMEM);

    float *x, *qkv;
    __nv_bfloat16 *hh, *hl, *ath, *atl, *fh, *fl;
    __nv_bfloat16 *qwh, *qwl, *owh, *owl, *f1h, *f1l, *f2h, *f2l;
    __half *tef;
    cudaGetSymbolAddress((void**)&x,   g_x);
    cudaGetSymbolAddress((void**)&qkv, g_qkv);
    cudaGetSymbolAddress((void**)&hh,  g_hh);  cudaGetSymbolAddress((void**)&hl,  g_hl);
    cudaGetSymbolAddress((void**)&ath, g_ath); cudaGetSymbolAddress((void**)&atl, g_atl);
    cudaGetSymbolAddress((void**)&fh,  g_fh);  cudaGetSymbolAddress((void**)&fl,  g_fl);
    cudaGetSymbolAddress((void**)&qwh, g_qw_h); cudaGetSymbolAddress((void**)&qwl, g_qw_l);
    cudaGetSymbolAddress((void**)&owh, g_ow_h); cudaGetSymbolAddress((void**)&owl, g_ow_l);
    cudaGetSymbolAddress((void**)&f1h, g_f1_h); cudaGetSymbolAddress((void**)&f1l, g_f1_l);
    cudaGetSymbolAddress((void**)&f2h, g_f2_h); cudaGetSymbolAddress((void**)&f2l, g_f2_l);
    cudaGetSymbolAddress((void**)&tef, g_te_f);

    // weight conversions (per replay)
    run_split(qkv_w, qwh, qwl, (long)Ll * 3 * Ee * Ee);
    run_split(out_w, owh, owl, (long)Ll * Ee * Ee);
    run_split(fc1_w, f1h, f1l, (long)Ll * FFf * Ee);
    run_split(fc2_w, f2h, f2l, (long)Ll * Ee * FFf);
    {
        int n4 = (int)((long)Vv * Ee / 4);
        conv_f16_kernel<<<(n4 + 255) / 256, 256>>>(tok_emb, tef, n4);
    }

    embed_kernel<<<(BT * Ee + 255) / 256, 256>>>(input_ids, tok_emb, pos_emb, x);

    for (int l = 0; l < Ll; l++) {
        // attention block (pre-norm)
        ln_split_kernel<<<BT, 256>>>(x, ln1_scale + l * Ee, ln1_bias + l * Ee, hh, hl);
        run_gemm(hh, hl, qwh + (size_t)l * 3 * Ee * Ee, qwl + (size_t)l * 3 * Ee * Ee,
                 nullptr, nullptr, qkv, nullptr, nullptr, 3 * Ee, Ee, 0, false);
        attn_flash<<<dim3(Tt/64, NHh, Bb), 256, ATT_SMEM>>>(qkv, ath, atl);
        run_gemm(ath, atl, owh + (size_t)l * Ee * Ee, owl + (size_t)l * Ee * Ee,
                 nullptr, x, x, nullptr, nullptr, Ee, Ee, FLAG_RES, true);
        // FFN block (pre-norm)
        ln_split_kernel<<<BT, 256>>>(x, ln2_scale + l * Ee, ln2_bias + l * Ee, hh, hl);
        run_gemm(hh, hl, f1h + (size_t)l * FFf * Ee, f1l + (size_t)l * FFf * Ee,
                 fc1_b + (size_t)l * FFf, nullptr, nullptr, fh, fl,
                 FFf, Ee, FLAG_BIAS | FLAG_GELU | FLAG_SPLITOUT, false);
        run_gemm(fh, fl, f2h + (size_t)l * Ee * FFf, f2l + (size_t)l * Ee * FFf,
                 fc2_b + (size_t)l * Ee, x, x, nullptr, nullptr,
                 Ee, FFf, FLAG_BIAS | FLAG_RES, true);
    }

    // final layernorm (fp16 hi/lo) + tied LM head (fp16 2-product)
    ln_split_f16_kernel<<<BT, 256>>>(x, lnf_scale, lnf_bias, (__half*)hh, (__half*)hl);
    {
        dim3 g(BT / 128, (Vv + 127) / 128);
        gemm_head<<<g, 256, GEMM_SMEM_H>>>((const __half*)hh, (const __half*)hl, tef, logits, Vv, Ee);
    }
}

// round 9
// speedup vs baseline: 2.6774x; 1.0901x over previous
#include <cuda_runtime.h>
#include <cuda_bf16.h>
#include <cuda_fp16.h>
#include <cstdint>
#include <math.h>

// ---------------- problem constants ----------------
#define Vv 50257
#define Ee 768
#define NHh 12
#define HDd 64
#define Ll 4
#define Tt 1024
#define Bb 2
#define FFf 3072
#define BT (Bb*Tt)            // 2048 rows

// ---------------- scratch (static, no allocs) ----------------
__device__ float g_x  [BT * Ee];                 // residual stream (fp32)
__device__ float g_qkv[BT * 3*Ee];               // qkv projection (fp32)
__device__ __half g_hh[BT*Ee],  g_hl[BT*Ee];     // LN output hi/lo fp16
__device__ __half g_ath[BT*Ee], g_atl[BT*Ee];    // attn output hi/lo fp16
__device__ __half g_fh[BT*FFf], g_fl[BT*FFf];    // ffn hidden hi/lo fp16
// weights, single fp16
__device__ __half g_qw[Ll*3*Ee*Ee];
__device__ __half g_ow[Ll*Ee*Ee];
__device__ __half g_f1[Ll*FFf*Ee];
__device__ __half g_f2[Ll*Ee*FFf];
__device__ __half g_te[Vv*Ee];

__device__ __forceinline__ void split1f(float v, __half& h, __half& l) {
    h = __float2half(v);
    l = __float2half(v - __half2float(h));
}

__device__ __forceinline__ uint32_t smem_u32(const void* p) {
    uint32_t a;
    asm("{ .reg .u64 t; cvta.to.shared.u64 t, %1; cvt.u32.u64 %0, t; }" : "=r"(a) : "l"(p));
    return a;
}
__device__ __forceinline__ void cp16(uint32_t dst, const void* src) {
    asm volatile("cp.async.cg.shared.global [%0], [%1], 16;" :: "r"(dst), "l"(src));
}
#define CP_COMMIT() asm volatile("cp.async.commit_group;" ::: "memory")
template<int N> __device__ __forceinline__ void cp_wait() {
    asm volatile("cp.async.wait_group %0;" :: "n"(N) : "memory");
}

__device__ __forceinline__ void ldsm_x4(uint32_t a, uint32_t& r0, uint32_t& r1, uint32_t& r2, uint32_t& r3) {
    asm volatile("ldmatrix.sync.aligned.m8n8.x4.shared.b16 {%0,%1,%2,%3}, [%4];"
                 : "=r"(r0), "=r"(r1), "=r"(r2), "=r"(r3) : "r"(a));
}
__device__ __forceinline__ void mma16816f(float* d, const uint32_t* a, const uint32_t* b) {
    asm volatile("mma.sync.aligned.m16n8k16.row.col.f32.f16.f16.f32 "
                 "{%0,%1,%2,%3}, {%4,%5,%6,%7}, {%8,%9}, {%0,%1,%2,%3};"
                 : "+f"(d[0]), "+f"(d[1]), "+f"(d[2]), "+f"(d[3])
                 : "r"(a[0]), "r"(a[1]), "r"(a[2]), "r"(a[3]), "r"(b[0]), "r"(b[1]));
}

// ---------------- fp32 -> fp16 convert (weights) ----------------
__global__ void conv_f16_kernel(const float* __restrict__ src, __half* __restrict__ dst, int n4) {
    int i = blockIdx.x * blockDim.x + threadIdx.x;
    if (i >= n4) return;
    float4 v = ((const float4*)src)[i];
    __half2 a, b;
    a.x = __float2half(v.x); a.y = __float2half(v.y);
    b.x = __float2half(v.z); b.y = __float2half(v.w);
    ((__half2*)dst)[2*i] = a; ((__half2*)dst)[2*i+1] = b;
}

// ---------------- embedding ----------------
__global__ void embed_kernel(const int* __restrict__ ids, const float* __restrict__ tok,
                             const float* __restrict__ pos, float* __restrict__ out) {
    int i = blockIdx.x * blockDim.x + threadIdx.x;
    if (i >= BT * Ee) return;
    int e = i % Ee, row = i / Ee, t = row % Tt;
    out[i] = tok[(size_t)ids[row] * Ee + e] + pos[t * Ee + e];
}

// ---------------- layernorm -> split fp16 hi/lo ----------------
__global__ void ln_split_kernel(const float* __restrict__ x,
                                const float* __restrict__ scale, const float* __restrict__ bias,
                                __half* __restrict__ oh, __half* __restrict__ ol) {
    __shared__ float s1[256], s2[256];
    int row = blockIdx.x, tid = threadIdx.x;
    const float* xr = x + (size_t)row * Ee;
    float sum = 0.f, sq = 0.f;
    for (int c = tid; c < Ee; c += 256) { float v = xr[c]; sum += v; sq += v * v; }
    s1[tid] = sum; s2[tid] = sq; __syncthreads();
    for (int s = 128; s > 0; s >>= 1) {
        if (tid < s) { s1[tid] += s1[tid+s]; s2[tid] += s2[tid+s]; }
        __syncthreads();
    }
    float mean = s1[0] * (1.0f / Ee);
    float var  = s2[0] * (1.0f / Ee) - mean * mean;
    float rstd = rsqrtf(var + 1e-5f);
    for (int c = tid; c < Ee; c += 256) {
        float v = (xr[c] - mean) * rstd * scale[c] + bias[c];
        __half h, l; split1f(v, h, l);
        oh[(size_t)row * Ee + c] = h; ol[(size_t)row * Ee + c] = l;
    }
}

// ---------------- HMMA GEMM: C = epi(A @ W^T), fp16 2-product ----------------
// A: (2048,K) hi/lo fp16 row-major.  W: (N,K) single fp16 row-major.
#define FLAG_BIAS 1
#define FLAG_GELU 2
#define FLAG_RES  4
#define FLAG_SPLITOUT 8

#define W_TILE_B 10240   // 128 rows x 64B padded to 80B
#define NSTAGE 3

template<int BM>
__global__ __launch_bounds__(256, 1)
void gemm_mma(const __half* __restrict__ Ah, const __half* __restrict__ Al,
              const __half* __restrict__ W,
              const float* __restrict__ bias, const float* __restrict__ res,
              float* __restrict__ C, __half* __restrict__ Chi, __half* __restrict__ Clo,
              int N, int K, int flags) {
    constexpr int A_TILE = BM * 80;
    constexpr int STAGE_B = 2 * A_TILE + W_TILE_B;
    constexpr int AC = BM * 4;               // A 16B chunks per tile
    constexpr int WNG = (BM == 128) ? 4 : 8; // warp cols
    constexpr int NJ  = (BM == 128) ? 4 : 2; // 8-col mma tiles per warp
    constexpr int NP  = (BM == 128) ? 2 : 1; // B ldsm pair iters
    constexpr int WNW = 128 / WNG;           // warp n width
    constexpr int NIT = (2 * AC + 512) / 256;

    extern __shared__ char smem[];
    const uint32_t sb = smem_u32(smem);
    const int tid  = threadIdx.x;
    const int lane = tid & 31;
    const int wid  = tid >> 5;
    const int wm   = wid / WNG;
    const int wn   = wid % WNG;
    const int bm   = blockIdx.x * BM;
    const int bn   = blockIdx.y * 128;

    float acc[4][NJ][4];
    #pragma unroll
    for (int i = 0; i < 4; i++)
        #pragma unroll
        for (int j = 0; j < NJ; j++)
            #pragma unroll
            for (int r = 0; r < 4; r++) acc[i][j][r] = 0.f;

    const int nc = K >> 5;   // BK = 32

    auto load_stage = [&](int c, int stage) {
        const int k0 = c << 5;
        const uint32_t sdst = sb + stage * STAGE_B;
        #pragma unroll
        for (int it = 0; it < NIT; it++) {
            int gi = it * 256 + tid;
            uint32_t dst; const __half* src;
            if (gi < AC) {
                int row = gi >> 2, chunk = gi & 3;
                dst = sdst + row * 80 + chunk * 16;
                src = Ah + (size_t)(bm + row) * K + k0 + chunk * 8;
            } else if (gi < 2 * AC) {
                int li = gi - AC;
                int row = li >> 2, chunk = li & 3;
                dst = sdst + A_TILE + row * 80 + chunk * 16;
                src = Al + (size_t)(bm + row) * K + k0 + chunk * 8;
            } else {
                int li = gi - 2 * AC;
                int row = li >> 2, chunk = li & 3;
                int gn = bn + row; if (gn > N - 1) gn = N - 1;
                dst = sdst + 2 * A_TILE + row * 80 + chunk * 16;
                src = W + (size_t)gn * K + k0 + chunk * 8;
            }
            cp16(dst, src);
        }
    };

    #pragma unroll
    for (int s = 0; s < NSTAGE - 1; s++) {
        if (s < nc) load_stage(s, s);
        CP_COMMIT();
    }

    uint32_t fa_h[2][4][4], fa_l[2][4][4], fb[2][NJ][2];

    auto load_frags = [&](uint32_t st, int ks, int slot) {
        #pragma unroll
        for (int p = 0; p < NP; p++) {
            int nrow = wn * WNW + p * 16 + (lane & 7) + 8 * (lane >> 4);
            uint32_t koff = ks * 32 + ((lane >> 3) & 1) * 16;
            uint32_t r0,r1,r2,r3;
            ldsm_x4(st + 2 * A_TILE + nrow * 80 + koff, r0, r1, r2, r3);
            fb[slot][2*p][0]=r0; fb[slot][2*p][1]=r1; fb[slot][2*p+1][0]=r2; fb[slot][2*p+1][1]=r3;
        }
        #pragma unroll
        for (int i = 0; i < 4; i++) {
            int mrow = wm * 64 + i * 16 + (lane & 7) + 8 * ((lane >> 3) & 1);
            uint32_t koff = ks * 32 + (lane >> 4) * 16;
            ldsm_x4(st + mrow * 80 + koff,
                    fa_h[slot][i][0], fa_h[slot][i][1], fa_h[slot][i][2], fa_h[slot][i][3]);
            ldsm_x4(st + A_TILE + mrow * 80 + koff,
                    fa_l[slot][i][0], fa_l[slot][i][1], fa_l[slot][i][2], fa_l[slot][i][3]);
        }
    };

    for (int c = 0; c < nc; c++) {
        cp_wait<NSTAGE - 2>();
        __syncthreads();

        if (c + NSTAGE - 1 < nc) load_stage(c + NSTAGE - 1, (c + NSTAGE - 1) % NSTAGE);
        CP_COMMIT();

        const uint32_t st = sb + (c % NSTAGE) * STAGE_B;
        load_frags(st, 0, 0);
        load_frags(st, 1, 1);

        #pragma unroll
        for (int ks = 0; ks < 2; ks++) {
            #pragma unroll
            for (int i = 0; i < 4; i++)
                #pragma unroll
                for (int j = 0; j < NJ; j++) {
                    mma16816f(acc[i][j], fa_h[ks][i], fb[ks][j]);
                    mma16816f(acc[i][j], fa_l[ks][i], fb[ks][j]);
                }
        }
    }

    // ---- epilogue: scalar stores (adjacent lanes contiguous; safe for odd N) ----
    #pragma unroll
    for (int i = 0; i < 4; i++) {
        int row0 = bm + wm * 64 + i * 16 + (lane >> 2);
        #pragma unroll
        for (int j = 0; j < NJ; j++) {
            int col = bn + wn * WNW + j * 8 + (lane & 3) * 2;
            float bv0 = 0.f, bv1 = 0.f;
            if (flags & FLAG_BIAS) {
                if (col < N)     bv0 = bias[col];
                if (col + 1 < N) bv1 = bias[col + 1];
            }
            #pragma unroll
            for (int half = 0; half < 2; half++) {
                int row = row0 + half * 8;
                float v0 = acc[i][j][2*half]     + bv0;
                float v1 = acc[i][j][2*half + 1] + bv1;
                if (flags & FLAG_GELU) {
                    v0 = 0.5f * v0 * (1.0f + erff(v0 * 0.7071067811865476f));
                    v1 = 0.5f * v1 * (1.0f + erff(v1 * 0.7071067811865476f));
                }
                size_t ci = (size_t)row * N + col;
                if (flags & FLAG_RES) {
                    if (col < N)     v0 += res[ci];
                    if (col + 1 < N) v1 += res[ci + 1];
                }
                if (flags & FLAG_SPLITOUT) {
                    __half h0,l0,h1,l1;
                    split1f(v0,h0,l0); split1f(v1,h1,l1);
                    if (col < N)     { Chi[ci]   = h0; Clo[ci]   = l0; }
                    if (col + 1 < N) { Chi[ci+1] = h1; Clo[ci+1] = l1; }
                } else {
                    if (col < N)     C[ci]   = v0;
                    if (col + 1 < N) C[ci+1] = v1;
                }
            }
        }
    }
}

// ---------------- flash attention: 64 queries per block ----------------
#define ATT_SMEM (4 * 64 * 68 * 4)
__global__ __launch_bounds__(256)
void attn_flash(const float* __restrict__ qkv,
                __half* __restrict__ oh, __half* __restrict__ ol) {
    extern __shared__ float sm[];
    float* Qs = sm;
    float* Ks = sm + 64 * 68;
    float* Vs = sm + 2 * 64 * 68;
    float* Ps = sm + 3 * 64 * 68;

    const int qt = blockIdx.x, h = blockIdx.y, b = blockIdx.z;
    const int tid = threadIdx.x;
    const int q   = tid >> 2;
    const int sg  = tid & 3;
    const int q_glob = qt * 64 + q;

    for (int i = tid; i < 64 * 16; i += 256) {
        int r = i >> 4, c4 = (i & 15);
        float4 v = *(const float4*)&qkv[((size_t)(b*Tt + qt*64 + r))*(3*Ee) + h*HDd + c4*4];
        *(float4*)&Qs[r * 68 + c4 * 4] = v;
    }

    float m_run = -1e30f, l_run = 0.f;
    float out[16];
    #pragma unroll
    for (int i = 0; i < 16; i++) out[i] = 0.f;
    __syncthreads();

    for (int kt = 0; kt <= qt; kt++) {
        for (int i = tid; i < 64 * 16; i += 256) {
            int r = i >> 4, c4 = (i & 15);
            size_t base = ((size_t)(b*Tt + kt*64 + r)) * (3*Ee) + h*HDd;
            float4 kv = *(const float4*)&qkv[base + Ee   + c4*4];
            float4 vv = *(const float4*)&qkv[base + 2*Ee + c4*4];
            *(float4*)&Ks[r * 68 + (c4 ^ ((r >> 4) & 3)) * 4] = kv;
            *(float4*)&Vs[r * 68 + c4 * 4] = vv;
        }
        __syncthreads();

        float s[16];
        #pragma unroll
        for (int kk = 0; kk < 16; kk++) s[kk] = 0.f;
        #pragma unroll
        for (int d4 = 0; d4 < 16; d4++) {
            float4 qv = *(const float4*)&Qs[q * 68 + d4 * 4];
            #pragma unroll
            for (int kk = 0; kk < 16; kk++) {
                int krow = sg * 16 + kk;
                float4 kv = *(const float4*)&Ks[krow * 68 + (d4 ^ sg) * 4];
                s[kk] = fmaf(qv.x, kv.x, fmaf(qv.y, kv.y, fmaf(qv.z, kv.z, fmaf(qv.w, kv.w, s[kk]))));
            }
        }
        const int k0g = kt * 64 + sg * 16;
        float lmax = -1e30f;
        #pragma unroll
        for (int kk = 0; kk < 16; kk++) {
            s[kk] *= 0.125f;
            if (k0g + kk > q_glob) s[kk] = -1e30f;
            lmax = fmaxf(lmax, s[kk]);
        }
        lmax = fmaxf(lmax, __shfl_xor_sync(0xFFFFFFFFu, lmax, 1));
        lmax = fmaxf(lmax, __shfl_xor_sync(0xFFFFFFFFu, lmax, 2));
        float mnew = fmaxf(m_run, lmax);
        float f = __expf(m_run - mnew);
        l_run *= f;
        #pragma unroll
        for (int i = 0; i < 16; i++) out[i] *= f;
        float psum = 0.f;
        #pragma unroll
        for (int kk = 0; kk < 16; kk++) {
            float p = __expf(s[kk] - mnew);
            psum += p;
            Ps[q * 68 + sg * 16 + kk] = p;
        }
        psum += __shfl_xor_sync(0xFFFFFFFFu, psum, 1);
        psum += __shfl_xor_sync(0xFFFFFFFFu, psum, 2);
        l_run += psum;
        m_run = mnew;
        __syncwarp();

        for (int k = 0; k < 64; k++) {
            float p = Ps[q * 68 + k];
            #pragma unroll
            for (int d4i = 0; d4i < 4; d4i++) {
                float4 vv = *(const float4*)&Vs[k * 68 + sg * 16 + d4i * 4];
                out[d4i*4+0] = fmaf(p, vv.x, out[d4i*4+0]);
                out[d4i*4+1] = fmaf(p, vv.y, out[d4i*4+1]);
                out[d4i*4+2] = fmaf(p, vv.z, out[d4i*4+2]);
                out[d4i*4+3] = fmaf(p, vv.w, out[d4i*4+3]);
            }
        }
        __syncthreads();
    }

    float inv = 1.0f / l_run;
    size_t obase = ((size_t)(b*Tt + q_glob)) * Ee + h * HDd + sg * 16;
    #pragma unroll
    for (int i = 0; i < 16; i++) {
        float o = out[i] * inv;
        __half hh, ll; split1f(o, hh, ll);
        oh[obase + i] = hh; ol[obase + i] = ll;
    }
}

// ---------------- launcher ----------------
#define GEMM_SMEM_128 (NSTAGE * (2*128*80 + W_TILE_B))   // 92160
#define GEMM_SMEM_64  (NSTAGE * (2*64*80  + W_TILE_B))   // 61440

static void run_gemm(const __half* Ah, const __half* Al, const __half* W,
                     const float* bias, const float* res,
                     float* C, __half* Chi, __half* Clo,
                     int N, int K, int flags, bool narrow) {
    if (narrow) {
        dim3 g(BT / 64, (N + 127) / 128);
        gemm_mma<64><<<g, 256, GEMM_SMEM_64>>>(Ah, Al, W, bias, res, C, Chi, Clo, N, K, flags);
    } else {
        dim3 g(BT / 128, (N + 127) / 128);
        gemm_mma<128><<<g, 256, GEMM_SMEM_128>>>(Ah, Al, W, bias, res, C, Chi, Clo, N, K, flags);
    }
}

static void run_conv(const float* src, __half* dst, long n) {
    int n4 = (int)(n / 4);
    conv_f16_kernel<<<(n4 + 255) / 256, 256>>>(src, dst, n4);
}

extern "C" void kernel_launch(void* const* d_in, const int* in_sizes, int n_in,
                              void* d_out, int out_size) {
    const int*   input_ids = (const int*)  d_in[0];
    const float* tok_emb   = (const float*)d_in[1];
    const float* pos_emb   = (const float*)d_in[2];
    const float* ln1_scale = (const float*)d_in[3];
    const float* ln1_bias  = (const float*)d_in[4];
    const float* qkv_w     = (const float*)d_in[5];
    const float* out_w     = (const float*)d_in[6];
    const float* ln2_scale = (const float*)d_in[7];
    const float* ln2_bias  = (const float*)d_in[8];
    const float* fc1_w     = (const float*)d_in[9];
    const float* fc1_b     = (const float*)d_in[10];
    const float* fc2_w     = (const float*)d_in[11];
    const float* fc2_b     = (const float*)d_in[12];
    const float* lnf_scale = (const float*)d_in[13];
    const float* lnf_bias  = (const float*)d_in[14];
    float* logits = (float*)d_out;

    cudaFuncSetAttribute((const void*)gemm_mma<128>, cudaFuncAttributeMaxDynamicSharedMemorySize, GEMM_SMEM_128);
    cudaFuncSetAttribute((const void*)gemm_mma<64>,  cudaFuncAttributeMaxDynamicSharedMemorySize, GEMM_SMEM_64);
    cudaFuncSetAttribute((const void*)attn_flash,    cudaFuncAttributeMaxDynamicSharedMemorySize, ATT_SMEM);

    float *x, *qkv;
    __half *hh, *hl, *ath, *atl, *fh, *fl;
    __half *qw, *ow, *f1, *f2, *te;
    cudaGetSymbolAddress((void**)&x,   g_x);
    cudaGetSymbolAddress((void**)&qkv, g_qkv);
    cudaGetSymbolAddress((void**)&hh,  g_hh);  cudaGetSymbolAddress((void**)&hl,  g_hl);
    cudaGetSymbolAddress((void**)&ath, g_ath); cudaGetSymbolAddress((void**)&atl, g_atl);
    cudaGetSymbolAddress((void**)&fh,  g_fh);  cudaGetSymbolAddress((void**)&fl,  g_fl);
    cudaGetSymbolAddress((void**)&qw,  g_qw);  cudaGetSymbolAddress((void**)&ow,  g_ow);
    cudaGetSymbolAddress((void**)&f1,  g_f1);  cudaGetSymbolAddress((void**)&f2,  g_f2);
    cudaGetSymbolAddress((void**)&te,  g_te);

    // weight conversions (per replay; single fp16 now)
    run_conv(qkv_w, qw, (long)Ll * 3 * Ee * Ee);
    run_conv(out_w, ow, (long)Ll * Ee * Ee);
    run_conv(fc1_w, f1, (long)Ll * FFf * Ee);
    run_conv(fc2_w, f2, (long)Ll * Ee * FFf);
    run_conv(tok_emb, te, (long)Vv * Ee);

    embed_kernel<<<(BT * Ee + 255) / 256, 256>>>(input_ids, tok_emb, pos_emb, x);

    for (int l = 0; l < Ll; l++) {
        // attention block (pre-norm)
        ln_split_kernel<<<BT, 256>>>(x, ln1_scale + l * Ee, ln1_bias + l * Ee, hh, hl);
        run_gemm(hh, hl, qw + (size_t)l * 3 * Ee * Ee,
                 nullptr, nullptr, qkv, nullptr, nullptr, 3 * Ee, Ee, 0, false);
        attn_flash<<<dim3(Tt/64, NHh, Bb), 256, ATT_SMEM>>>(qkv, ath, atl);
        run_gemm(ath, atl, ow + (size_t)l * Ee * Ee,
                 nullptr, x, x, nullptr, nullptr, Ee, Ee, FLAG_RES, true);
        // FFN block (pre-norm)
        ln_split_kernel<<<BT, 256>>>(x, ln2_scale + l * Ee, ln2_bias + l * Ee, hh, hl);
        run_gemm(hh, hl, f1 + (size_t)l * FFf * Ee,
                 fc1_b + (size_t)l * FFf, nullptr, nullptr, fh, fl,
                 FFf, Ee, FLAG_BIAS | FLAG_GELU | FLAG_SPLITOUT, false);
        run_gemm(fh, fl, f2 + (size_t)l * Ee * FFf,
                 fc2_b + (size_t)l * Ee, x, x, nullptr, nullptr,
                 Ee, FFf, FLAG_BIAS | FLAG_RES, true);
    }

    // final layernorm + tied LM head
    ln_split_kernel<<<BT, 256>>>(x, lnf_scale, lnf_bias, hh, hl);
    run_gemm(hh, hl, te, nullptr, nullptr, logits, nullptr, nullptr,
             Vv, Ee, 0, false);
}

// round 10
// speedup vs baseline: 2.8574x; 1.0672x over previous
#include <cuda_runtime.h>
#include <cuda_bf16.h>
#include <cuda_fp16.h>
#include <cstdint>
#include <math.h>

// ---------------- problem constants ----------------
#define Vv 50257
#define Ee 768
#define NHh 12
#define HDd 64
#define Ll 4
#define Tt 1024
#define Bb 2
#define FFf 3072
#define BT (Bb*Tt)            // 2048 rows

// ---------------- scratch (static, no allocs) ----------------
__device__ float g_x  [BT * Ee];                 // residual stream (fp32)
__device__ float g_qkv[BT * 3*Ee];               // qkv projection (fp32)
__device__ __half g_hh[BT*Ee],  g_hl[BT*Ee];     // LN output hi/lo fp16
__device__ __half g_ath[BT*Ee], g_atl[BT*Ee];    // attn output hi/lo fp16
__device__ __half g_fh[BT*FFf], g_fl[BT*FFf];    // ffn hidden hi/lo fp16
// weights, single fp16
__device__ __half g_qw[Ll*3*Ee*Ee];
__device__ __half g_ow[Ll*Ee*Ee];
__device__ __half g_f1[Ll*FFf*Ee];
__device__ __half g_f2[Ll*Ee*FFf];
__device__ __half g_te[Vv*Ee];

__device__ __forceinline__ void split1f(float v, __half& h, __half& l) {
    h = __float2half(v);
    l = __float2half(v - __half2float(h));
}

__device__ __forceinline__ uint32_t smem_u32(const void* p) {
    uint32_t a;
    asm("{ .reg .u64 t; cvta.to.shared.u64 t, %1; cvt.u32.u64 %0, t; }" : "=r"(a) : "l"(p));
    return a;
}
__device__ __forceinline__ void cp16(uint32_t dst, const void* src) {
    asm volatile("cp.async.cg.shared.global [%0], [%1], 16;" :: "r"(dst), "l"(src));
}
#define CP_COMMIT() asm volatile("cp.async.commit_group;" ::: "memory")
template<int N> __device__ __forceinline__ void cp_wait() {
    asm volatile("cp.async.wait_group %0;" :: "n"(N) : "memory");
}

__device__ __forceinline__ void ldsm_x4(uint32_t a, uint32_t& r0, uint32_t& r1, uint32_t& r2, uint32_t& r3) {
    asm volatile("ldmatrix.sync.aligned.m8n8.x4.shared.b16 {%0,%1,%2,%3}, [%4];"
                 : "=r"(r0), "=r"(r1), "=r"(r2), "=r"(r3) : "r"(a));
}
__device__ __forceinline__ void mma16816f(float* d, const uint32_t* a, const uint32_t* b) {
    asm volatile("mma.sync.aligned.m16n8k16.row.col.f32.f16.f16.f32 "
                 "{%0,%1,%2,%3}, {%4,%5,%6,%7}, {%8,%9}, {%0,%1,%2,%3};"
                 : "+f"(d[0]), "+f"(d[1]), "+f"(d[2]), "+f"(d[3])
                 : "r"(a[0]), "r"(a[1]), "r"(a[2]), "r"(a[3]), "r"(b[0]), "r"(b[1]));
}

// ---------------- fp32 -> fp16 convert (weights) ----------------
__global__ void conv_f16_kernel(const float* __restrict__ src, __half* __restrict__ dst, int n4) {
    int i = blockIdx.x * blockDim.x + threadIdx.x;
    if (i >= n4) return;
    float4 v = ((const float4*)src)[i];
    __half2 a, b;
    a.x = __float2half(v.x); a.y = __float2half(v.y);
    b.x = __float2half(v.z); b.y = __float2half(v.w);
    ((__half2*)dst)[2*i] = a; ((__half2*)dst)[2*i+1] = b;
}

// ---------------- embedding ----------------
__global__ void embed_kernel(const int* __restrict__ ids, const float* __restrict__ tok,
                             const float* __restrict__ pos, float* __restrict__ out) {
    int i = blockIdx.x * blockDim.x + threadIdx.x;
    if (i >= BT * Ee) return;
    int e = i % Ee, row = i / Ee, t = row % Tt;
    out[i] = tok[(size_t)ids[row] * Ee + e] + pos[t * Ee + e];
}

// ---------------- layernorm -> split fp16 hi/lo ----------------
__global__ void ln_split_kernel(const float* __restrict__ x,
                                const float* __restrict__ scale, const float* __restrict__ bias,
                                __half* __restrict__ oh, __half* __restrict__ ol) {
    __shared__ float s1[256], s2[256];
    int row = blockIdx.x, tid = threadIdx.x;
    const float* xr = x + (size_t)row * Ee;
    float sum = 0.f, sq = 0.f;
    for (int c = tid; c < Ee; c += 256) { float v = xr[c]; sum += v; sq += v * v; }
    s1[tid] = sum; s2[tid] = sq; __syncthreads();
    for (int s = 128; s > 0; s >>= 1) {
        if (tid < s) { s1[tid] += s1[tid+s]; s2[tid] += s2[tid+s]; }
        __syncthreads();
    }
    float mean = s1[0] * (1.0f / Ee);
    float var  = s2[0] * (1.0f / Ee) - mean * mean;
    float rstd = rsqrtf(var + 1e-5f);
    for (int c = tid; c < Ee; c += 256) {
        float v = (xr[c] - mean) * rstd * scale[c] + bias[c];
        __half h, l; split1f(v, h, l);
        oh[(size_t)row * Ee + c] = h; ol[(size_t)row * Ee + c] = l;
    }
}

// ---------------- HMMA GEMM: C = epi(A @ W^T) ----------------
// NPROD=2: A hi/lo fp16 (2 mmas); NPROD=1: single fp16 A (1 mma, for LM head)
#define FLAG_BIAS 1
#define FLAG_GELU 2
#define FLAG_RES  4
#define FLAG_SPLITOUT 8

#define W_TILE_B 10240   // 128 rows x 64B padded to 80B
#define NSTAGE 3

template<int BM, int NPROD>
__global__ __launch_bounds__(256, 1)
void gemm_mma(const __half* __restrict__ Ah, const __half* __restrict__ Al,
              const __half* __restrict__ W,
              const float* __restrict__ bias, const float* __restrict__ res,
              float* __restrict__ C, __half* __restrict__ Chi, __half* __restrict__ Clo,
              int N, int K, int flags) {
    constexpr int A_TILE = BM * 80;
    constexpr int W_OFF  = NPROD * A_TILE;
    constexpr int STAGE_B = W_OFF + W_TILE_B;
    constexpr int AC = BM * 4;               // A 16B chunks per tile
    constexpr int WNG = (BM == 128) ? 4 : 8; // warp cols
    constexpr int NJ  = (BM == 128) ? 4 : 2; // 8-col mma tiles per warp
    constexpr int NP  = (BM == 128) ? 2 : 1; // B ldsm pair iters
    constexpr int WNW = 128 / WNG;           // warp n width
    constexpr int NIT = (NPROD * AC + 512) / 256;

    extern __shared__ char smem[];
    const uint32_t sb = smem_u32(smem);
    const int tid  = threadIdx.x;
    const int lane = tid & 31;
    const int wid  = tid >> 5;
    const int wm   = wid / WNG;
    const int wn   = wid % WNG;
    const int bm   = blockIdx.x * BM;
    const int bn   = blockIdx.y * 128;

    float acc[4][NJ][4];
    #pragma unroll
    for (int i = 0; i < 4; i++)
        #pragma unroll
        for (int j = 0; j < NJ; j++)
            #pragma unroll
            for (int r = 0; r < 4; r++) acc[i][j][r] = 0.f;

    const int nc = K >> 5;   // BK = 32

    auto load_stage = [&](int c, int stage) {
        const int k0 = c << 5;
        const uint32_t sdst = sb + stage * STAGE_B;
        #pragma unroll
        for (int it = 0; it < NIT; it++) {
            int gi = it * 256 + tid;
            uint32_t dst; const __half* src;
            if (gi < AC) {
                int row = gi >> 2, chunk = gi & 3;
                dst = sdst + row * 80 + chunk * 16;
                src = Ah + (size_t)(bm + row) * K + k0 + chunk * 8;
            } else if (NPROD == 2 && gi < 2 * AC) {
                int li = gi - AC;
                int row = li >> 2, chunk = li & 3;
                dst = sdst + A_TILE + row * 80 + chunk * 16;
                src = Al + (size_t)(bm + row) * K + k0 + chunk * 8;
            } else {
                int li = gi - NPROD * AC;
                int row = li >> 2, chunk = li & 3;
                int gn = bn + row; if (gn > N - 1) gn = N - 1;
                dst = sdst + W_OFF + row * 80 + chunk * 16;
                src = W + (size_t)gn * K + k0 + chunk * 8;
            }
            cp16(dst, src);
        }
    };

    #pragma unroll
    for (int s = 0; s < NSTAGE - 1; s++) {
        if (s < nc) load_stage(s, s);
        CP_COMMIT();
    }

    uint32_t fa_h[2][4][4], fa_l[2][4][4], fb[2][NJ][2];

    auto load_frags = [&](uint32_t st, int ks, int slot) {
        #pragma unroll
        for (int p = 0; p < NP; p++) {
            int nrow = wn * WNW + p * 16 + (lane & 7) + 8 * (lane >> 4);
            uint32_t koff = ks * 32 + ((lane >> 3) & 1) * 16;
            uint32_t r0,r1,r2,r3;
            ldsm_x4(st + W_OFF + nrow * 80 + koff, r0, r1, r2, r3);
            fb[slot][2*p][0]=r0; fb[slot][2*p][1]=r1; fb[slot][2*p+1][0]=r2; fb[slot][2*p+1][1]=r3;
        }
        #pragma unroll
        for (int i = 0; i < 4; i++) {
            int mrow = wm * 64 + i * 16 + (lane & 7) + 8 * ((lane >> 3) & 1);
            uint32_t koff = ks * 32 + (lane >> 4) * 16;
            ldsm_x4(st + mrow * 80 + koff,
                    fa_h[slot][i][0], fa_h[slot][i][1], fa_h[slot][i][2], fa_h[slot][i][3]);
            if (NPROD == 2)
                ldsm_x4(st + A_TILE + mrow * 80 + koff,
                        fa_l[slot][i][0], fa_l[slot][i][1], fa_l[slot][i][2], fa_l[slot][i][3]);
        }
    };

    for (int c = 0; c < nc; c++) {
        cp_wait<NSTAGE - 2>();
        __syncthreads();

        if (c + NSTAGE - 1 < nc) load_stage(c + NSTAGE - 1, (c + NSTAGE - 1) % NSTAGE);
        CP_COMMIT();

        const uint32_t st = sb + (c % NSTAGE) * STAGE_B;
        load_frags(st, 0, 0);
        load_frags(st, 1, 1);

        #pragma unroll
        for (int ks = 0; ks < 2; ks++) {
            #pragma unroll
            for (int i = 0; i < 4; i++)
                #pragma unroll
                for (int j = 0; j < NJ; j++) {
                    mma16816f(acc[i][j], fa_h[ks][i], fb[ks][j]);
                    if (NPROD == 2)
                        mma16816f(acc[i][j], fa_l[ks][i], fb[ks][j]);
                }
        }
    }

    // ---- epilogue: scalar stores (adjacent lanes contiguous; safe for odd N) ----
    #pragma unroll
    for (int i = 0; i < 4; i++) {
        int row0 = bm + wm * 64 + i * 16 + (lane >> 2);
        #pragma unroll
        for (int j = 0; j < NJ; j++) {
            int col = bn + wn * WNW + j * 8 + (lane & 3) * 2;
            float bv0 = 0.f, bv1 = 0.f;
            if (flags & FLAG_BIAS) {
                if (col < N)     bv0 = bias[col];
                if (col + 1 < N) bv1 = bias[col + 1];
            }
            #pragma unroll
            for (int half = 0; half < 2; half++) {
                int row = row0 + half * 8;
                float v0 = acc[i][j][2*half]     + bv0;
                float v1 = acc[i][j][2*half + 1] + bv1;
                if (flags & FLAG_GELU) {
                    v0 = 0.5f * v0 * (1.0f + erff(v0 * 0.7071067811865476f));
                    v1 = 0.5f * v1 * (1.0f + erff(v1 * 0.7071067811865476f));
                }
                size_t ci = (size_t)row * N + col;
                if (flags & FLAG_RES) {
                    if (col < N)     v0 += res[ci];
                    if (col + 1 < N) v1 += res[ci + 1];
                }
                if (flags & FLAG_SPLITOUT) {
                    __half h0,l0,h1,l1;
                    split1f(v0,h0,l0); split1f(v1,h1,l1);
                    if (col < N)     { Chi[ci]   = h0; Clo[ci]   = l0; }
                    if (col + 1 < N) { Chi[ci+1] = h1; Clo[ci+1] = l1; }
                } else {
                    if (col < N)     C[ci]   = v0;
                    if (col + 1 < N) C[ci+1] = v1;
                }
            }
        }
    }
}

// ---------------- flash attention: 64 queries per block ----------------
#define ATT_SMEM (4 * 64 * 68 * 4)
__global__ __launch_bounds__(256)
void attn_flash(const float* __restrict__ qkv,
                __half* __restrict__ oh, __half* __restrict__ ol) {
    extern __shared__ float sm[];
    float* Qs = sm;
    float* Ks = sm + 64 * 68;
    float* Vs = sm + 2 * 64 * 68;
    float* Ps = sm + 3 * 64 * 68;

    const int qt = blockIdx.x, h = blockIdx.y, b = blockIdx.z;
    const int tid = threadIdx.x;
    const int q   = tid >> 2;
    const int sg  = tid & 3;
    const int q_glob = qt * 64 + q;

    for (int i = tid; i < 64 * 16; i += 256) {
        int r = i >> 4, c4 = (i & 15);
        float4 v = *(const float4*)&qkv[((size_t)(b*Tt + qt*64 + r))*(3*Ee) + h*HDd + c4*4];
        *(float4*)&Qs[r * 68 + c4 * 4] = v;
    }

    float m_run = -1e30f, l_run = 0.f;
    float out[16];
    #pragma unroll
    for (int i = 0; i < 16; i++) out[i] = 0.f;
    __syncthreads();

    for (int kt = 0; kt <= qt; kt++) {
        for (int i = tid; i < 64 * 16; i += 256) {
            int r = i >> 4, c4 = (i & 15);
            size_t base = ((size_t)(b*Tt + kt*64 + r)) * (3*Ee) + h*HDd;
            float4 kv = *(const float4*)&qkv[base + Ee   + c4*4];
            float4 vv = *(const float4*)&qkv[base + 2*Ee + c4*4];
            *(float4*)&Ks[r * 68 + (c4 ^ ((r >> 4) & 3)) * 4] = kv;
            *(float4*)&Vs[r * 68 + c4 * 4] = vv;
        }
        __syncthreads();

        float s[16];
        #pragma unroll
        for (int kk = 0; kk < 16; kk++) s[kk] = 0.f;
        #pragma unroll
        for (int d4 = 0; d4 < 16; d4++) {
            float4 qv = *(const float4*)&Qs[q * 68 + d4 * 4];
            #pragma unroll
            for (int kk = 0; kk < 16; kk++) {
                int krow = sg * 16 + kk;
                float4 kv = *(const float4*)&Ks[krow * 68 + (d4 ^ sg) * 4];
                s[kk] = fmaf(qv.x, kv.x, fmaf(qv.y, kv.y, fmaf(qv.z, kv.z, fmaf(qv.w, kv.w, s[kk]))));
            }
        }
        const int k0g = kt * 64 + sg * 16;
        float lmax = -1e30f;
        #pragma unroll
        for (int kk = 0; kk < 16; kk++) {
            s[kk] *= 0.125f;
            if (k0g + kk > q_glob) s[kk] = -1e30f;
            lmax = fmaxf(lmax, s[kk]);
        }
        lmax = fmaxf(lmax, __shfl_xor_sync(0xFFFFFFFFu, lmax, 1));
        lmax = fmaxf(lmax, __shfl_xor_sync(0xFFFFFFFFu, lmax, 2));
        float mnew = fmaxf(m_run, lmax);
        float f = __expf(m_run - mnew);
        l_run *= f;
        #pragma unroll
        for (int i = 0; i < 16; i++) out[i] *= f;
        float psum = 0.f;
        #pragma unroll
        for (int kk = 0; kk < 16; kk++) {
            float p = __expf(s[kk] - mnew);
            psum += p;
            Ps[q * 68 + sg * 16 + kk] = p;
        }
        psum += __shfl_xor_sync(0xFFFFFFFFu, psum, 1);
        psum += __shfl_xor_sync(0xFFFFFFFFu, psum, 2);
        l_run += psum;
        m_run = mnew;
        __syncwarp();

        for (int k = 0; k < 64; k++) {
            float p = Ps[q * 68 + k];
            #pragma unroll
            for (int d4i = 0; d4i < 4; d4i++) {
                float4 vv = *(const float4*)&Vs[k * 68 + sg * 16 + d4i * 4];
                out[d4i*4+0] = fmaf(p, vv.x, out[d4i*4+0]);
                out[d4i*4+1] = fmaf(p, vv.y, out[d4i*4+1]);
                out[d4i*4+2] = fmaf(p, vv.z, out[d4i*4+2]);
                out[d4i*4+3] = fmaf(p, vv.w, out[d4i*4+3]);
            }
        }
        __syncthreads();
    }

    float inv = 1.0f / l_run;
    size_t obase = ((size_t)(b*Tt + q_glob)) * Ee + h * HDd + sg * 16;
    #pragma unroll
    for (int i = 0; i < 16; i++) {
        float o = out[i] * inv;
        __half hh, ll; split1f(o, hh, ll);
        oh[obase + i] = hh; ol[obase + i] = ll;
    }
}

// ---------------- launcher ----------------
#define GEMM_SMEM_128_2 (NSTAGE * (2*128*80 + W_TILE_B))   // 92160
#define GEMM_SMEM_64_2  (NSTAGE * (2*64*80  + W_TILE_B))   // 61440
#define GEMM_SMEM_128_1 (NSTAGE * (128*80   + W_TILE_B))   // 61440

static void run_gemm(const __half* Ah, const __half* Al, const __half* W,
                     const float* bias, const float* res,
                     float* C, __half* Chi, __half* Clo,
                     int N, int K, int flags, bool narrow) {
    if (narrow) {
        dim3 g(BT / 64, (N + 127) / 128);
        gemm_mma<64,2><<<g, 256, GEMM_SMEM_64_2>>>(Ah, Al, W, bias, res, C, Chi, Clo, N, K, flags);
    } else {
        dim3 g(BT / 128, (N + 127) / 128);
        gemm_mma<128,2><<<g, 256, GEMM_SMEM_128_2>>>(Ah, Al, W, bias, res, C, Chi, Clo, N, K, flags);
    }
}

static void run_conv(const float* src, __half* dst, long n) {
    int n4 = (int)(n / 4);
    conv_f16_kernel<<<(n4 + 255) / 256, 256>>>(src, dst, n4);
}

extern "C" void kernel_launch(void* const* d_in, const int* in_sizes, int n_in,
                              void* d_out, int out_size) {
    const int*   input_ids = (const int*)  d_in[0];
    const float* tok_emb   = (const float*)d_in[1];
    const float* pos_emb   = (const float*)d_in[2];
    const float* ln1_scale = (const float*)d_in[3];
    const float* ln1_bias  = (const float*)d_in[4];
    const float* qkv_w     = (const float*)d_in[5];
    const float* out_w     = (const float*)d_in[6];
    const float* ln2_scale = (const float*)d_in[7];
    const float* ln2_bias  = (const float*)d_in[8];
    const float* fc1_w     = (const float*)d_in[9];
    const float* fc1_b     = (const float*)d_in[10];
    const float* fc2_w     = (const float*)d_in[11];
    const float* fc2_b     = (const float*)d_in[12];
    const float* lnf_scale = (const float*)d_in[13];
    const float* lnf_bias  = (const float*)d_in[14];
    float* logits = (float*)d_out;

    cudaFuncSetAttribute((const void*)gemm_mma<128,2>, cudaFuncAttributeMaxDynamicSharedMemorySize, GEMM_SMEM_128_2);
    cudaFuncSetAttribute((const void*)gemm_mma<64,2>,  cudaFuncAttributeMaxDynamicSharedMemorySize, GEMM_SMEM_64_2);
    cudaFuncSetAttribute((const void*)gemm_mma<128,1>, cudaFuncAttributeMaxDynamicSharedMemorySize, GEMM_SMEM_128_1);
    cudaFuncSetAttribute((const void*)attn_flash,      cudaFuncAttributeMaxDynamicSharedMemorySize, ATT_SMEM);

    float *x, *qkv;
    __half *hh, *hl, *ath, *atl, *fh, *fl;
    __half *qw, *ow, *f1, *f2, *te;
    cudaGetSymbolAddress((void**)&x,   g_x);
    cudaGetSymbolAddress((void**)&qkv, g_qkv);
    cudaGetSymbolAddress((void**)&hh,  g_hh);  cudaGetSymbolAddress((void**)&hl,  g_hl);
    cudaGetSymbolAddress((void**)&ath, g_ath); cudaGetSymbolAddress((void**)&atl, g_atl);
    cudaGetSymbolAddress((void**)&fh,  g_fh);  cudaGetSymbolAddress((void**)&fl,  g_fl);
    cudaGetSymbolAddress((void**)&qw,  g_qw);  cudaGetSymbolAddress((void**)&ow,  g_ow);
    cudaGetSymbolAddress((void**)&f1,  g_f1);  cudaGetSymbolAddress((void**)&f2,  g_f2);
    cudaGetSymbolAddress((void**)&te,  g_te);

    // weight conversions (per replay; single fp16)
    run_conv(qkv_w, qw, (long)Ll * 3 * Ee * Ee);
    run_conv(out_w, ow, (long)Ll * Ee * Ee);
    run_conv(fc1_w, f1, (long)Ll * FFf * Ee);
    run_conv(fc2_w, f2, (long)Ll * Ee * FFf);
    run_conv(tok_emb, te, (long)Vv * Ee);

    embed_kernel<<<(BT * Ee + 255) / 256, 256>>>(input_ids, tok_emb, pos_emb, x);

    for (int l = 0; l < Ll; l++) {
        // attention block (pre-norm)
        ln_split_kernel<<<BT, 256>>>(x, ln1_scale + l * Ee, ln1_bias + l * Ee, hh, hl);
        run_gemm(hh, hl, qw + (size_t)l * 3 * Ee * Ee,
                 nullptr, nullptr, qkv, nullptr, nullptr, 3 * Ee, Ee, 0, false);
        attn_flash<<<dim3(Tt/64, NHh, Bb), 256, ATT_SMEM>>>(qkv, ath, atl);
        run_gemm(ath, atl, ow + (size_t)l * Ee * Ee,
                 nullptr, x, x, nullptr, nullptr, Ee, Ee, FLAG_RES, true);
        // FFN block (pre-norm)
        ln_split_kernel<<<BT, 256>>>(x, ln2_scale + l * Ee, ln2_bias + l * Ee, hh, hl);
        run_gemm(hh, hl, f1 + (size_t)l * FFf * Ee,
                 fc1_b + (size_t)l * FFf, nullptr, nullptr, fh, fl,
                 FFf, Ee, FLAG_BIAS | FLAG_GELU | FLAG_SPLITOUT, false);
        run_gemm(fh, fl, f2 + (size_t)l * Ee * FFf,
                 fc2_b + (size_t)l * Ee, x, x, nullptr, nullptr,
                 Ee, FFf, FLAG_BIAS | FLAG_RES, true);
    }

    // final layernorm + tied LM head (single-product fp16: W-error dominates anyway)
    ln_split_kernel<<<BT, 256>>>(x, lnf_scale, lnf_bias, hh, hl);
    {
        dim3 g(BT / 128, (Vv + 127) / 128);
        gemm_mma<128,1><<<g, 256, GEMM_SMEM_128_1>>>(hh, nullptr, te, nullptr, nullptr,
                                                     logits, nullptr, nullptr, Vv, Ee, 0);
    }
}

// round 11
// speedup vs baseline: 3.2612x; 1.1413x over previous
#include <cuda_runtime.h>
#include <cuda_bf16.h>
#include <cuda_fp16.h>
#include <cstdint>
#include <math.h>

// ---------------- problem constants ----------------
#define Vv 50257
#define Ee 768
#define NHh 12
#define HDd 64
#define Ll 4
#define Tt 1024
#define Bb 2
#define FFf 3072
#define BT (Bb*Tt)            // 2048 rows

// ---------------- scratch (static, no allocs) ----------------
__device__ float g_x  [BT * Ee];                 // residual stream (fp32)
__device__ float g_qkv[BT * 3*Ee];               // qkv projection (fp32)
__device__ __half g_h [BT*Ee];                   // LN output fp16
__device__ __half g_at[BT*Ee];                   // attn output fp16
__device__ __half g_f [BT*FFf];                  // ffn hidden fp16
// weights, single fp16
__device__ __half g_qw[Ll*3*Ee*Ee];
__device__ __half g_ow[Ll*Ee*Ee];
__device__ __half g_f1[Ll*FFf*Ee];
__device__ __half g_f2[Ll*Ee*FFf];
__device__ __half g_te[Vv*Ee];

__device__ __forceinline__ uint32_t smem_u32(const void* p) {
    uint32_t a;
    asm("{ .reg .u64 t; cvta.to.shared.u64 t, %1; cvt.u32.u64 %0, t; }" : "=r"(a) : "l"(p));
    return a;
}
__device__ __forceinline__ void cp16(uint32_t dst, const void* src) {
    asm volatile("cp.async.cg.shared.global [%0], [%1], 16;" :: "r"(dst), "l"(src));
}
#define CP_COMMIT() asm volatile("cp.async.commit_group;" ::: "memory")
template<int N> __device__ __forceinline__ void cp_wait() {
    asm volatile("cp.async.wait_group %0;" :: "n"(N) : "memory");
}

__device__ __forceinline__ void ldsm_x4(uint32_t a, uint32_t& r0, uint32_t& r1, uint32_t& r2, uint32_t& r3) {
    asm volatile("ldmatrix.sync.aligned.m8n8.x4.shared.b16 {%0,%1,%2,%3}, [%4];"
                 : "=r"(r0), "=r"(r1), "=r"(r2), "=r"(r3) : "r"(a));
}
__device__ __forceinline__ void mma16816f(float* d, const uint32_t* a, const uint32_t* b) {
    asm volatile("mma.sync.aligned.m16n8k16.row.col.f32.f16.f16.f32 "
                 "{%0,%1,%2,%3}, {%4,%5,%6,%7}, {%8,%9}, {%0,%1,%2,%3};"
                 : "+f"(d[0]), "+f"(d[1]), "+f"(d[2]), "+f"(d[3])
                 : "r"(a[0]), "r"(a[1]), "r"(a[2]), "r"(a[3]), "r"(b[0]), "r"(b[1]));
}

// ---------------- merged fp32 -> fp16 weight conversion (one launch) ----------------
#define C_QW (Ll*3*Ee*Ee/4)
#define C_OW (Ll*Ee*Ee/4)
#define C_F1 (Ll*FFf*Ee/4)
#define C_F2 (Ll*Ee*FFf/4)
#define C_TE (Vv*Ee/4)
#define C_TOT (C_QW + C_OW + C_F1 + C_F2 + C_TE)

__global__ void conv_all_kernel(const float* __restrict__ qkv_w, const float* __restrict__ out_w,
                                const float* __restrict__ fc1_w, const float* __restrict__ fc2_w,
                                const float* __restrict__ tok_emb,
                                __half* __restrict__ qw, __half* __restrict__ ow,
                                __half* __restrict__ f1, __half* __restrict__ f2,
                                __half* __restrict__ te) {
    int i = blockIdx.x * blockDim.x + threadIdx.x;
    if (i >= C_TOT) return;
    const float* src; __half* dst; int off = i;
    if (off < C_QW)                        { src = qkv_w;  dst = qw; }
    else if ((off -= C_QW) < C_OW)         { src = out_w;  dst = ow; }
    else if ((off -= C_OW) < C_F1)         { src = fc1_w;  dst = f1; }
    else if ((off -= C_F1) < C_F2)         { src = fc2_w;  dst = f2; }
    else      { off -= C_F2;                 src = tok_emb; dst = te; }
    float4 v = ((const float4*)src)[off];
    __half2 a, b;
    a.x = __float2half(v.x); a.y = __float2half(v.y);
    b.x = __float2half(v.z); b.y = __float2half(v.w);
    ((__half2*)dst)[2*off]   = a;
    ((__half2*)dst)[2*off+1] = b;
}

// ---------------- embedding ----------------
__global__ void embed_kernel(const int* __restrict__ ids, const float* __restrict__ tok,
                             const float* __restrict__ pos, float* __restrict__ out) {
    int i = blockIdx.x * blockDim.x + threadIdx.x;
    if (i >= BT * Ee) return;
    int e = i % Ee, row = i / Ee, t = row % Tt;
    out[i] = tok[(size_t)ids[row] * Ee + e] + pos[t * Ee + e];
}

// ---------------- layernorm -> fp16 ----------------
__global__ void ln_kernel(const float* __restrict__ x,
                          const float* __restrict__ scale, const float* __restrict__ bias,
                          __half* __restrict__ o) {
    __shared__ float s1[256], s2[256];
    int row = blockIdx.x, tid = threadIdx.x;
    const float* xr = x + (size_t)row * Ee;
    float sum = 0.f, sq = 0.f;
    for (int c = tid; c < Ee; c += 256) { float v = xr[c]; sum += v; sq += v * v; }
    s1[tid] = sum; s2[tid] = sq; __syncthreads();
    for (int s = 128; s > 0; s >>= 1) {
        if (tid < s) { s1[tid] += s1[tid+s]; s2[tid] += s2[tid+s]; }
        __syncthreads();
    }
    float mean = s1[0] * (1.0f / Ee);
    float var  = s2[0] * (1.0f / Ee) - mean * mean;
    float rstd = rsqrtf(var + 1e-5f);
    for (int c = tid; c < Ee; c += 256) {
        float v = (xr[c] - mean) * rstd * scale[c] + bias[c];
        o[(size_t)row * Ee + c] = __float2half(v);
    }
}

// ---------------- HMMA GEMM: C = epi(A @ W^T), single fp16 product ----------------
#define FLAG_BIAS 1
#define FLAG_GELU 2
#define FLAG_RES  4
#define FLAG_F16OUT 8

#define W_TILE_B 10240   // 128 rows x 64B padded to 80B
#define NSTAGE 3

template<int BM, int MINB>
__global__ __launch_bounds__(256, MINB)
void gemm_mma(const __half* __restrict__ A, const __half* __restrict__ W,
              const float* __restrict__ bias, const float* __restrict__ res,
              float* __restrict__ C, __half* __restrict__ Cf,
              int N, int K, int flags) {
    constexpr int A_TILE = BM * 80;
    constexpr int STAGE_B = A_TILE + W_TILE_B;
    constexpr int AC = BM * 4;               // A 16B chunks per tile
    constexpr int WNG = (BM == 128) ? 4 : 8; // warp cols
    constexpr int NJ  = (BM == 128) ? 4 : 2; // 8-col mma tiles per warp
    constexpr int NP  = (BM == 128) ? 2 : 1; // B ldsm iters
    constexpr int WNW = 128 / WNG;           // warp n width
    constexpr int NIT = (AC + 512) / 256;

    extern __shared__ char smem[];
    const uint32_t sb = smem_u32(smem);
    const int tid  = threadIdx.x;
    const int lane = tid & 31;
    const int wid  = tid >> 5;
    const int wm   = wid / WNG;
    const int wn   = wid % WNG;
    const int bm   = blockIdx.x * BM;
    const int bn   = blockIdx.y * 128;

    float acc[4][NJ][4];
    #pragma unroll
    for (int i = 0; i < 4; i++)
        #pragma unroll
        for (int j = 0; j < NJ; j++)
            #pragma unroll
            for (int r = 0; r < 4; r++) acc[i][j][r] = 0.f;

    const int nc = K >> 5;   // BK = 32

    auto load_stage = [&](int c, int stage) {
        const int k0 = c << 5;
        const uint32_t sdst = sb + stage * STAGE_B;
        #pragma unroll
        for (int it = 0; it < NIT; it++) {
            int gi = it * 256 + tid;
            uint32_t dst; const __half* src;
            if (gi < AC) {
                int row = gi >> 2, chunk = gi & 3;
                dst = sdst + row * 80 + chunk * 16;
                src = A + (size_t)(bm + row) * K + k0 + chunk * 8;
            } else {
                int li = gi - AC;
                int row = li >> 2, chunk = li & 3;
                int gn = bn + row; if (gn > N - 1) gn = N - 1;
                dst = sdst + A_TILE + row * 80 + chunk * 16;
                src = W + (size_t)gn * K + k0 + chunk * 8;
            }
            cp16(dst, src);
        }
    };

    #pragma unroll
    for (int s = 0; s < NSTAGE - 1; s++) {
        if (s < nc) load_stage(s, s);
        CP_COMMIT();
    }

    uint32_t fa[2][4][4], fb[2][NJ][2];

    auto load_frags = [&](uint32_t st, int ks, int slot) {
        #pragma unroll
        for (int p = 0; p < NP; p++) {
            int nrow = wn * WNW + p * 16 + (lane & 7) + 8 * (lane >> 4);
            uint32_t koff = ks * 32 + ((lane >> 3) & 1) * 16;
            uint32_t r0,r1,r2,r3;
            ldsm_x4(st + A_TILE + nrow * 80 + koff, r0, r1, r2, r3);
            fb[slot][2*p][0]=r0; fb[slot][2*p][1]=r1; fb[slot][2*p+1][0]=r2; fb[slot][2*p+1][1]=r3;
        }
        #pragma unroll
        for (int i = 0; i < 4; i++) {
            int mrow = wm * 64 + i * 16 + (lane & 7) + 8 * ((lane >> 3) & 1);
            uint32_t koff = ks * 32 + (lane >> 4) * 16;
            ldsm_x4(st + mrow * 80 + koff,
                    fa[slot][i][0], fa[slot][i][1], fa[slot][i][2], fa[slot][i][3]);
        }
    };

    for (int c = 0; c < nc; c++) {
        cp_wait<NSTAGE - 2>();
        __syncthreads();

        if (c + NSTAGE - 1 < nc) load_stage(c + NSTAGE - 1, (c + NSTAGE - 1) % NSTAGE);
        CP_COMMIT();

        const uint32_t st = sb + (c % NSTAGE) * STAGE_B;
        load_frags(st, 0, 0);
        load_frags(st, 1, 1);

        #pragma unroll
        for (int ks = 0; ks < 2; ks++) {
            #pragma unroll
            for (int i = 0; i < 4; i++)
                #pragma unroll
                for (int j = 0; j < NJ; j++)
                    mma16816f(acc[i][j], fa[ks][i], fb[ks][j]);
        }
    }

    // ---- epilogue: scalar stores (adjacent lanes contiguous; safe for odd N) ----
    #pragma unroll
    for (int i = 0; i < 4; i++) {
        int row0 = bm + wm * 64 + i * 16 + (lane >> 2);
        #pragma unroll
        for (int j = 0; j < NJ; j++) {
            int col = bn + wn * WNW + j * 8 + (lane & 3) * 2;
            float bv0 = 0.f, bv1 = 0.f;
            if (flags & FLAG_BIAS) {
                if (col < N)     bv0 = bias[col];
                if (col + 1 < N) bv1 = bias[col + 1];
            }
            #pragma unroll
            for (int half = 0; half < 2; half++) {
                int row = row0 + half * 8;
                float v0 = acc[i][j][2*half]     + bv0;
                float v1 = acc[i][j][2*half + 1] + bv1;
                if (flags & FLAG_GELU) {
                    v0 = 0.5f * v0 * (1.0f + erff(v0 * 0.7071067811865476f));
                    v1 = 0.5f * v1 * (1.0f + erff(v1 * 0.7071067811865476f));
                }
                size_t ci = (size_t)row * N + col;
                if (flags & FLAG_RES) {
                    if (col < N)     v0 += res[ci];
                    if (col + 1 < N) v1 += res[ci + 1];
                }
                if (flags & FLAG_F16OUT) {
                    if (col < N)     Cf[ci]   = __float2half(v0);
                    if (col + 1 < N) Cf[ci+1] = __float2half(v1);
                } else {
                    if (col < N)     C[ci]   = v0;
                    if (col + 1 < N) C[ci+1] = v1;
                }
            }
        }
    }
}

// ---------------- flash attention: 64 queries per block ----------------
#define ATT_SMEM (4 * 64 * 68 * 4)
__global__ __launch_bounds__(256)
void attn_flash(const float* __restrict__ qkv, __half* __restrict__ o) {
    extern __shared__ float sm[];
    float* Qs = sm;
    float* Ks = sm + 64 * 68;
    float* Vs = sm + 2 * 64 * 68;
    float* Ps = sm + 3 * 64 * 68;

    const int qt = blockIdx.x, h = blockIdx.y, b = blockIdx.z;
    const int tid = threadIdx.x;
    const int q   = tid >> 2;
    const int sg  = tid & 3;
    const int q_glob = qt * 64 + q;

    for (int i = tid; i < 64 * 16; i += 256) {
        int r = i >> 4, c4 = (i & 15);
        float4 v = *(const float4*)&qkv[((size_t)(b*Tt + qt*64 + r))*(3*Ee) + h*HDd + c4*4];
        *(float4*)&Qs[r * 68 + c4 * 4] = v;
    }

    float m_run = -1e30f, l_run = 0.f;
    float out[16];
    #pragma unroll
    for (int i = 0; i < 16; i++) out[i] = 0.f;
    __syncthreads();

    for (int kt = 0; kt <= qt; kt++) {
        for (int i = tid; i < 64 * 16; i += 256) {
            int r = i >> 4, c4 = (i & 15);
            size_t base = ((size_t)(b*Tt + kt*64 + r)) * (3*Ee) + h*HDd;
            float4 kv = *(const float4*)&qkv[base + Ee   + c4*4];
            float4 vv = *(const float4*)&qkv[base + 2*Ee + c4*4];
            *(float4*)&Ks[r * 68 + (c4 ^ ((r >> 4) & 3)) * 4] = kv;
            *(float4*)&Vs[r * 68 + c4 * 4] = vv;
        }
        __syncthreads();

        float s[16];
        #pragma unroll
        for (int kk = 0; kk < 16; kk++) s[kk] = 0.f;
        #pragma unroll
        for (int d4 = 0; d4 < 16; d4++) {
            float4 qv = *(const float4*)&Qs[q * 68 + d4 * 4];
            #pragma unroll
            for (int kk = 0; kk < 16; kk++) {
                int krow = sg * 16 + kk;
                float4 kv = *(const float4*)&Ks[krow * 68 + (d4 ^ sg) * 4];
                s[kk] = fmaf(qv.x, kv.x, fmaf(qv.y, kv.y, fmaf(qv.z, kv.z, fmaf(qv.w, kv.w, s[kk]))));
            }
        }
        const int k0g = kt * 64 + sg * 16;
        float lmax = -1e30f;
        #pragma unroll
        for (int kk = 0; kk < 16; kk++) {
            s[kk] *= 0.125f;
            if (k0g + kk > q_glob) s[kk] = -1e30f;
            lmax = fmaxf(lmax, s[kk]);
        }
        lmax = fmaxf(lmax, __shfl_xor_sync(0xFFFFFFFFu, lmax, 1));
        lmax = fmaxf(lmax, __shfl_xor_sync(0xFFFFFFFFu, lmax, 2));
        float mnew = fmaxf(m_run, lmax);
        float f = __expf(m_run - mnew);
        l_run *= f;
        #pragma unroll
        for (int i = 0; i < 16; i++) out[i] *= f;
        float psum = 0.f;
        #pragma unroll
        for (int kk = 0; kk < 16; kk++) {
            float p = __expf(s[kk] - mnew);
            psum += p;
            Ps[q * 68 + sg * 16 + kk] = p;
        }
        psum += __shfl_xor_sync(0xFFFFFFFFu, psum, 1);
        psum += __shfl_xor_sync(0xFFFFFFFFu, psum, 2);
        l_run += psum;
        m_run = mnew;
        __syncwarp();

        for (int k = 0; k < 64; k++) {
            float p = Ps[q * 68 + k];
            #pragma unroll
            for (int d4i = 0; d4i < 4; d4i++) {
                float4 vv = *(const float4*)&Vs[k * 68 + sg * 16 + d4i * 4];
                out[d4i*4+0] = fmaf(p, vv.x, out[d4i*4+0]);
                out[d4i*4+1] = fmaf(p, vv.y, out[d4i*4+1]);
                out[d4i*4+2] = fmaf(p, vv.z, out[d4i*4+2]);
                out[d4i*4+3] = fmaf(p, vv.w, out[d4i*4+3]);
            }
        }
        __syncthreads();
    }

    float inv = 1.0f / l_run;
    size_t obase = ((size_t)(b*Tt + q_glob)) * Ee + h * HDd + sg * 16;
    #pragma unroll
    for (int i = 0; i < 16; i++)
        o[obase + i] = __float2half(out[i] * inv);
}

// ---------------- launcher ----------------
#define GEMM_SMEM_128 (NSTAGE * (128*80 + W_TILE_B))   // 61440
#define GEMM_SMEM_64  (NSTAGE * (64*80  + W_TILE_B))   // 46080

static void run_gemm_wide(const __half* A, const __half* W,
                          const float* bias, const float* res,
                          float* C, __half* Cf, int N, int K, int flags) {
    dim3 g(BT / 128, (N + 127) / 128);
    gemm_mma<128,1><<<g, 256, GEMM_SMEM_128>>>(A, W, bias, res, C, Cf, N, K, flags);
}
static void run_gemm_narrow(const __half* A, const __half* W,
                            const float* bias, const float* res,
                            float* C, __half* Cf, int N, int K, int flags) {
    dim3 g(BT / 64, (N + 127) / 128);
    gemm_mma<64,2><<<g, 256, GEMM_SMEM_64>>>(A, W, bias, res, C, Cf, N, K, flags);
}

extern "C" void kernel_launch(void* const* d_in, const int* in_sizes, int n_in,
                              void* d_out, int out_size) {
    const int*   input_ids = (const int*)  d_in[0];
    const float* tok_emb   = (const float*)d_in[1];
    const float* pos_emb   = (const float*)d_in[2];
    const float* ln1_scale = (const float*)d_in[3];
    const float* ln1_bias  = (const float*)d_in[4];
    const float* qkv_w     = (const float*)d_in[5];
    const float* out_w     = (const float*)d_in[6];
    const float* ln2_scale = (const float*)d_in[7];
    const float* ln2_bias  = (const float*)d_in[8];
    const float* fc1_w     = (const float*)d_in[9];
    const float* fc1_b     = (const float*)d_in[10];
    const float* fc2_w     = (const float*)d_in[11];
    const float* fc2_b     = (const float*)d_in[12];
    const float* lnf_scale = (const float*)d_in[13];
    const float* lnf_bias  = (const float*)d_in[14];
    float* logits = (float*)d_out;

    cudaFuncSetAttribute((const void*)gemm_mma<128,1>, cudaFuncAttributeMaxDynamicSharedMemorySize, GEMM_SMEM_128);
    cudaFuncSetAttribute((const void*)gemm_mma<64,2>,  cudaFuncAttributeMaxDynamicSharedMemorySize, GEMM_SMEM_64);
    cudaFuncSetAttribute((const void*)attn_flash,      cudaFuncAttributeMaxDynamicSharedMemorySize, ATT_SMEM);

    float *x, *qkv;
    __half *h, *at, *f, *qw, *ow, *f1, *f2, *te;
    cudaGetSymbolAddress((void**)&x,   g_x);
    cudaGetSymbolAddress((void**)&qkv, g_qkv);
    cudaGetSymbolAddress((void**)&h,   g_h);
    cudaGetSymbolAddress((void**)&at,  g_at);
    cudaGetSymbolAddress((void**)&f,   g_f);
    cudaGetSymbolAddress((void**)&qw,  g_qw);  cudaGetSymbolAddress((void**)&ow,  g_ow);
    cudaGetSymbolAddress((void**)&f1,  g_f1);  cudaGetSymbolAddress((void**)&f2,  g_f2);
    cudaGetSymbolAddress((void**)&te,  g_te);

    // single merged weight conversion
    conv_all_kernel<<<(C_TOT + 255) / 256, 256>>>(qkv_w, out_w, fc1_w, fc2_w, tok_emb,
                                                  qw, ow, f1, f2, te);

    embed_kernel<<<(BT * Ee + 255) / 256, 256>>>(input_ids, tok_emb, pos_emb, x);

    for (int l = 0; l < Ll; l++) {
        // attention block (pre-norm)
        ln_kernel<<<BT, 256>>>(x, ln1_scale + l * Ee, ln1_bias + l * Ee, h);
        run_gemm_wide(h, qw + (size_t)l * 3 * Ee * Ee,
                      nullptr, nullptr, qkv, nullptr, 3 * Ee, Ee, 0);
        attn_flash<<<dim3(Tt/64, NHh, Bb), 256, ATT_SMEM>>>(qkv, at);
        run_gemm_narrow(at, ow + (size_t)l * Ee * Ee,
                        nullptr, x, x, nullptr, Ee, Ee, FLAG_RES);
        // FFN block (pre-norm)
        ln_kernel<<<BT, 256>>>(x, ln2_scale + l * Ee, ln2_bias + l * Ee, h);
        run_gemm_wide(h, f1 + (size_t)l * FFf * Ee,
                      fc1_b + (size_t)l * FFf, nullptr, nullptr, f,
                      FFf, Ee, FLAG_BIAS | FLAG_GELU | FLAG_F16OUT);
        run_gemm_narrow(f, f2 + (size_t)l * Ee * FFf,
                        fc2_b + (size_t)l * Ee, x, x, nullptr,
                        Ee, FFf, FLAG_BIAS | FLAG_RES);
    }

    // final layernorm + tied LM head
    ln_kernel<<<BT, 256>>>(x, lnf_scale, lnf_bias, h);
    run_gemm_wide(h, te, nullptr, nullptr, logits, nullptr, Vv, Ee, 0);
}

// round 12
// speedup vs baseline: 3.6566x; 1.1212x over previous
#include <cuda_runtime.h>
#include <cuda_bf16.h>
#include <cuda_fp16.h>
#include <cstdint>
#include <math.h>

// ---------------- problem constants ----------------
#define Vv 50257
#define Ee 768
#define NHh 12
#define HDd 64
#define Ll 4
#define Tt 1024
#define Bb 2
#define FFf 3072
#define BT (Bb*Tt)            // 2048 rows

// ---------------- scratch (static, no allocs) ----------------
__device__ float g_x  [BT * Ee];                 // residual stream (fp32)
__device__ float g_qkv[BT * 3*Ee];               // qkv projection (fp32)
__device__ __half g_h [BT*Ee];                   // LN output fp16
__device__ __half g_at[BT*Ee];                   // attn output fp16
__device__ __half g_f [BT*FFf];                  // ffn hidden fp16
// weights, single fp16
__device__ __half g_qw[Ll*3*Ee*Ee];
__device__ __half g_ow[Ll*Ee*Ee];
__device__ __half g_f1[Ll*FFf*Ee];
__device__ __half g_f2[Ll*Ee*FFf];
__device__ __half g_te[Vv*Ee];

__device__ __forceinline__ uint32_t smem_u32(const void* p) {
    uint32_t a;
    asm("{ .reg .u64 t; cvta.to.shared.u64 t, %1; cvt.u32.u64 %0, t; }" : "=r"(a) : "l"(p));
    return a;
}
__device__ __forceinline__ void cp16(uint32_t dst, const void* src) {
    asm volatile("cp.async.cg.shared.global [%0], [%1], 16;" :: "r"(dst), "l"(src));
}
#define CP_COMMIT() asm volatile("cp.async.commit_group;" ::: "memory")
template<int N> __device__ __forceinline__ void cp_wait() {
    asm volatile("cp.async.wait_group %0;" :: "n"(N) : "memory");
}

__device__ __forceinline__ void ldsm_x4(uint32_t a, uint32_t& r0, uint32_t& r1, uint32_t& r2, uint32_t& r3) {
    asm volatile("ldmatrix.sync.aligned.m8n8.x4.shared.b16 {%0,%1,%2,%3}, [%4];"
                 : "=r"(r0), "=r"(r1), "=r"(r2), "=r"(r3) : "r"(a));
}
__device__ __forceinline__ void mma16816f(float* d, const uint32_t* a, const uint32_t* b) {
    asm volatile("mma.sync.aligned.m16n8k16.row.col.f32.f16.f16.f32 "
                 "{%0,%1,%2,%3}, {%4,%5,%6,%7}, {%8,%9}, {%0,%1,%2,%3};"
                 : "+f"(d[0]), "+f"(d[1]), "+f"(d[2]), "+f"(d[3])
                 : "r"(a[0]), "r"(a[1]), "r"(a[2]), "r"(a[3]), "r"(b[0]), "r"(b[1]));
}

// ---------------- merged fp32 -> fp16 weight conversion (one launch) ----------------
#define C_QW (Ll*3*Ee*Ee/4)
#define C_OW (Ll*Ee*Ee/4)
#define C_F1 (Ll*FFf*Ee/4)
#define C_F2 (Ll*Ee*FFf/4)
#define C_TE (Vv*Ee/4)
#define C_TOT (C_QW + C_OW + C_F1 + C_F2 + C_TE)

__global__ void conv_all_kernel(const float* __restrict__ qkv_w, const float* __restrict__ out_w,
                                const float* __restrict__ fc1_w, const float* __restrict__ fc2_w,
                                const float* __restrict__ tok_emb,
                                __half* __restrict__ qw, __half* __restrict__ ow,
                                __half* __restrict__ f1, __half* __restrict__ f2,
                                __half* __restrict__ te) {
    int i = blockIdx.x * blockDim.x + threadIdx.x;
    if (i >= C_TOT) return;
    const float* src; __half* dst; int off = i;
    if (off < C_QW)                        { src = qkv_w;  dst = qw; }
    else if ((off -= C_QW) < C_OW)         { src = out_w;  dst = ow; }
    else if ((off -= C_OW) < C_F1)         { src = fc1_w;  dst = f1; }
    else if ((off -= C_F1) < C_F2)         { src = fc2_w;  dst = f2; }
    else      { off -= C_F2;                 src = tok_emb; dst = te; }
    float4 v = ((const float4*)src)[off];
    __half2 a, b;
    a.x = __float2half(v.x); a.y = __float2half(v.y);
    b.x = __float2half(v.z); b.y = __float2half(v.w);
    ((__half2*)dst)[2*off]   = a;
    ((__half2*)dst)[2*off+1] = b;
}

// ---------------- embedding ----------------
__global__ void embed_kernel(const int* __restrict__ ids, const float* __restrict__ tok,
                             const float* __restrict__ pos, float* __restrict__ out) {
    int i = blockIdx.x * blockDim.x + threadIdx.x;
    if (i >= BT * Ee) return;
    int e = i % Ee, row = i / Ee, t = row % Tt;
    out[i] = tok[(size_t)ids[row] * Ee + e] + pos[t * Ee + e];
}

// ---------------- layernorm -> fp16 ----------------
__global__ void ln_kernel(const float* __restrict__ x,
                          const float* __restrict__ scale, const float* __restrict__ bias,
                          __half* __restrict__ o) {
    __shared__ float s1[256], s2[256];
    int row = blockIdx.x, tid = threadIdx.x;
    const float* xr = x + (size_t)row * Ee;
    float sum = 0.f, sq = 0.f;
    for (int c = tid; c < Ee; c += 256) { float v = xr[c]; sum += v; sq += v * v; }
    s1[tid] = sum; s2[tid] = sq; __syncthreads();
    for (int s = 128; s > 0; s >>= 1) {
        if (tid < s) { s1[tid] += s1[tid+s]; s2[tid] += s2[tid+s]; }
        __syncthreads();
    }
    float mean = s1[0] * (1.0f / Ee);
    float var  = s2[0] * (1.0f / Ee) - mean * mean;
    float rstd = rsqrtf(var + 1e-5f);
    for (int c = tid; c < Ee; c += 256) {
        float v = (xr[c] - mean) * rstd * scale[c] + bias[c];
        o[(size_t)row * Ee + c] = __float2half(v);
    }
}

// ---------------- HMMA GEMM: C = epi(A @ W^T), single fp16 product ----------------
// 2 CTAs/SM (registers kept <=128 via single fragment slot)
#define FLAG_BIAS 1
#define FLAG_GELU 2
#define FLAG_RES  4
#define FLAG_F16OUT 8

#define W_TILE_B 10240   // 128 rows x 64B padded to 80B
#define NSTAGE 3

template<int BM>
__global__ __launch_bounds__(256, 2)
void gemm_mma(const __half* __restrict__ A, const __half* __restrict__ W,
              const float* __restrict__ bias, const float* __restrict__ res,
              float* __restrict__ C, __half* __restrict__ Cf,
              int N, int K, int flags) {
    constexpr int A_TILE = BM * 80;
    constexpr int STAGE_B = A_TILE + W_TILE_B;
    constexpr int AC = BM * 4;               // A 16B chunks per tile
    constexpr int WNG = (BM == 128) ? 4 : 8; // warp cols
    constexpr int NJ  = (BM == 128) ? 4 : 2; // 8-col mma tiles per warp
    constexpr int NP  = (BM == 128) ? 2 : 1; // B ldsm iters
    constexpr int WNW = 128 / WNG;           // warp n width
    constexpr int NIT = (AC + 512) / 256;

    extern __shared__ char smem[];
    const uint32_t sb = smem_u32(smem);
    const int tid  = threadIdx.x;
    const int lane = tid & 31;
    const int wid  = tid >> 5;
    const int wm   = wid / WNG;
    const int wn   = wid % WNG;
    const int bm   = blockIdx.x * BM;
    const int bn   = blockIdx.y * 128;

    float acc[4][NJ][4];
    #pragma unroll
    for (int i = 0; i < 4; i++)
        #pragma unroll
        for (int j = 0; j < NJ; j++)
            #pragma unroll
            for (int r = 0; r < 4; r++) acc[i][j][r] = 0.f;

    const int nc = K >> 5;   // BK = 32

    auto load_stage = [&](int c, int stage) {
        const int k0 = c << 5;
        const uint32_t sdst = sb + stage * STAGE_B;
        #pragma unroll
        for (int it = 0; it < NIT; it++) {
            int gi = it * 256 + tid;
            uint32_t dst; const __half* src;
            if (gi < AC) {
                int row = gi >> 2, chunk = gi & 3;
                dst = sdst + row * 80 + chunk * 16;
                src = A + (size_t)(bm + row) * K + k0 + chunk * 8;
            } else {
                int li = gi - AC;
                int row = li >> 2, chunk = li & 3;
                int gn = bn + row; if (gn > N - 1) gn = N - 1;
                dst = sdst + A_TILE + row * 80 + chunk * 16;
                src = W + (size_t)gn * K + k0 + chunk * 8;
            }
            cp16(dst, src);
        }
    };

    #pragma unroll
    for (int s = 0; s < NSTAGE - 1; s++) {
        if (s < nc) load_stage(s, s);
        CP_COMMIT();
    }

    for (int c = 0; c < nc; c++) {
        cp_wait<NSTAGE - 2>();
        __syncthreads();

        if (c + NSTAGE - 1 < nc) load_stage(c + NSTAGE - 1, (c + NSTAGE - 1) % NSTAGE);
        CP_COMMIT();

        const uint32_t st = sb + (c % NSTAGE) * STAGE_B;
        #pragma unroll
        for (int ks = 0; ks < 2; ks++) {
            uint32_t fa[4][4], fb[NJ][2];
            #pragma unroll
            for (int p = 0; p < NP; p++) {
                int nrow = wn * WNW + p * 16 + (lane & 7) + 8 * (lane >> 4);
                uint32_t koff = ks * 32 + ((lane >> 3) & 1) * 16;
                uint32_t r0,r1,r2,r3;
                ldsm_x4(st + A_TILE + nrow * 80 + koff, r0, r1, r2, r3);
                fb[2*p][0]=r0; fb[2*p][1]=r1; fb[2*p+1][0]=r2; fb[2*p+1][1]=r3;
            }
            #pragma unroll
            for (int i = 0; i < 4; i++) {
                int mrow = wm * 64 + i * 16 + (lane & 7) + 8 * ((lane >> 3) & 1);
                uint32_t koff = ks * 32 + (lane >> 4) * 16;
                ldsm_x4(st + mrow * 80 + koff, fa[i][0], fa[i][1], fa[i][2], fa[i][3]);
            }
            #pragma unroll
            for (int i = 0; i < 4; i++)
                #pragma unroll
                for (int j = 0; j < NJ; j++)
                    mma16816f(acc[i][j], fa[i], fb[j]);
        }
    }

    // ---- epilogue: scalar stores (adjacent lanes contiguous; safe for odd N) ----
    #pragma unroll
    for (int i = 0; i < 4; i++) {
        int row0 = bm + wm * 64 + i * 16 + (lane >> 2);
        #pragma unroll
        for (int j = 0; j < NJ; j++) {
            int col = bn + wn * WNW + j * 8 + (lane & 3) * 2;
            float bv0 = 0.f, bv1 = 0.f;
            if (flags & FLAG_BIAS) {
                if (col < N)     bv0 = bias[col];
                if (col + 1 < N) bv1 = bias[col + 1];
            }
            #pragma unroll
            for (int half = 0; half < 2; half++) {
                int row = row0 + half * 8;
                float v0 = acc[i][j][2*half]     + bv0;
                float v1 = acc[i][j][2*half + 1] + bv1;
                if (flags & FLAG_GELU) {
                    v0 = 0.5f * v0 * (1.0f + erff(v0 * 0.7071067811865476f));
                    v1 = 0.5f * v1 * (1.0f + erff(v1 * 0.7071067811865476f));
                }
                size_t ci = (size_t)row * N + col;
                if (flags & FLAG_RES) {
                    if (col < N)     v0 += res[ci];
                    if (col + 1 < N) v1 += res[ci + 1];
                }
                if (flags & FLAG_F16OUT) {
                    if (col < N)     Cf[ci]   = __float2half(v0);
                    if (col + 1 < N) Cf[ci+1] = __float2half(v1);
                } else {
                    if (col < N)     C[ci]   = v0;
                    if (col + 1 < N) C[ci+1] = v1;
                }
            }
        }
    }
}

// ---------------- flash attention: 64 queries per block ----------------
#define ATT_SMEM (4 * 64 * 68 * 4)
__global__ __launch_bounds__(256)
void attn_flash(const float* __restrict__ qkv, __half* __restrict__ o) {
    extern __shared__ float sm[];
    float* Qs = sm;
    float* Ks = sm + 64 * 68;
    float* Vs = sm + 2 * 64 * 68;
    float* Ps = sm + 3 * 64 * 68;

    const int qt = blockIdx.x, h = blockIdx.y, b = blockIdx.z;
    const int tid = threadIdx.x;
    const int q   = tid >> 2;
    const int sg  = tid & 3;
    const int q_glob = qt * 64 + q;

    for (int i = tid; i < 64 * 16; i += 256) {
        int r = i >> 4, c4 = (i & 15);
        float4 v = *(const float4*)&qkv[((size_t)(b*Tt + qt*64 + r))*(3*Ee) + h*HDd + c4*4];
        *(float4*)&Qs[r * 68 + c4 * 4] = v;
    }

    float m_run = -1e30f, l_run = 0.f;
    float out[16];
    #pragma unroll
    for (int i = 0; i < 16; i++) out[i] = 0.f;
    __syncthreads();

    for (int kt = 0; kt <= qt; kt++) {
        for (int i = tid; i < 64 * 16; i += 256) {
            int r = i >> 4, c4 = (i & 15);
            size_t base = ((size_t)(b*Tt + kt*64 + r)) * (3*Ee) + h*HDd;
            float4 kv = *(const float4*)&qkv[base + Ee   + c4*4];
            float4 vv = *(const float4*)&qkv[base + 2*Ee + c4*4];
            *(float4*)&Ks[r * 68 + (c4 ^ ((r >> 4) & 3)) * 4] = kv;
            *(float4*)&Vs[r * 68 + c4 * 4] = vv;
        }
        __syncthreads();

        float s[16];
        #pragma unroll
        for (int kk = 0; kk < 16; kk++) s[kk] = 0.f;
        #pragma unroll
        for (int d4 = 0; d4 < 16; d4++) {
            float4 qv = *(const float4*)&Qs[q * 68 + d4 * 4];
            #pragma unroll
            for (int kk = 0; kk < 16; kk++) {
                int krow = sg * 16 + kk;
                float4 kv = *(const float4*)&Ks[krow * 68 + (d4 ^ sg) * 4];
                s[kk] = fmaf(qv.x, kv.x, fmaf(qv.y, kv.y, fmaf(qv.z, kv.z, fmaf(qv.w, kv.w, s[kk]))));
            }
        }
        const int k0g = kt * 64 + sg * 16;
        float lmax = -1e30f;
        #pragma unroll
        for (int kk = 0; kk < 16; kk++) {
            s[kk] *= 0.125f;
            if (k0g + kk > q_glob) s[kk] = -1e30f;
            lmax = fmaxf(lmax, s[kk]);
        }
        lmax = fmaxf(lmax, __shfl_xor_sync(0xFFFFFFFFu, lmax, 1));
        lmax = fmaxf(lmax, __shfl_xor_sync(0xFFFFFFFFu, lmax, 2));
        float mnew = fmaxf(m_run, lmax);
        float f = __expf(m_run - mnew);
        l_run *= f;
        #pragma unroll
        for (int i = 0; i < 16; i++) out[i] *= f;
        float psum = 0.f;
        #pragma unroll
        for (int kk = 0; kk < 16; kk++) {
            float p = __expf(s[kk] - mnew);
            psum += p;
            Ps[q * 68 + sg * 16 + kk] = p;
        }
        psum += __shfl_xor_sync(0xFFFFFFFFu, psum, 1);
        psum += __shfl_xor_sync(0xFFFFFFFFu, psum, 2);
        l_run += psum;
        m_run = mnew;
        __syncwarp();

        for (int k = 0; k < 64; k++) {
            float p = Ps[q * 68 + k];
            #pragma unroll
            for (int d4i = 0; d4i < 4; d4i++) {
                float4 vv = *(const float4*)&Vs[k * 68 + sg * 16 + d4i * 4];
                out[d4i*4+0] = fmaf(p, vv.x, out[d4i*4+0]);
                out[d4i*4+1] = fmaf(p, vv.y, out[d4i*4+1]);
                out[d4i*4+2] = fmaf(p, vv.z, out[d4i*4+2]);
                out[d4i*4+3] = fmaf(p, vv.w, out[d4i*4+3]);
            }
        }
        __syncthreads();
    }

    float inv = 1.0f / l_run;
    size_t obase = ((size_t)(b*Tt + q_glob)) * Ee + h * HDd + sg * 16;
    #pragma unroll
    for (int i = 0; i < 16; i++)
        o[obase + i] = __float2half(out[i] * inv);
}

// ---------------- launcher ----------------
#define GEMM_SMEM_128 (NSTAGE * (128*80 + W_TILE_B))   // 61440
#define GEMM_SMEM_64  (NSTAGE * (64*80  + W_TILE_B))   // 46080

static void run_gemm_wide(const __half* A, const __half* W,
                          const float* bias, const float* res,
                          float* C, __half* Cf, int N, int K, int flags) {
    dim3 g(BT / 128, (N + 127) / 128);
    gemm_mma<128><<<g, 256, GEMM_SMEM_128>>>(A, W, bias, res, C, Cf, N, K, flags);
}
static void run_gemm_narrow(const __half* A, const __half* W,
                            const float* bias, const float* res,
                            float* C, __half* Cf, int N, int K, int flags) {
    dim3 g(BT / 64, (N + 127) / 128);
    gemm_mma<64><<<g, 256, GEMM_SMEM_64>>>(A, W, bias, res, C, Cf, N, K, flags);
}

extern "C" void kernel_launch(void* const* d_in, const int* in_sizes, int n_in,
                              void* d_out, int out_size) {
    const int*   input_ids = (const int*)  d_in[0];
    const float* tok_emb   = (const float*)d_in[1];
    const float* pos_emb   = (const float*)d_in[2];
    const float* ln1_scale = (const float*)d_in[3];
    const float* ln1_bias  = (const float*)d_in[4];
    const float* qkv_w     = (const float*)d_in[5];
    const float* out_w     = (const float*)d_in[6];
    const float* ln2_scale = (const float*)d_in[7];
    const float* ln2_bias  = (const float*)d_in[8];
    const float* fc1_w     = (const float*)d_in[9];
    const float* fc1_b     = (const float*)d_in[10];
    const float* fc2_w     = (const float*)d_in[11];
    const float* fc2_b     = (const float*)d_in[12];
    const float* lnf_scale = (const float*)d_in[13];
    const float* lnf_bias  = (const float*)d_in[14];
    float* logits = (float*)d_out;

    cudaFuncSetAttribute((const void*)gemm_mma<128>, cudaFuncAttributeMaxDynamicSharedMemorySize, GEMM_SMEM_128);
    cudaFuncSetAttribute((const void*)gemm_mma<64>,  cudaFuncAttributeMaxDynamicSharedMemorySize, GEMM_SMEM_64);
    cudaFuncSetAttribute((const void*)attn_flash,    cudaFuncAttributeMaxDynamicSharedMemorySize, ATT_SMEM);

    float *x, *qkv;
    __half *h, *at, *f, *qw, *ow, *f1, *f2, *te;
    cudaGetSymbolAddress((void**)&x,   g_x);
    cudaGetSymbolAddress((void**)&qkv, g_qkv);
    cudaGetSymbolAddress((void**)&h,   g_h);
    cudaGetSymbolAddress((void**)&at,  g_at);
    cudaGetSymbolAddress((void**)&f,   g_f);
    cudaGetSymbolAddress((void**)&qw,  g_qw);  cudaGetSymbolAddress((void**)&ow,  g_ow);
    cudaGetSymbolAddress((void**)&f1,  g_f1);  cudaGetSymbolAddress((void**)&f2,  g_f2);
    cudaGetSymbolAddress((void**)&te,  g_te);

    // single merged weight conversion
    conv_all_kernel<<<(C_TOT + 255) / 256, 256>>>(qkv_w, out_w, fc1_w, fc2_w, tok_emb,
                                                  qw, ow, f1, f2, te);

    embed_kernel<<<(BT * Ee + 255) / 256, 256>>>(input_ids, tok_emb, pos_emb, x);

    for (int l = 0; l < Ll; l++) {
        // attention block (pre-norm)
        ln_kernel<<<BT, 256>>>(x, ln1_scale + l * Ee, ln1_bias + l * Ee, h);
        run_gemm_wide(h, qw + (size_t)l * 3 * Ee * Ee,
                      nullptr, nullptr, qkv, nullptr, 3 * Ee, Ee, 0);
        attn_flash<<<dim3(Tt/64, NHh, Bb), 256, ATT_SMEM>>>(qkv, at);
        run_gemm_narrow(at, ow + (size_t)l * Ee * Ee,
                        nullptr, x, x, nullptr, Ee, Ee, FLAG_RES);
        // FFN block (pre-norm)
        ln_kernel<<<BT, 256>>>(x, ln2_scale + l * Ee, ln2_bias + l * Ee, h);
        run_gemm_wide(h, f1 + (size_t)l * FFf * Ee,
                      fc1_b + (size_t)l * FFf, nullptr, nullptr, f,
                      FFf, Ee, FLAG_BIAS | FLAG_GELU | FLAG_F16OUT);
        run_gemm_narrow(f, f2 + (size_t)l * Ee * FFf,
                        fc2_b + (size_t)l * Ee, x, x, nullptr,
                        Ee, FFf, FLAG_BIAS | FLAG_RES);
    }

    // final layernorm + tied LM head
    ln_kernel<<<BT, 256>>>(x, lnf_scale, lnf_bias, h);
    run_gemm_wide(h, te, nullptr, nullptr, logits, nullptr, Vv, Ee, 0);
}